// round 1
// baseline (speedup 1.0000x reference)
#include <cuda_runtime.h>

#define D_MODEL 1024
#define N_HEADS 16
#define D_K     64
#define B_      2
#define T_      2048
#define M_ROWS  (B_ * T_)      // 4096

// ---------------- scratch (static device globals: allowed) ----------------
__device__ float g_Qp[M_ROWS * D_MODEL];
__device__ float g_Kp[M_ROWS * D_MODEL];
__device__ float g_Vp[M_ROWS * D_MODEL];
__device__ float g_An[M_ROWS * D_MODEL];

// =====================================================================
// SGEMM (NT): C[m][n] = sum_k A[m][k] * W[n][k] + bias[n]
// BM=BN=128, BK=8, 256 threads, 8x8 microtile per thread.
// =====================================================================
#define GBM 128
#define GBN 128
#define GBK 8

__global__ __launch_bounds__(256)
void gemm_nt_bias_kernel(const float* __restrict__ A,
                         const float* __restrict__ W,
                         const float* __restrict__ bias,
                         float* __restrict__ C,
                         int M, int N, int Kd)
{
    __shared__ float As[GBK][GBM];
    __shared__ float Bs[GBK][GBN];

    const int bm = blockIdx.y * GBM;
    const int bn = blockIdx.x * GBN;
    const int tid = threadIdx.x;

    // loading: each thread one float4 of A and one of W per BK step
    const int lr = tid >> 1;           // 0..127
    const int lc = (tid & 1) << 2;     // 0 or 4
    const float* Ap = A + (size_t)(bm + lr) * Kd + lc;
    const float* Wp = W + (size_t)(bn + lr) * Kd + lc;

    const int tx = tid & 15;           // 0..15 -> N
    const int ty = tid >> 4;           // 0..15 -> M

    float acc[8][8];
#pragma unroll
    for (int i = 0; i < 8; ++i)
#pragma unroll
        for (int j = 0; j < 8; ++j) acc[i][j] = 0.f;

    for (int k0 = 0; k0 < Kd; k0 += GBK) {
        float4 a4 = *reinterpret_cast<const float4*>(Ap + k0);
        float4 b4 = *reinterpret_cast<const float4*>(Wp + k0);
        As[lc + 0][lr] = a4.x; As[lc + 1][lr] = a4.y;
        As[lc + 2][lr] = a4.z; As[lc + 3][lr] = a4.w;
        Bs[lc + 0][lr] = b4.x; Bs[lc + 1][lr] = b4.y;
        Bs[lc + 2][lr] = b4.z; Bs[lc + 3][lr] = b4.w;
        __syncthreads();

#pragma unroll
        for (int kk = 0; kk < GBK; ++kk) {
            float af[8], bf[8];
            *reinterpret_cast<float4*>(af)     = *reinterpret_cast<const float4*>(&As[kk][ty * 8]);
            *reinterpret_cast<float4*>(af + 4) = *reinterpret_cast<const float4*>(&As[kk][ty * 8 + 4]);
            *reinterpret_cast<float4*>(bf)     = *reinterpret_cast<const float4*>(&Bs[kk][tx * 8]);
            *reinterpret_cast<float4*>(bf + 4) = *reinterpret_cast<const float4*>(&Bs[kk][tx * 8 + 4]);
#pragma unroll
            for (int i = 0; i < 8; ++i)
#pragma unroll
                for (int j = 0; j < 8; ++j)
                    acc[i][j] += af[i] * bf[j];
        }
        __syncthreads();
    }

    float bv[8];
    *reinterpret_cast<float4*>(bv)     = *reinterpret_cast<const float4*>(&bias[bn + tx * 8]);
    *reinterpret_cast<float4*>(bv + 4) = *reinterpret_cast<const float4*>(&bias[bn + tx * 8 + 4]);

#pragma unroll
    for (int i = 0; i < 8; ++i) {
        float* Crow = C + (size_t)(bm + ty * 8 + i) * N + bn + tx * 8;
        float4 r0, r1;
        r0.x = acc[i][0] + bv[0]; r0.y = acc[i][1] + bv[1];
        r0.z = acc[i][2] + bv[2]; r0.w = acc[i][3] + bv[3];
        r1.x = acc[i][4] + bv[4]; r1.y = acc[i][5] + bv[5];
        r1.z = acc[i][6] + bv[6]; r1.w = acc[i][7] + bv[7];
        *reinterpret_cast<float4*>(Crow)     = r0;
        *reinterpret_cast<float4*>(Crow + 4) = r1;
    }
}

// =====================================================================
// Flash attention: one block = one (b,h) x 64-row q tile.
// Q/K stored d-major (transposed) in smem; P reuses the K buffer.
// Thread grid 16x16: thread (ty,tx) owns S/O rows ty*4..+3,
// S cols tx*4..+3 and O dims tx*4..+3.
// =====================================================================
#define FPITCH 68
#define FLASH_SMEM (3 * 64 * FPITCH * (int)sizeof(float))

__global__ __launch_bounds__(256)
void flash_attn_kernel(const float* __restrict__ Q,
                       const float* __restrict__ K,
                       const float* __restrict__ V,
                       const int* __restrict__ mask,
                       const int* __restrict__ causal_p,
                       float* __restrict__ O)
{
    extern __shared__ float sm[];
    float* Qt  = sm;                    // [64 d][64 r] pitch 68
    float* KPt = sm + 64 * FPITCH;      // Kt, then reused for P^T
    float* Vs  = sm + 2 * 64 * FPITCH;  // [64 j][64 d] pitch 68

    const int qt  = blockIdx.x;         // q tile, 0..31
    const int bh  = blockIdx.y;         // 0..31
    const int b   = bh >> 4;
    const int h   = bh & 15;
    const int tid = threadIdx.x;
    const int tx  = tid & 15;
    const int ty  = tid >> 4;
    const int lrow = tid >> 2;          // 0..63
    const int lcol = (tid & 3) << 4;    // 0,16,32,48

    const int causal = *causal_p;
    const int* mrow = mask + b * T_;

    // load Q tile (transposed to d-major)
    {
        const float* Qg = Q + (size_t)(b * T_ + qt * 64) * D_MODEL + h * D_K;
#pragma unroll
        for (int j = 0; j < 4; ++j) {
            float4 v4 = *reinterpret_cast<const float4*>(Qg + (size_t)lrow * D_MODEL + lcol + j * 4);
            int d = lcol + j * 4;
            Qt[(d + 0) * FPITCH + lrow] = v4.x;
            Qt[(d + 1) * FPITCH + lrow] = v4.y;
            Qt[(d + 2) * FPITCH + lrow] = v4.z;
            Qt[(d + 3) * FPITCH + lrow] = v4.w;
        }
    }

    float m_i[4], l_i[4], o[4][4];
#pragma unroll
    for (int i = 0; i < 4; ++i) {
        m_i[i] = -1e30f; l_i[i] = 0.f;
#pragma unroll
        for (int e = 0; e < 4; ++e) o[i][e] = 0.f;
    }

    const int kend = causal ? qt : (T_ / 64 - 1);

    for (int kt = 0; kt <= kend; ++kt) {
        __syncthreads();   // prev PV reads done before overwriting tiles
        {
            const float* Kg = K + (size_t)(b * T_ + kt * 64) * D_MODEL + h * D_K;
            const float* Vg = V + (size_t)(b * T_ + kt * 64) * D_MODEL + h * D_K;
#pragma unroll
            for (int j = 0; j < 4; ++j) {
                float4 v4 = *reinterpret_cast<const float4*>(Kg + (size_t)lrow * D_MODEL + lcol + j * 4);
                int d = lcol + j * 4;
                KPt[(d + 0) * FPITCH + lrow] = v4.x;
                KPt[(d + 1) * FPITCH + lrow] = v4.y;
                KPt[(d + 2) * FPITCH + lrow] = v4.z;
                KPt[(d + 3) * FPITCH + lrow] = v4.w;
                float4 w4 = *reinterpret_cast<const float4*>(Vg + (size_t)lrow * D_MODEL + lcol + j * 4);
                *reinterpret_cast<float4*>(&Vs[lrow * FPITCH + lcol + j * 4]) = w4;
            }
        }
        __syncthreads();

        // S = Q K^T
        float s[4][4];
#pragma unroll
        for (int i = 0; i < 4; ++i)
#pragma unroll
            for (int j = 0; j < 4; ++j) s[i][j] = 0.f;

#pragma unroll 8
        for (int d = 0; d < 64; ++d) {
            float qv[4], kv[4];
            *reinterpret_cast<float4*>(qv) = *reinterpret_cast<const float4*>(&Qt[d * FPITCH + ty * 4]);
            *reinterpret_cast<float4*>(kv) = *reinterpret_cast<const float4*>(&KPt[d * FPITCH + tx * 4]);
#pragma unroll
            for (int i = 0; i < 4; ++i)
#pragma unroll
                for (int j = 0; j < 4; ++j)
                    s[i][j] += qv[i] * kv[j];
        }
        __syncthreads();   // everyone done reading Kt; KPt reusable for P

        // scale + masks
        const int qbase = qt * 64 + ty * 4;
        const int kbase = kt * 64 + tx * 4;
        int mk[4];
#pragma unroll
        for (int j = 0; j < 4; ++j) mk[j] = mrow[kbase + j];
#pragma unroll
        for (int i = 0; i < 4; ++i) {
            const int qr = qbase + i;
#pragma unroll
            for (int j = 0; j < 4; ++j) {
                float val = s[i][j] * 0.125f;   // 1/sqrt(64)
                if ((causal && (kbase + j) > qr) || (mk[j] == 0)) val = -1e30f;
                s[i][j] = val;
            }
        }

        // online softmax (row reduction across 16 tx lanes of this warp half)
#pragma unroll
        for (int i = 0; i < 4; ++i) {
            float mx = fmaxf(fmaxf(s[i][0], s[i][1]), fmaxf(s[i][2], s[i][3]));
#pragma unroll
            for (int off = 8; off; off >>= 1)
                mx = fmaxf(mx, __shfl_xor_sync(0xffffffffu, mx, off));
            float mnew  = fmaxf(m_i[i], mx);
            float alpha = __expf(m_i[i] - mnew);
            float rs = 0.f;
#pragma unroll
            for (int j = 0; j < 4; ++j) {
                float p = __expf(s[i][j] - mnew);
                s[i][j] = p;
                rs += p;
            }
#pragma unroll
            for (int off = 8; off; off >>= 1)
                rs += __shfl_xor_sync(0xffffffffu, rs, off);
            l_i[i] = l_i[i] * alpha + rs;
            m_i[i] = mnew;
#pragma unroll
            for (int e = 0; e < 4; ++e) o[i][e] *= alpha;
        }

        // write P transposed into the dead K buffer
#pragma unroll
        for (int j = 0; j < 4; ++j)
#pragma unroll
            for (int i = 0; i < 4; ++i)
                KPt[(tx * 4 + j) * FPITCH + ty * 4 + i] = s[i][j];
        __syncthreads();

        // O += P V
#pragma unroll 8
        for (int j = 0; j < 64; ++j) {
            float pv[4], vv[4];
            *reinterpret_cast<float4*>(pv) = *reinterpret_cast<const float4*>(&KPt[j * FPITCH + ty * 4]);
            *reinterpret_cast<float4*>(vv) = *reinterpret_cast<const float4*>(&Vs[j * FPITCH + tx * 4]);
#pragma unroll
            for (int i = 0; i < 4; ++i)
#pragma unroll
                for (int e = 0; e < 4; ++e)
                    o[i][e] += pv[i] * vv[e];
        }
    }

    // epilogue: normalize, write [b, t, h*64+d] layout
    float* Og = O + (size_t)(b * T_ + qt * 64) * D_MODEL + h * D_K;
#pragma unroll
    for (int i = 0; i < 4; ++i) {
        float inv = 1.f / l_i[i];
        float4 r;
        r.x = o[i][0] * inv; r.y = o[i][1] * inv;
        r.z = o[i][2] * inv; r.w = o[i][3] * inv;
        *reinterpret_cast<float4*>(Og + (size_t)(ty * 4 + i) * D_MODEL + tx * 4) = r;
    }
}

// =====================================================================
// launch
// =====================================================================
extern "C" void kernel_launch(void* const* d_in, const int* in_sizes, int n_in,
                              void* d_out, int out_size)
{
    const float* q    = (const float*)d_in[0];
    const float* k    = (const float*)d_in[1];
    const float* v    = (const float*)d_in[2];
    const float* Wq   = (const float*)d_in[3];
    const float* bq   = (const float*)d_in[4];
    const float* Wk   = (const float*)d_in[5];
    const float* bk   = (const float*)d_in[6];
    const float* Wv   = (const float*)d_in[7];
    const float* bv   = (const float*)d_in[8];
    const float* Wo   = (const float*)d_in[9];
    const float* bo   = (const float*)d_in[10];
    const int*   mask = (const int*)d_in[11];
    const int*   causal = (const int*)d_in[12];
    float* out = (float*)d_out;

    float *Qp, *Kp, *Vp, *An;
    cudaGetSymbolAddress((void**)&Qp, g_Qp);
    cudaGetSymbolAddress((void**)&Kp, g_Kp);
    cudaGetSymbolAddress((void**)&Vp, g_Vp);
    cudaGetSymbolAddress((void**)&An, g_An);

    dim3 ggrid(D_MODEL / GBN, M_ROWS / GBM);   // (8, 32)
    gemm_nt_bias_kernel<<<ggrid, 256>>>(q, Wq, bq, Qp, M_ROWS, D_MODEL, D_MODEL);
    gemm_nt_bias_kernel<<<ggrid, 256>>>(k, Wk, bk, Kp, M_ROWS, D_MODEL, D_MODEL);
    gemm_nt_bias_kernel<<<ggrid, 256>>>(v, Wv, bv, Vp, M_ROWS, D_MODEL, D_MODEL);

    cudaFuncSetAttribute(flash_attn_kernel,
                         cudaFuncAttributeMaxDynamicSharedMemorySize, FLASH_SMEM);
    dim3 fgrid(T_ / 64, B_ * N_HEADS);         // (32, 32)
    flash_attn_kernel<<<fgrid, 256, FLASH_SMEM>>>(Qp, Kp, Vp, mask, causal, An);

    gemm_nt_bias_kernel<<<ggrid, 256>>>(An, Wo, bo, out, M_ROWS, D_MODEL, D_MODEL);
}

// round 3
// speedup vs baseline: 1.4992x; 1.4992x over previous
#include <cuda_runtime.h>
#include <cuda_bf16.h>
#include <cstdint>

#define D_MODEL 1024
#define N_HEADS 16
#define D_K     64
#define B_      2
#define T_      2048
#define M_ROWS  (B_ * T_)      // 4096

// ---------------- scratch (static device globals: allowed) ----------------
__device__ float g_Qp[M_ROWS * D_MODEL];
__device__ float g_Kp[M_ROWS * D_MODEL];
__device__ float g_Vp[M_ROWS * D_MODEL];
__device__ float g_An[M_ROWS * D_MODEL];
__device__ __nv_bfloat16 g_Ah[M_ROWS * D_MODEL];
__device__ __nv_bfloat16 g_Al[M_ROWS * D_MODEL];
__device__ __nv_bfloat16 g_Wh[D_MODEL * D_MODEL];
__device__ __nv_bfloat16 g_Wl[D_MODEL * D_MODEL];

// =====================================================================
// portable tensor-core helpers (valid on plain sm_103 target)
// =====================================================================
__device__ __forceinline__ uint32_t smem_to_u32(const void* p) {
    uint32_t a;
    asm("{ .reg .u64 t; cvta.to.shared.u64 t, %1; cvt.u32.u64 %0, t; }" : "=r"(a) : "l"(p));
    return a;
}

__device__ __forceinline__ void ldm_x4(uint32_t* r, uint32_t addr) {
    asm volatile("ldmatrix.sync.aligned.m8n8.x4.shared.b16 {%0,%1,%2,%3}, [%4];"
                 : "=r"(r[0]), "=r"(r[1]), "=r"(r[2]), "=r"(r[3]) : "r"(addr));
}

__device__ __forceinline__ void mma_bf16(float* c, const uint32_t* a, uint32_t b0, uint32_t b1) {
    asm volatile("mma.sync.aligned.m16n8k16.row.col.f32.bf16.bf16.f32 "
                 "{%0,%1,%2,%3}, {%4,%5,%6,%7}, {%8,%9}, {%0,%1,%2,%3};"
                 : "+f"(c[0]), "+f"(c[1]), "+f"(c[2]), "+f"(c[3])
                 : "r"(a[0]), "r"(a[1]), "r"(a[2]), "r"(a[3]), "r"(b0), "r"(b1));
}

#define CP_ASYNC16(saddr, gptr) \
    asm volatile("cp.async.cg.shared.global [%0], [%1], 16;" :: "r"(saddr), "l"(gptr))
#define CP_COMMIT() asm volatile("cp.async.commit_group;" ::: "memory")
#define CP_WAIT1()  asm volatile("cp.async.wait_group 1;" ::: "memory")
#define CP_WAIT0()  asm volatile("cp.async.wait_group 0;" ::: "memory")

// =====================================================================
// fp32 -> bf16 (hi, lo) split
// =====================================================================
__global__ __launch_bounds__(256)
void split_bf16_kernel(const float* __restrict__ x,
                       __nv_bfloat16* __restrict__ hi,
                       __nv_bfloat16* __restrict__ lo, int n4)
{
    int i = blockIdx.x * blockDim.x + threadIdx.x;
    if (i >= n4) return;
    float4 v = reinterpret_cast<const float4*>(x)[i];
    __nv_bfloat16 h0 = __float2bfloat16(v.x);
    __nv_bfloat16 h1 = __float2bfloat16(v.y);
    __nv_bfloat16 h2 = __float2bfloat16(v.z);
    __nv_bfloat16 h3 = __float2bfloat16(v.w);
    __nv_bfloat16 l0 = __float2bfloat16(v.x - __bfloat162float(h0));
    __nv_bfloat16 l1 = __float2bfloat16(v.y - __bfloat162float(h1));
    __nv_bfloat16 l2 = __float2bfloat16(v.z - __bfloat162float(h2));
    __nv_bfloat16 l3 = __float2bfloat16(v.w - __bfloat162float(h3));
    __nv_bfloat162* hp = reinterpret_cast<__nv_bfloat162*>(hi) + i * 2;
    __nv_bfloat162* lp = reinterpret_cast<__nv_bfloat162*>(lo) + i * 2;
    hp[0] = __nv_bfloat162(h0, h1);
    hp[1] = __nv_bfloat162(h2, h3);
    lp[0] = __nv_bfloat162(l0, l1);
    lp[1] = __nv_bfloat162(l2, l3);
}

// =====================================================================
// mma.sync GEMM: C[m][n] = sum_k A[m][k]*W[n][k] + bias[n], 2-term bf16 split
// CTA tile 128x128, BK=32, 256 thr (8 warps, 2m x 4n, warp tile 64x32).
// smem pitch 80B (conflict-free ldmatrix), cp.async double buffer.
// =====================================================================
#define PITCH      80
#define TERM_BYTES (128 * PITCH)        // 10240
#define OFF_GAH    0
#define OFF_GAL    (1 * TERM_BYTES)
#define OFF_GBH    (2 * TERM_BYTES)
#define OFF_GBL    (3 * TERM_BYTES)
#define STAGE_BYTES (4 * TERM_BYTES)    // 40960
#define GEMM_SMEM   (2 * STAGE_BYTES)   // 81920

__global__ __launch_bounds__(256, 1)
void gemm_tc_kernel(const __nv_bfloat16* __restrict__ Ah,
                    const __nv_bfloat16* __restrict__ Al,
                    const __nv_bfloat16* __restrict__ Bh,
                    const __nv_bfloat16* __restrict__ Bl,
                    const float* __restrict__ bias,
                    float* __restrict__ C)
{
    extern __shared__ char sm[];
    const uint32_t smb = smem_to_u32(sm);

    const int tid  = threadIdx.x;
    const int lane = tid & 31;
    const int wid  = tid >> 5;
    const int warp_m = wid >> 2;   // 0..1
    const int warp_n = wid & 3;    // 0..3
    const int bm = blockIdx.y * 128;
    const int bn = blockIdx.x * 128;

    // cp.async lane mapping: unit u -> row=u>>2 (0..127), c=u&3 (16B chunk)
    const int u0row = tid >> 2;
    const int u0c   = tid & 3;
    const int u1row = (tid + 256) >> 2;
    const int u1c   = u0c;

    float acc[4][4][4];
#pragma unroll
    for (int mi = 0; mi < 4; ++mi)
#pragma unroll
        for (int nj = 0; nj < 4; ++nj)
#pragma unroll
            for (int e = 0; e < 4; ++e) acc[mi][nj][e] = 0.f;

    // ldmatrix lane-static offsets
    const uint32_t a_lane = (uint32_t)((lane & 15) * PITCH + (lane >> 4) * 16);
    const uint32_t b_lane = (uint32_t)(((lane & 7) + ((lane >> 4) << 3)) * PITCH + ((lane >> 3) & 1) * 16);

    const uint32_t aH_base = smb + OFF_GAH + (uint32_t)(warp_m * 64 * PITCH) + a_lane;
    const uint32_t aL_base = smb + OFF_GAL + (uint32_t)(warp_m * 64 * PITCH) + a_lane;
    const uint32_t bH_base = smb + OFF_GBH + (uint32_t)(warp_n * 32 * PITCH) + b_lane;
    const uint32_t bL_base = smb + OFF_GBL + (uint32_t)(warp_n * 32 * PITCH) + b_lane;

    const int NCHUNK = D_MODEL / 32;   // 32

    // ---- issue chunk c into stage j ----
    auto issue = [&](int c, int j) {
        const int koff = c * 32;
        const uint32_t sb = smb + (uint32_t)j * STAGE_BYTES;
        {
            uint32_t so = (uint32_t)(u0row * PITCH + u0c * 16);
            size_t gA = (size_t)(bm + u0row) * D_MODEL + koff + u0c * 8;
            size_t gB = (size_t)(bn + u0row) * D_MODEL + koff + u0c * 8;
            CP_ASYNC16(sb + OFF_GAH + so, Ah + gA);
            CP_ASYNC16(sb + OFF_GAL + so, Al + gA);
            CP_ASYNC16(sb + OFF_GBH + so, Bh + gB);
            CP_ASYNC16(sb + OFF_GBL + so, Bl + gB);
        }
        {
            uint32_t so = (uint32_t)(u1row * PITCH + u1c * 16);
            size_t gA = (size_t)(bm + u1row) * D_MODEL + koff + u1c * 8;
            size_t gB = (size_t)(bn + u1row) * D_MODEL + koff + u1c * 8;
            CP_ASYNC16(sb + OFF_GAH + so, Ah + gA);
            CP_ASYNC16(sb + OFF_GAL + so, Al + gA);
            CP_ASYNC16(sb + OFF_GBH + so, Bh + gB);
            CP_ASYNC16(sb + OFF_GBL + so, Bl + gB);
        }
        CP_COMMIT();
    };

    issue(0, 0);

    for (int c = 0; c < NCHUNK; ++c) {
        const int j = c & 1;
        if (c + 1 < NCHUNK) { issue(c + 1, (c + 1) & 1); CP_WAIT1(); }
        else                { CP_WAIT0(); }
        __syncthreads();

        const uint32_t stg = (uint32_t)j * STAGE_BYTES;
#pragma unroll
        for (int ks = 0; ks < 2; ++ks) {
            const uint32_t kb = (uint32_t)(ks * 32);
            uint32_t ah[4][4], al[4][4], bh[4][2], bl[4][2];
#pragma unroll
            for (int mi = 0; mi < 4; ++mi) {
                ldm_x4(ah[mi], aH_base + stg + kb + (uint32_t)(mi * 16 * PITCH));
                ldm_x4(al[mi], aL_base + stg + kb + (uint32_t)(mi * 16 * PITCH));
            }
#pragma unroll
            for (int p = 0; p < 2; ++p) {
                uint32_t r[4];
                ldm_x4(r, bH_base + stg + kb + (uint32_t)(p * 16 * PITCH));
                bh[p * 2 + 0][0] = r[0]; bh[p * 2 + 0][1] = r[1];
                bh[p * 2 + 1][0] = r[2]; bh[p * 2 + 1][1] = r[3];
                ldm_x4(r, bL_base + stg + kb + (uint32_t)(p * 16 * PITCH));
                bl[p * 2 + 0][0] = r[0]; bl[p * 2 + 0][1] = r[1];
                bl[p * 2 + 1][0] = r[2]; bl[p * 2 + 1][1] = r[3];
            }
#pragma unroll
            for (int mi = 0; mi < 4; ++mi)
#pragma unroll
                for (int nj = 0; nj < 4; ++nj) {
                    mma_bf16(acc[mi][nj], ah[mi], bh[nj][0], bh[nj][1]);
                    mma_bf16(acc[mi][nj], ah[mi], bl[nj][0], bl[nj][1]);
                    mma_bf16(acc[mi][nj], al[mi], bh[nj][0], bh[nj][1]);
                }
        }
        __syncthreads();
    }

    // epilogue
    const int rbase = bm + warp_m * 64;
    const int cbase = bn + warp_n * 32;
#pragma unroll
    for (int mi = 0; mi < 4; ++mi) {
#pragma unroll
        for (int nj = 0; nj < 4; ++nj) {
            int r0 = rbase + mi * 16 + (lane >> 2);
            int cc = cbase + nj * 8 + 2 * (lane & 3);
            float b0 = bias[cc], b1 = bias[cc + 1];
            float2 v0, v1;
            v0.x = acc[mi][nj][0] + b0; v0.y = acc[mi][nj][1] + b1;
            v1.x = acc[mi][nj][2] + b0; v1.y = acc[mi][nj][3] + b1;
            *reinterpret_cast<float2*>(C + (size_t)r0 * D_MODEL + cc) = v0;
            *reinterpret_cast<float2*>(C + (size_t)(r0 + 8) * D_MODEL + cc) = v1;
        }
    }
}

// =====================================================================
// Flash attention (unchanged from R1)
// =====================================================================
#define FPITCH 68
#define FLASH_SMEM (3 * 64 * FPITCH * (int)sizeof(float))

__global__ __launch_bounds__(256)
void flash_attn_kernel(const float* __restrict__ Q,
                       const float* __restrict__ K,
                       const float* __restrict__ V,
                       const int* __restrict__ mask,
                       const int* __restrict__ causal_p,
                       float* __restrict__ O)
{
    extern __shared__ float smf[];
    float* Qt  = smf;
    float* KPt = smf + 64 * FPITCH;
    float* Vs  = smf + 2 * 64 * FPITCH;

    const int qt  = blockIdx.x;
    const int bh  = blockIdx.y;
    const int b   = bh >> 4;
    const int h   = bh & 15;
    const int tid = threadIdx.x;
    const int tx  = tid & 15;
    const int ty  = tid >> 4;
    const int lrow = tid >> 2;
    const int lcol = (tid & 3) << 4;

    const int causal = *causal_p;
    const int* mrow = mask + b * T_;

    {
        const float* Qg = Q + (size_t)(b * T_ + qt * 64) * D_MODEL + h * D_K;
#pragma unroll
        for (int j = 0; j < 4; ++j) {
            float4 v4 = *reinterpret_cast<const float4*>(Qg + (size_t)lrow * D_MODEL + lcol + j * 4);
            int d = lcol + j * 4;
            Qt[(d + 0) * FPITCH + lrow] = v4.x;
            Qt[(d + 1) * FPITCH + lrow] = v4.y;
            Qt[(d + 2) * FPITCH + lrow] = v4.z;
            Qt[(d + 3) * FPITCH + lrow] = v4.w;
        }
    }

    float m_i[4], l_i[4], o[4][4];
#pragma unroll
    for (int i = 0; i < 4; ++i) {
        m_i[i] = -1e30f; l_i[i] = 0.f;
#pragma unroll
        for (int e = 0; e < 4; ++e) o[i][e] = 0.f;
    }

    const int kend = causal ? qt : (T_ / 64 - 1);

    for (int kt = 0; kt <= kend; ++kt) {
        __syncthreads();
        {
            const float* Kg = K + (size_t)(b * T_ + kt * 64) * D_MODEL + h * D_K;
            const float* Vg = V + (size_t)(b * T_ + kt * 64) * D_MODEL + h * D_K;
#pragma unroll
            for (int j = 0; j < 4; ++j) {
                float4 v4 = *reinterpret_cast<const float4*>(Kg + (size_t)lrow * D_MODEL + lcol + j * 4);
                int d = lcol + j * 4;
                KPt[(d + 0) * FPITCH + lrow] = v4.x;
                KPt[(d + 1) * FPITCH + lrow] = v4.y;
                KPt[(d + 2) * FPITCH + lrow] = v4.z;
                KPt[(d + 3) * FPITCH + lrow] = v4.w;
                float4 w4 = *reinterpret_cast<const float4*>(Vg + (size_t)lrow * D_MODEL + lcol + j * 4);
                *reinterpret_cast<float4*>(&Vs[lrow * FPITCH + lcol + j * 4]) = w4;
            }
        }
        __syncthreads();

        float s[4][4];
#pragma unroll
        for (int i = 0; i < 4; ++i)
#pragma unroll
            for (int j = 0; j < 4; ++j) s[i][j] = 0.f;

#pragma unroll 8
        for (int d = 0; d < 64; ++d) {
            float qv[4], kv[4];
            *reinterpret_cast<float4*>(qv) = *reinterpret_cast<const float4*>(&Qt[d * FPITCH + ty * 4]);
            *reinterpret_cast<float4*>(kv) = *reinterpret_cast<const float4*>(&KPt[d * FPITCH + tx * 4]);
#pragma unroll
            for (int i = 0; i < 4; ++i)
#pragma unroll
                for (int j = 0; j < 4; ++j)
                    s[i][j] += qv[i] * kv[j];
        }
        __syncthreads();

        const int qbase = qt * 64 + ty * 4;
        const int kbase = kt * 64 + tx * 4;
        int mk[4];
#pragma unroll
        for (int j = 0; j < 4; ++j) mk[j] = mrow[kbase + j];
#pragma unroll
        for (int i = 0; i < 4; ++i) {
            const int qr = qbase + i;
#pragma unroll
            for (int j = 0; j < 4; ++j) {
                float val = s[i][j] * 0.125f;
                if ((causal && (kbase + j) > qr) || (mk[j] == 0)) val = -1e30f;
                s[i][j] = val;
            }
        }

#pragma unroll
        for (int i = 0; i < 4; ++i) {
            float mx = fmaxf(fmaxf(s[i][0], s[i][1]), fmaxf(s[i][2], s[i][3]));
#pragma unroll
            for (int off = 8; off; off >>= 1)
                mx = fmaxf(mx, __shfl_xor_sync(0xffffffffu, mx, off));
            float mnew  = fmaxf(m_i[i], mx);
            float alpha = __expf(m_i[i] - mnew);
            float rs = 0.f;
#pragma unroll
            for (int j = 0; j < 4; ++j) {
                float p = __expf(s[i][j] - mnew);
                s[i][j] = p;
                rs += p;
            }
#pragma unroll
            for (int off = 8; off; off >>= 1)
                rs += __shfl_xor_sync(0xffffffffu, rs, off);
            l_i[i] = l_i[i] * alpha + rs;
            m_i[i] = mnew;
#pragma unroll
            for (int e = 0; e < 4; ++e) o[i][e] *= alpha;
        }

#pragma unroll
        for (int j = 0; j < 4; ++j)
#pragma unroll
            for (int i = 0; i < 4; ++i)
                KPt[(tx * 4 + j) * FPITCH + ty * 4 + i] = s[i][j];
        __syncthreads();

#pragma unroll 8
        for (int j = 0; j < 64; ++j) {
            float pv[4], vv[4];
            *reinterpret_cast<float4*>(pv) = *reinterpret_cast<const float4*>(&KPt[j * FPITCH + ty * 4]);
            *reinterpret_cast<float4*>(vv) = *reinterpret_cast<const float4*>(&Vs[j * FPITCH + tx * 4]);
#pragma unroll
            for (int i = 0; i < 4; ++i)
#pragma unroll
                for (int e = 0; e < 4; ++e)
                    o[i][e] += pv[i] * vv[e];
        }
    }

    float* Og = O + (size_t)(b * T_ + qt * 64) * D_MODEL + h * D_K;
#pragma unroll
    for (int i = 0; i < 4; ++i) {
        float inv = 1.f / l_i[i];
        float4 r;
        r.x = o[i][0] * inv; r.y = o[i][1] * inv;
        r.z = o[i][2] * inv; r.w = o[i][3] * inv;
        *reinterpret_cast<float4*>(Og + (size_t)(ty * 4 + i) * D_MODEL + tx * 4) = r;
    }
}

// =====================================================================
// launch
// =====================================================================
extern "C" void kernel_launch(void* const* d_in, const int* in_sizes, int n_in,
                              void* d_out, int out_size)
{
    const float* q    = (const float*)d_in[0];
    const float* k    = (const float*)d_in[1];
    const float* v    = (const float*)d_in[2];
    const float* Wq   = (const float*)d_in[3];
    const float* bq   = (const float*)d_in[4];
    const float* Wk   = (const float*)d_in[5];
    const float* bk   = (const float*)d_in[6];
    const float* Wv   = (const float*)d_in[7];
    const float* bv   = (const float*)d_in[8];
    const float* Wo   = (const float*)d_in[9];
    const float* bo   = (const float*)d_in[10];
    const int*   mask = (const int*)d_in[11];
    const int*   causal = (const int*)d_in[12];
    float* out = (float*)d_out;

    float *Qp, *Kp, *Vp, *An;
    __nv_bfloat16 *Ah, *Al, *Wh, *Wl;
    cudaGetSymbolAddress((void**)&Qp, g_Qp);
    cudaGetSymbolAddress((void**)&Kp, g_Kp);
    cudaGetSymbolAddress((void**)&Vp, g_Vp);
    cudaGetSymbolAddress((void**)&An, g_An);
    cudaGetSymbolAddress((void**)&Ah, g_Ah);
    cudaGetSymbolAddress((void**)&Al, g_Al);
    cudaGetSymbolAddress((void**)&Wh, g_Wh);
    cudaGetSymbolAddress((void**)&Wl, g_Wl);

    cudaFuncSetAttribute(gemm_tc_kernel,
                         cudaFuncAttributeMaxDynamicSharedMemorySize, GEMM_SMEM);
    cudaFuncSetAttribute(flash_attn_kernel,
                         cudaFuncAttributeMaxDynamicSharedMemorySize, FLASH_SMEM);

    const int nA4 = M_ROWS * D_MODEL / 4;
    const int nW4 = D_MODEL * D_MODEL / 4;
    dim3 ggrid(D_MODEL / 128, M_ROWS / 128);   // (8, 32)

    // Q projection
    split_bf16_kernel<<<nA4 / 256, 256>>>(q, Ah, Al, nA4);
    split_bf16_kernel<<<nW4 / 256, 256>>>(Wq, Wh, Wl, nW4);
    gemm_tc_kernel<<<ggrid, 256, GEMM_SMEM>>>(Ah, Al, Wh, Wl, bq, Qp);
    // K projection
    split_bf16_kernel<<<nA4 / 256, 256>>>(k, Ah, Al, nA4);
    split_bf16_kernel<<<nW4 / 256, 256>>>(Wk, Wh, Wl, nW4);
    gemm_tc_kernel<<<ggrid, 256, GEMM_SMEM>>>(Ah, Al, Wh, Wl, bk, Kp);
    // V projection
    split_bf16_kernel<<<nA4 / 256, 256>>>(v, Ah, Al, nA4);
    split_bf16_kernel<<<nW4 / 256, 256>>>(Wv, Wh, Wl, nW4);
    gemm_tc_kernel<<<ggrid, 256, GEMM_SMEM>>>(Ah, Al, Wh, Wl, bv, Vp);

    // attention
    dim3 fgrid(T_ / 64, B_ * N_HEADS);
    flash_attn_kernel<<<fgrid, 256, FLASH_SMEM>>>(Qp, Kp, Vp, mask, causal, An);

    // output projection
    split_bf16_kernel<<<nA4 / 256, 256>>>(An, Ah, Al, nA4);
    split_bf16_kernel<<<nW4 / 256, 256>>>(Wo, Wh, Wl, nW4);
    gemm_tc_kernel<<<ggrid, 256, GEMM_SMEM>>>(Ah, Al, Wh, Wl, bo, out);
}

// round 4
// speedup vs baseline: 2.5795x; 1.7206x over previous
#include <cuda_runtime.h>
#include <cuda_bf16.h>
#include <cstdint>

#define D_MODEL 1024
#define N_HEADS 16
#define D_K     64
#define B_      2
#define T_      2048
#define M_ROWS  (B_ * T_)      // 4096

// ---------------- scratch (static device globals: allowed) ----------------
__device__ __nv_bfloat16 g_Ah[M_ROWS * D_MODEL];
__device__ __nv_bfloat16 g_Al[M_ROWS * D_MODEL];
__device__ __nv_bfloat16 g_Wh[D_MODEL * D_MODEL];
__device__ __nv_bfloat16 g_Wl[D_MODEL * D_MODEL];
__device__ __nv_bfloat16 g_Qh[M_ROWS * D_MODEL];
__device__ __nv_bfloat16 g_Ql[M_ROWS * D_MODEL];
__device__ __nv_bfloat16 g_Kh[M_ROWS * D_MODEL];
__device__ __nv_bfloat16 g_Kl[M_ROWS * D_MODEL];
__device__ __nv_bfloat16 g_Vh[M_ROWS * D_MODEL];
__device__ __nv_bfloat16 g_Vl[M_ROWS * D_MODEL];
__device__ __nv_bfloat16 g_Anh[M_ROWS * D_MODEL];
__device__ __nv_bfloat16 g_Anl[M_ROWS * D_MODEL];

// =====================================================================
// portable tensor-core helpers (valid on plain sm_103 target)
// =====================================================================
__device__ __forceinline__ uint32_t smem_to_u32(const void* p) {
    uint32_t a;
    asm("{ .reg .u64 t; cvta.to.shared.u64 t, %1; cvt.u32.u64 %0, t; }" : "=r"(a) : "l"(p));
    return a;
}

__device__ __forceinline__ void ldm_x4(uint32_t* r, uint32_t addr) {
    asm volatile("ldmatrix.sync.aligned.m8n8.x4.shared.b16 {%0,%1,%2,%3}, [%4];"
                 : "=r"(r[0]), "=r"(r[1]), "=r"(r[2]), "=r"(r[3]) : "r"(addr));
}
__device__ __forceinline__ void ldm_x4_t(uint32_t* r, uint32_t addr) {
    asm volatile("ldmatrix.sync.aligned.m8n8.x4.trans.shared.b16 {%0,%1,%2,%3}, [%4];"
                 : "=r"(r[0]), "=r"(r[1]), "=r"(r[2]), "=r"(r[3]) : "r"(addr));
}

__device__ __forceinline__ void mma_bf16(float* c, const uint32_t* a, uint32_t b0, uint32_t b1) {
    asm volatile("mma.sync.aligned.m16n8k16.row.col.f32.bf16.bf16.f32 "
                 "{%0,%1,%2,%3}, {%4,%5,%6,%7}, {%8,%9}, {%0,%1,%2,%3};"
                 : "+f"(c[0]), "+f"(c[1]), "+f"(c[2]), "+f"(c[3])
                 : "r"(a[0]), "r"(a[1]), "r"(a[2]), "r"(a[3]), "r"(b0), "r"(b1));
}

#define CP_ASYNC16(saddr, gptr) \
    asm volatile("cp.async.cg.shared.global [%0], [%1], 16;" :: "r"(saddr), "l"(gptr))
#define CP_COMMIT() asm volatile("cp.async.commit_group;" ::: "memory")
#define CP_WAIT1()  asm volatile("cp.async.wait_group 1;" ::: "memory")
#define CP_WAIT0()  asm volatile("cp.async.wait_group 0;" ::: "memory")

// pack two f32 -> bf16x2 (hi arg in upper 16 bits)
__device__ __forceinline__ uint32_t cvt2bf(float hi, float lo) {
    uint32_t r;
    asm("cvt.rn.bf16x2.f32 %0, %1, %2;" : "=r"(r) : "f"(hi), "f"(lo));
    return r;
}

// FFMA-pipe exp (no MUFU): x <= 0, ~1e-4 rel accuracy
__device__ __forceinline__ float fast_exp(float x) {
    x = fmaxf(x, -87.f);
    float t = fmaf(x, 1.442695041f, 12582912.f);   // magic rint
    uint32_t e = __float_as_uint(t);
    float zi = t - 12582912.f;
    float f = fmaf(x, 1.442695041f, -zi);          // frac in [-0.5, 0.5]
    float p = fmaf(f, 0.009618130f, 0.055504110f); // 2^f Taylor deg-4
    p = fmaf(f, p, 0.240226507f);
    p = fmaf(f, p, 0.693147181f);
    p = fmaf(f, p, 1.0f);
    return p * __uint_as_float((e << 23) + 0x3F800000u);
}

// =====================================================================
// fp32 -> bf16 (hi, lo) split
// =====================================================================
__global__ __launch_bounds__(256)
void split_bf16_kernel(const float* __restrict__ x,
                       __nv_bfloat16* __restrict__ hi,
                       __nv_bfloat16* __restrict__ lo, int n4)
{
    int i = blockIdx.x * blockDim.x + threadIdx.x;
    if (i >= n4) return;
    float4 v = reinterpret_cast<const float4*>(x)[i];
    __nv_bfloat16 h0 = __float2bfloat16(v.x);
    __nv_bfloat16 h1 = __float2bfloat16(v.y);
    __nv_bfloat16 h2 = __float2bfloat16(v.z);
    __nv_bfloat16 h3 = __float2bfloat16(v.w);
    __nv_bfloat16 l0 = __float2bfloat16(v.x - __bfloat162float(h0));
    __nv_bfloat16 l1 = __float2bfloat16(v.y - __bfloat162float(h1));
    __nv_bfloat16 l2 = __float2bfloat16(v.z - __bfloat162float(h2));
    __nv_bfloat16 l3 = __float2bfloat16(v.w - __bfloat162float(h3));
    __nv_bfloat162* hp = reinterpret_cast<__nv_bfloat162*>(hi) + i * 2;
    __nv_bfloat162* lp = reinterpret_cast<__nv_bfloat162*>(lo) + i * 2;
    hp[0] = __nv_bfloat162(h0, h1);
    hp[1] = __nv_bfloat162(h2, h3);
    lp[0] = __nv_bfloat162(l0, l1);
    lp[1] = __nv_bfloat162(l2, l3);
}

// =====================================================================
// mma.sync GEMM with dual epilogue (f32 OR bf16 hi/lo split output)
// =====================================================================
#define PITCH      80
#define TERM_BYTES (128 * PITCH)
#define OFF_GAH    0
#define OFF_GAL    (1 * TERM_BYTES)
#define OFF_GBH    (2 * TERM_BYTES)
#define OFF_GBL    (3 * TERM_BYTES)
#define STAGE_BYTES (4 * TERM_BYTES)
#define GEMM_SMEM   (2 * STAGE_BYTES)

__global__ __launch_bounds__(256, 1)
void gemm_tc_kernel(const __nv_bfloat16* __restrict__ Ah,
                    const __nv_bfloat16* __restrict__ Al,
                    const __nv_bfloat16* __restrict__ Bh,
                    const __nv_bfloat16* __restrict__ Bl,
                    const float* __restrict__ bias,
                    __nv_bfloat16* __restrict__ Chi,
                    __nv_bfloat16* __restrict__ Clo,
                    float* __restrict__ Cf)
{
    extern __shared__ char sm[];
    const uint32_t smb = smem_to_u32(sm);

    const int tid  = threadIdx.x;
    const int lane = tid & 31;
    const int wid  = tid >> 5;
    const int warp_m = wid >> 2;
    const int warp_n = wid & 3;
    const int bm = blockIdx.y * 128;
    const int bn = blockIdx.x * 128;

    const int u0row = tid >> 2;
    const int u0c   = tid & 3;
    const int u1row = (tid + 256) >> 2;
    const int u1c   = u0c;

    float acc[4][4][4];
#pragma unroll
    for (int mi = 0; mi < 4; ++mi)
#pragma unroll
        for (int nj = 0; nj < 4; ++nj)
#pragma unroll
            for (int e = 0; e < 4; ++e) acc[mi][nj][e] = 0.f;

    const uint32_t a_lane = (uint32_t)((lane & 15) * PITCH + (lane >> 4) * 16);
    const uint32_t b_lane = (uint32_t)(((lane & 7) + ((lane >> 4) << 3)) * PITCH + ((lane >> 3) & 1) * 16);

    const uint32_t aH_base = smb + OFF_GAH + (uint32_t)(warp_m * 64 * PITCH) + a_lane;
    const uint32_t aL_base = smb + OFF_GAL + (uint32_t)(warp_m * 64 * PITCH) + a_lane;
    const uint32_t bH_base = smb + OFF_GBH + (uint32_t)(warp_n * 32 * PITCH) + b_lane;
    const uint32_t bL_base = smb + OFF_GBL + (uint32_t)(warp_n * 32 * PITCH) + b_lane;

    const int NCHUNK = D_MODEL / 32;

    auto issue = [&](int c, int j) {
        const int koff = c * 32;
        const uint32_t sb = smb + (uint32_t)j * STAGE_BYTES;
        {
            uint32_t so = (uint32_t)(u0row * PITCH + u0c * 16);
            size_t gA = (size_t)(bm + u0row) * D_MODEL + koff + u0c * 8;
            size_t gB = (size_t)(bn + u0row) * D_MODEL + koff + u0c * 8;
            CP_ASYNC16(sb + OFF_GAH + so, Ah + gA);
            CP_ASYNC16(sb + OFF_GAL + so, Al + gA);
            CP_ASYNC16(sb + OFF_GBH + so, Bh + gB);
            CP_ASYNC16(sb + OFF_GBL + so, Bl + gB);
        }
        {
            uint32_t so = (uint32_t)(u1row * PITCH + u1c * 16);
            size_t gA = (size_t)(bm + u1row) * D_MODEL + koff + u1c * 8;
            size_t gB = (size_t)(bn + u1row) * D_MODEL + koff + u1c * 8;
            CP_ASYNC16(sb + OFF_GAH + so, Ah + gA);
            CP_ASYNC16(sb + OFF_GAL + so, Al + gA);
            CP_ASYNC16(sb + OFF_GBH + so, Bh + gB);
            CP_ASYNC16(sb + OFF_GBL + so, Bl + gB);
        }
        CP_COMMIT();
    };

    issue(0, 0);

    for (int c = 0; c < NCHUNK; ++c) {
        const int j = c & 1;
        if (c + 1 < NCHUNK) { issue(c + 1, (c + 1) & 1); CP_WAIT1(); }
        else                { CP_WAIT0(); }
        __syncthreads();

        const uint32_t stg = (uint32_t)j * STAGE_BYTES;
#pragma unroll
        for (int ks = 0; ks < 2; ++ks) {
            const uint32_t kb = (uint32_t)(ks * 32);
            uint32_t ah[4][4], al[4][4], bhv[4][2], blv[4][2];
#pragma unroll
            for (int mi = 0; mi < 4; ++mi) {
                ldm_x4(ah[mi], aH_base + stg + kb + (uint32_t)(mi * 16 * PITCH));
                ldm_x4(al[mi], aL_base + stg + kb + (uint32_t)(mi * 16 * PITCH));
            }
#pragma unroll
            for (int p = 0; p < 2; ++p) {
                uint32_t r[4];
                ldm_x4(r, bH_base + stg + kb + (uint32_t)(p * 16 * PITCH));
                bhv[p * 2 + 0][0] = r[0]; bhv[p * 2 + 0][1] = r[1];
                bhv[p * 2 + 1][0] = r[2]; bhv[p * 2 + 1][1] = r[3];
                ldm_x4(r, bL_base + stg + kb + (uint32_t)(p * 16 * PITCH));
                blv[p * 2 + 0][0] = r[0]; blv[p * 2 + 0][1] = r[1];
                blv[p * 2 + 1][0] = r[2]; blv[p * 2 + 1][1] = r[3];
            }
#pragma unroll
            for (int mi = 0; mi < 4; ++mi)
#pragma unroll
                for (int nj = 0; nj < 4; ++nj) {
                    mma_bf16(acc[mi][nj], ah[mi], bhv[nj][0], bhv[nj][1]);
                    mma_bf16(acc[mi][nj], ah[mi], blv[nj][0], blv[nj][1]);
                    mma_bf16(acc[mi][nj], al[mi], bhv[nj][0], bhv[nj][1]);
                }
        }
        __syncthreads();
    }

    const int rbase = bm + warp_m * 64;
    const int cbase = bn + warp_n * 32;
#pragma unroll
    for (int mi = 0; mi < 4; ++mi) {
#pragma unroll
        for (int nj = 0; nj < 4; ++nj) {
            int r0 = rbase + mi * 16 + (lane >> 2);
            int cc = cbase + nj * 8 + 2 * (lane & 3);
            float b0 = bias[cc], b1 = bias[cc + 1];
            float v0 = acc[mi][nj][0] + b0, v1 = acc[mi][nj][1] + b1;
            float v2 = acc[mi][nj][2] + b0, v3 = acc[mi][nj][3] + b1;
            if (Cf) {
                float2 w0, w1;
                w0.x = v0; w0.y = v1; w1.x = v2; w1.y = v3;
                *reinterpret_cast<float2*>(Cf + (size_t)r0 * D_MODEL + cc) = w0;
                *reinterpret_cast<float2*>(Cf + (size_t)(r0 + 8) * D_MODEL + cc) = w1;
            } else {
                uint32_t hp0 = cvt2bf(v1, v0);
                uint32_t hp1 = cvt2bf(v3, v2);
                float h0 = __uint_as_float(hp0 << 16), h1 = __uint_as_float(hp0 & 0xFFFF0000u);
                float h2 = __uint_as_float(hp1 << 16), h3 = __uint_as_float(hp1 & 0xFFFF0000u);
                uint32_t lp0 = cvt2bf(v1 - h1, v0 - h0);
                uint32_t lp1 = cvt2bf(v3 - h3, v2 - h2);
                *reinterpret_cast<uint32_t*>(Chi + (size_t)r0 * D_MODEL + cc) = hp0;
                *reinterpret_cast<uint32_t*>(Chi + (size_t)(r0 + 8) * D_MODEL + cc) = hp1;
                *reinterpret_cast<uint32_t*>(Clo + (size_t)r0 * D_MODEL + cc) = lp0;
                *reinterpret_cast<uint32_t*>(Clo + (size_t)(r0 + 8) * D_MODEL + cc) = lp1;
            }
        }
    }
}

// =====================================================================
// mma.sync flash attention
// CTA = 128 q-rows x one (b,h). 8 warps x 16 q-rows. KV tile 64, double buffer.
// smem pitch = 72 bf16 (144B) -> conflict-free ldmatrix.
// =====================================================================
#define FP2      72
#define QTERM_B  18432               // 128*72*2
#define KVARR_B  9216                // 64*72*2
#define STG_B    (4 * KVARR_B + 256) // Kh|Kl|Vh|Vl|madd  = 37120
#define FL_SMEM  (2 * QTERM_B + 2 * STG_B)   // 111104

__global__ __launch_bounds__(256, 1)
void flash_tc_kernel(const __nv_bfloat16* __restrict__ Qh_g, const __nv_bfloat16* __restrict__ Ql_g,
                     const __nv_bfloat16* __restrict__ Kh_g, const __nv_bfloat16* __restrict__ Kl_g,
                     const __nv_bfloat16* __restrict__ Vh_g, const __nv_bfloat16* __restrict__ Vl_g,
                     const int* __restrict__ mask, const int* __restrict__ causal_p,
                     __nv_bfloat16* __restrict__ Oh_g, __nv_bfloat16* __restrict__ Ol_g)
{
    extern __shared__ char smc[];
    const uint32_t smb = smem_to_u32(smc);
    const int tid = threadIdx.x, lane = tid & 31, warp = tid >> 5;
    const int qb = (int)(gridDim.x - 1 - blockIdx.x);     // big tiles first
    const int bh = blockIdx.y, b = bh >> 4, h = bh & 15;
    const int causal = *causal_p;
    const int kend = causal ? (2 * qb + 1) : (T_ / 64 - 1);
    const int rowg0 = b * T_ + qb * 128;

    auto issue_kv = [&](int kt, int s) {
        const uint32_t sb = smb + 2u * QTERM_B + (uint32_t)s * STG_B;
        const int tk0 = b * T_ + kt * 64;
#pragma unroll
        for (int u = tid; u < 2048; u += 256) {
            const int arr = u >> 9, rem = u & 511;
            const int row = rem >> 3, c = rem & 7;
            const __nv_bfloat16* base = (arr == 0) ? Kh_g : (arr == 1) ? Kl_g
                                       : (arr == 2) ? Vh_g : Vl_g;
            CP_ASYNC16(sb + (uint32_t)(arr * KVARR_B + row * 144 + c * 16),
                       base + ((size_t)(tk0 + row) * D_MODEL + h * 64 + c * 8));
        }
        if (tid < 64) {
            float mv = (mask[tk0 + tid] == 0) ? -1e30f : 0.f;
            reinterpret_cast<float*>(smc + 2 * QTERM_B + s * STG_B + 4 * KVARR_B)[tid] = mv;
        }
    };

    // prologue: Q (both terms) + tile0, one commit group
    {
#pragma unroll
        for (int u = tid; u < 2048; u += 256) {
            const int term = u >> 10, rem = u & 1023;
            const int row = rem >> 3, c = rem & 7;
            const __nv_bfloat16* src = (term ? Ql_g : Qh_g)
                + ((size_t)(rowg0 + row) * D_MODEL + h * 64 + c * 8);
            CP_ASYNC16(smb + (uint32_t)(term * QTERM_B + row * 144 + c * 16), src);
        }
        issue_kv(0, 0);
        CP_COMMIT();
    }

    const uint32_t a_lane = (uint32_t)((lane & 15) * 144 + (lane >> 4) * 16);
    const uint32_t b_lane = (uint32_t)(((lane & 7) + ((lane >> 4) << 3)) * 144 + ((lane >> 3) & 1) * 16);

    uint32_t qhf[4][4], qlf[4][4];
    float o[8][4];
#pragma unroll
    for (int nd = 0; nd < 8; ++nd)
#pragma unroll
        for (int e = 0; e < 4; ++e) o[nd][e] = 0.f;
    float m0 = -1e30f, m1 = -1e30f, l0 = 0.f, l1 = 0.f;

    const int r_in_warp = lane >> 2;
    const int rg0 = qb * 128 + warp * 16 + r_in_warp;   // seq-local q row
    const int rg1 = rg0 + 8;
    const int colb = 2 * (lane & 3);

    for (int kt = 0; kt <= kend; ++kt) {
        CP_WAIT0();
        __syncthreads();

        if (kt == 0) {
            const uint32_t qs = smb + (uint32_t)(warp * 16 * 144);
#pragma unroll
            for (int ks = 0; ks < 4; ++ks) {
                ldm_x4(qhf[ks], qs + a_lane + (uint32_t)(ks * 32));
                ldm_x4(qlf[ks], qs + QTERM_B + a_lane + (uint32_t)(ks * 32));
            }
        }

        const int j = kt & 1;
        const uint32_t sb = smb + 2u * QTERM_B + (uint32_t)j * STG_B;
        const float* madd = reinterpret_cast<const float*>(smc + 2 * QTERM_B + j * STG_B + 4 * KVARR_B);

        // ---- S = Q K^T (3-term) ----
        float c[8][4];
#pragma unroll
        for (int nj = 0; nj < 8; ++nj)
#pragma unroll
            for (int e = 0; e < 4; ++e) c[nj][e] = 0.f;

#pragma unroll
        for (int ks = 0; ks < 4; ++ks) {
            const uint32_t kb = (uint32_t)(ks * 32);
#pragma unroll
            for (int nb = 0; nb < 4; ++nb) {
                uint32_t rh[4], rl[4];
                ldm_x4(rh, sb + 0 * KVARR_B + b_lane + (uint32_t)(nb * 2304) + kb);
                ldm_x4(rl, sb + 1 * KVARR_B + b_lane + (uint32_t)(nb * 2304) + kb);
                mma_bf16(c[2 * nb],     qhf[ks], rh[0], rh[1]);
                mma_bf16(c[2 * nb],     qhf[ks], rl[0], rl[1]);
                mma_bf16(c[2 * nb],     qlf[ks], rh[0], rh[1]);
                mma_bf16(c[2 * nb + 1], qhf[ks], rh[2], rh[3]);
                mma_bf16(c[2 * nb + 1], qhf[ks], rl[2], rl[3]);
                mma_bf16(c[2 * nb + 1], qlf[ks], rh[2], rh[3]);
            }
        }

        // ---- scale + mask + online softmax ----
        const bool diag = (causal != 0) && (kt >= 2 * qb);
        float mx0 = -1e30f, mx1 = -1e30f;
#pragma unroll
        for (int nj = 0; nj < 8; ++nj) {
            const int cl = nj * 8 + colb;
            const int cg = kt * 64 + cl;
            const float ma0 = madd[cl], ma1 = madd[cl + 1];
            float s0 = fmaf(c[nj][0], 0.125f, ma0);
            float s1 = fmaf(c[nj][1], 0.125f, ma1);
            float s2 = fmaf(c[nj][2], 0.125f, ma0);
            float s3 = fmaf(c[nj][3], 0.125f, ma1);
            if (diag) {
                if (cg > rg0)     s0 = -1e30f;
                if (cg + 1 > rg0) s1 = -1e30f;
                if (cg > rg1)     s2 = -1e30f;
                if (cg + 1 > rg1) s3 = -1e30f;
            }
            c[nj][0] = s0; c[nj][1] = s1; c[nj][2] = s2; c[nj][3] = s3;
            mx0 = fmaxf(mx0, fmaxf(s0, s1));
            mx1 = fmaxf(mx1, fmaxf(s2, s3));
        }
        mx0 = fmaxf(mx0, __shfl_xor_sync(0xffffffffu, mx0, 1));
        mx0 = fmaxf(mx0, __shfl_xor_sync(0xffffffffu, mx0, 2));
        mx1 = fmaxf(mx1, __shfl_xor_sync(0xffffffffu, mx1, 1));
        mx1 = fmaxf(mx1, __shfl_xor_sync(0xffffffffu, mx1, 2));

        const float mn0 = fmaxf(m0, mx0), mn1 = fmaxf(m1, mx1);
        const float al0 = fast_exp(m0 - mn0), al1 = fast_exp(m1 - mn1);
        float rs0 = 0.f, rs1 = 0.f;
#pragma unroll
        for (int nj = 0; nj < 8; ++nj) {
            float p0 = fast_exp(c[nj][0] - mn0);
            float p1 = fast_exp(c[nj][1] - mn0);
            float p2 = fast_exp(c[nj][2] - mn1);
            float p3 = fast_exp(c[nj][3] - mn1);
            c[nj][0] = p0; c[nj][1] = p1; c[nj][2] = p2; c[nj][3] = p3;
            rs0 += p0 + p1; rs1 += p2 + p3;
        }
        rs0 += __shfl_xor_sync(0xffffffffu, rs0, 1);
        rs0 += __shfl_xor_sync(0xffffffffu, rs0, 2);
        rs1 += __shfl_xor_sync(0xffffffffu, rs1, 1);
        rs1 += __shfl_xor_sync(0xffffffffu, rs1, 2);
        l0 = l0 * al0 + rs0; m0 = mn0;
        l1 = l1 * al1 + rs1; m1 = mn1;
#pragma unroll
        for (int nd = 0; nd < 8; ++nd) {
            o[nd][0] *= al0; o[nd][1] *= al0;
            o[nd][2] *= al1; o[nd][3] *= al1;
        }

        // ---- convert P to bf16 hi/lo A-fragments ----
        uint32_t pfh[4][4], pfl[4][4];
#pragma unroll
        for (int ks = 0; ks < 4; ++ks) {
#pragma unroll
            for (int half = 0; half < 2; ++half) {
                const int nj = 2 * ks + half;
                uint32_t hpA = cvt2bf(c[nj][1], c[nj][0]);
                uint32_t hpB = cvt2bf(c[nj][3], c[nj][2]);
                float hA0 = __uint_as_float(hpA << 16), hA1 = __uint_as_float(hpA & 0xFFFF0000u);
                float hB0 = __uint_as_float(hpB << 16), hB1 = __uint_as_float(hpB & 0xFFFF0000u);
                uint32_t lpA = cvt2bf(c[nj][1] - hA1, c[nj][0] - hA0);
                uint32_t lpB = cvt2bf(c[nj][3] - hB1, c[nj][2] - hB0);
                pfh[ks][2 * half + 0] = hpA; pfh[ks][2 * half + 1] = hpB;
                pfl[ks][2 * half + 0] = lpA; pfl[ks][2 * half + 1] = lpB;
            }
        }

        // ---- O += P V (3-term), V via trans ldmatrix ----
        const uint32_t v_lane = (uint32_t)((lane & 15) * 144 + (lane >> 4) * 16);
#pragma unroll
        for (int ks = 0; ks < 4; ++ks) {
#pragma unroll
            for (int nb = 0; nb < 4; ++nb) {
                uint32_t vh[4], vl[4];
                const uint32_t va = sb + 2u * KVARR_B + v_lane
                                  + (uint32_t)(ks * 16 * 144) + (uint32_t)(nb * 32);
                ldm_x4_t(vh, va);
                ldm_x4_t(vl, va + KVARR_B);
                mma_bf16(o[2 * nb],     pfh[ks], vh[0], vh[1]);
                mma_bf16(o[2 * nb],     pfh[ks], vl[0], vl[1]);
                mma_bf16(o[2 * nb],     pfl[ks], vh[0], vh[1]);
                mma_bf16(o[2 * nb + 1], pfh[ks], vh[2], vh[3]);
                mma_bf16(o[2 * nb + 1], pfh[ks], vl[2], vl[3]);
                mma_bf16(o[2 * nb + 1], pfl[ks], vh[2], vh[3]);
            }
        }

        __syncthreads();
        if (kt + 1 <= kend) { issue_kv(kt + 1, (kt + 1) & 1); CP_COMMIT(); }
    }

    // ---- epilogue: normalize, write bf16 hi/lo ----
    const float inv0 = __fdividef(1.f, l0);
    const float inv1 = __fdividef(1.f, l1);
    const size_t gr0 = (size_t)(rowg0 + warp * 16 + r_in_warp) * D_MODEL + h * 64;
    const size_t gr1 = gr0 + 8 * D_MODEL;
#pragma unroll
    for (int nd = 0; nd < 8; ++nd) {
        const int cc = nd * 8 + colb;
        float v0 = o[nd][0] * inv0, v1 = o[nd][1] * inv0;
        float v2 = o[nd][2] * inv1, v3 = o[nd][3] * inv1;
        uint32_t hp0 = cvt2bf(v1, v0);
        uint32_t hp1 = cvt2bf(v3, v2);
        float h0 = __uint_as_float(hp0 << 16), h1 = __uint_as_float(hp0 & 0xFFFF0000u);
        float h2 = __uint_as_float(hp1 << 16), h3 = __uint_as_float(hp1 & 0xFFFF0000u);
        uint32_t lp0 = cvt2bf(v1 - h1, v0 - h0);
        uint32_t lp1 = cvt2bf(v3 - h3, v2 - h2);
        *reinterpret_cast<uint32_t*>(Oh_g + gr0 + cc) = hp0;
        *reinterpret_cast<uint32_t*>(Oh_g + gr1 + cc) = hp1;
        *reinterpret_cast<uint32_t*>(Ol_g + gr0 + cc) = lp0;
        *reinterpret_cast<uint32_t*>(Ol_g + gr1 + cc) = lp1;
    }
}

// =====================================================================
// launch
// =====================================================================
extern "C" void kernel_launch(void* const* d_in, const int* in_sizes, int n_in,
                              void* d_out, int out_size)
{
    const float* q    = (const float*)d_in[0];
    const float* k    = (const float*)d_in[1];
    const float* v    = (const float*)d_in[2];
    const float* Wq   = (const float*)d_in[3];
    const float* bq   = (const float*)d_in[4];
    const float* Wk   = (const float*)d_in[5];
    const float* bk   = (const float*)d_in[6];
    const float* Wv   = (const float*)d_in[7];
    const float* bv   = (const float*)d_in[8];
    const float* Wo   = (const float*)d_in[9];
    const float* bo   = (const float*)d_in[10];
    const int*   mask = (const int*)d_in[11];
    const int*   causal = (const int*)d_in[12];
    float* out = (float*)d_out;

    __nv_bfloat16 *Ah, *Al, *Wh, *Wl, *Qh, *Ql, *Kh, *Kl, *Vh, *Vl, *Anh, *Anl;
    cudaGetSymbolAddress((void**)&Ah, g_Ah);
    cudaGetSymbolAddress((void**)&Al, g_Al);
    cudaGetSymbolAddress((void**)&Wh, g_Wh);
    cudaGetSymbolAddress((void**)&Wl, g_Wl);
    cudaGetSymbolAddress((void**)&Qh, g_Qh);
    cudaGetSymbolAddress((void**)&Ql, g_Ql);
    cudaGetSymbolAddress((void**)&Kh, g_Kh);
    cudaGetSymbolAddress((void**)&Kl, g_Kl);
    cudaGetSymbolAddress((void**)&Vh, g_Vh);
    cudaGetSymbolAddress((void**)&Vl, g_Vl);
    cudaGetSymbolAddress((void**)&Anh, g_Anh);
    cudaGetSymbolAddress((void**)&Anl, g_Anl);

    cudaFuncSetAttribute(gemm_tc_kernel,
                         cudaFuncAttributeMaxDynamicSharedMemorySize, GEMM_SMEM);
    cudaFuncSetAttribute(flash_tc_kernel,
                         cudaFuncAttributeMaxDynamicSharedMemorySize, FL_SMEM);

    const int nA4 = M_ROWS * D_MODEL / 4;
    const int nW4 = D_MODEL * D_MODEL / 4;
    dim3 ggrid(D_MODEL / 128, M_ROWS / 128);

    // Q projection -> bf16 hi/lo
    split_bf16_kernel<<<nA4 / 256, 256>>>(q, Ah, Al, nA4);
    split_bf16_kernel<<<nW4 / 256, 256>>>(Wq, Wh, Wl, nW4);
    gemm_tc_kernel<<<ggrid, 256, GEMM_SMEM>>>(Ah, Al, Wh, Wl, bq, Qh, Ql, nullptr);
    // K projection
    split_bf16_kernel<<<nA4 / 256, 256>>>(k, Ah, Al, nA4);
    split_bf16_kernel<<<nW4 / 256, 256>>>(Wk, Wh, Wl, nW4);
    gemm_tc_kernel<<<ggrid, 256, GEMM_SMEM>>>(Ah, Al, Wh, Wl, bk, Kh, Kl, nullptr);
    // V projection
    split_bf16_kernel<<<nA4 / 256, 256>>>(v, Ah, Al, nA4);
    split_bf16_kernel<<<nW4 / 256, 256>>>(Wv, Wh, Wl, nW4);
    gemm_tc_kernel<<<ggrid, 256, GEMM_SMEM>>>(Ah, Al, Wh, Wl, bv, Vh, Vl, nullptr);

    // attention (tensor-core flash) -> An hi/lo
    dim3 fgrid(T_ / 128, B_ * N_HEADS);   // (16, 32)
    flash_tc_kernel<<<fgrid, 256, FL_SMEM>>>(Qh, Ql, Kh, Kl, Vh, Vl, mask, causal, Anh, Anl);

    // output projection (f32 out)
    split_bf16_kernel<<<nW4 / 256, 256>>>(Wo, Wh, Wl, nW4);
    gemm_tc_kernel<<<ggrid, 256, GEMM_SMEM>>>(Anh, Anl, Wh, Wl, bo, nullptr, nullptr, out);
}

// round 5
// speedup vs baseline: 2.7586x; 1.0694x over previous
#include <cuda_runtime.h>
#include <cuda_bf16.h>
#include <cstdint>

#define D_MODEL 1024
#define N_HEADS 16
#define D_K     64
#define B_      2
#define T_      2048
#define M_ROWS  (B_ * T_)      // 4096
#define ASZ     (M_ROWS * D_MODEL)
#define WSZ     (D_MODEL * D_MODEL)

// ---------------- scratch (static device globals: allowed) ----------------
__device__ __nv_bfloat16 g_Ah[3 * ASZ];
__device__ __nv_bfloat16 g_Al[3 * ASZ];
__device__ __nv_bfloat16 g_Wh[4 * WSZ];
__device__ __nv_bfloat16 g_Wl[4 * WSZ];
__device__ __nv_bfloat16 g_Qh[ASZ];
__device__ __nv_bfloat16 g_Ql[ASZ];
__device__ __nv_bfloat16 g_Kh[ASZ];
__device__ __nv_bfloat16 g_Kl[ASZ];
__device__ __nv_bfloat16 g_Vh[ASZ];
__device__ __nv_bfloat16 g_Vl[ASZ];
__device__ __nv_bfloat16 g_Anh[ASZ];
__device__ __nv_bfloat16 g_Anl[ASZ];

// =====================================================================
// portable tensor-core helpers (valid on plain sm_103 target)
// =====================================================================
__device__ __forceinline__ uint32_t smem_to_u32(const void* p) {
    uint32_t a;
    asm("{ .reg .u64 t; cvta.to.shared.u64 t, %1; cvt.u32.u64 %0, t; }" : "=r"(a) : "l"(p));
    return a;
}

__device__ __forceinline__ void ldm_x4(uint32_t* r, uint32_t addr) {
    asm volatile("ldmatrix.sync.aligned.m8n8.x4.shared.b16 {%0,%1,%2,%3}, [%4];"
                 : "=r"(r[0]), "=r"(r[1]), "=r"(r[2]), "=r"(r[3]) : "r"(addr));
}
__device__ __forceinline__ void ldm_x4_t(uint32_t* r, uint32_t addr) {
    asm volatile("ldmatrix.sync.aligned.m8n8.x4.trans.shared.b16 {%0,%1,%2,%3}, [%4];"
                 : "=r"(r[0]), "=r"(r[1]), "=r"(r[2]), "=r"(r[3]) : "r"(addr));
}

__device__ __forceinline__ void mma_bf16(float* c, const uint32_t* a, uint32_t b0, uint32_t b1) {
    asm volatile("mma.sync.aligned.m16n8k16.row.col.f32.bf16.bf16.f32 "
                 "{%0,%1,%2,%3}, {%4,%5,%6,%7}, {%8,%9}, {%0,%1,%2,%3};"
                 : "+f"(c[0]), "+f"(c[1]), "+f"(c[2]), "+f"(c[3])
                 : "r"(a[0]), "r"(a[1]), "r"(a[2]), "r"(a[3]), "r"(b0), "r"(b1));
}

#define CP_ASYNC16(saddr, gptr) \
    asm volatile("cp.async.cg.shared.global [%0], [%1], 16;" :: "r"(saddr), "l"(gptr))
#define CP_COMMIT() asm volatile("cp.async.commit_group;" ::: "memory")
#define CP_WAIT1()  asm volatile("cp.async.wait_group 1;" ::: "memory")
#define CP_WAIT0()  asm volatile("cp.async.wait_group 0;" ::: "memory")

__device__ __forceinline__ uint32_t cvt2bf(float hi, float lo) {
    uint32_t r;
    asm("cvt.rn.bf16x2.f32 %0, %1, %2;" : "=r"(r) : "f"(hi), "f"(lo));
    return r;
}

// FFMA-pipe exp (no MUFU): x <= 0, ~1e-4 rel accuracy
__device__ __forceinline__ float fast_exp(float x) {
    x = fmaxf(x, -87.f);
    float t = fmaf(x, 1.442695041f, 12582912.f);
    uint32_t e = __float_as_uint(t);
    float zi = t - 12582912.f;
    float f = fmaf(x, 1.442695041f, -zi);
    float p = fmaf(f, 0.009618130f, 0.055504110f);
    p = fmaf(f, p, 0.240226507f);
    p = fmaf(f, p, 0.693147181f);
    p = fmaf(f, p, 1.0f);
    return p * __uint_as_float((e << 23) + 0x3F800000u);
}

// =====================================================================
// fused fp32 -> bf16 (hi, lo) splits, z-indexed over inputs
// =====================================================================
__device__ __forceinline__ void split_one(const float* __restrict__ x,
                                          __nv_bfloat16* __restrict__ hi,
                                          __nv_bfloat16* __restrict__ lo, int i)
{
    float4 v = reinterpret_cast<const float4*>(x)[i];
    __nv_bfloat16 h0 = __float2bfloat16(v.x);
    __nv_bfloat16 h1 = __float2bfloat16(v.y);
    __nv_bfloat16 h2 = __float2bfloat16(v.z);
    __nv_bfloat16 h3 = __float2bfloat16(v.w);
    __nv_bfloat16 l0 = __float2bfloat16(v.x - __bfloat162float(h0));
    __nv_bfloat16 l1 = __float2bfloat16(v.y - __bfloat162float(h1));
    __nv_bfloat16 l2 = __float2bfloat16(v.z - __bfloat162float(h2));
    __nv_bfloat16 l3 = __float2bfloat16(v.w - __bfloat162float(h3));
    __nv_bfloat162* hp = reinterpret_cast<__nv_bfloat162*>(hi) + i * 2;
    __nv_bfloat162* lp = reinterpret_cast<__nv_bfloat162*>(lo) + i * 2;
    hp[0] = __nv_bfloat162(h0, h1);
    hp[1] = __nv_bfloat162(h2, h3);
    lp[0] = __nv_bfloat162(l0, l1);
    lp[1] = __nv_bfloat162(l2, l3);
}

__global__ __launch_bounds__(256)
void split3_kernel(const float* __restrict__ q, const float* __restrict__ k,
                   const float* __restrict__ v,
                   __nv_bfloat16* __restrict__ hi, __nv_bfloat16* __restrict__ lo)
{
    const int z = blockIdx.z;
    const float* x = (z == 0) ? q : (z == 1) ? k : v;
    int i = blockIdx.x * blockDim.x + threadIdx.x;
    split_one(x, hi + (size_t)z * ASZ, lo + (size_t)z * ASZ, i);
}

__global__ __launch_bounds__(256)
void split4_kernel(const float* __restrict__ w0, const float* __restrict__ w1,
                   const float* __restrict__ w2, const float* __restrict__ w3,
                   __nv_bfloat16* __restrict__ hi, __nv_bfloat16* __restrict__ lo)
{
    const int z = blockIdx.z;
    const float* x = (z == 0) ? w0 : (z == 1) ? w1 : (z == 2) ? w2 : w3;
    int i = blockIdx.x * blockDim.x + threadIdx.x;
    split_one(x, hi + (size_t)z * WSZ, lo + (size_t)z * WSZ, i);
}

// =====================================================================
// mma.sync GEMM core: CTA tile 256x128, BK=32, 8 warps (4m x 2n), warp 64x64
// =====================================================================
#define GP        80
#define AT_B      (256 * GP)           // 20480
#define BT_B      (128 * GP)           // 10240
#define OFF_AH    0
#define OFF_AL    AT_B
#define OFF_BH    (2 * AT_B)
#define OFF_BL    (2 * AT_B + BT_B)
#define STAGE_B   (2 * AT_B + 2 * BT_B)  // 61440
#define GEMM_SMEM (2 * STAGE_B)          // 122880

__device__ __forceinline__ void gemm_core(const __nv_bfloat16* __restrict__ Ah,
                                          const __nv_bfloat16* __restrict__ Al,
                                          const __nv_bfloat16* __restrict__ Bh,
                                          const __nv_bfloat16* __restrict__ Bl,
                                          const float* __restrict__ bias,
                                          __nv_bfloat16* __restrict__ Chi,
                                          __nv_bfloat16* __restrict__ Clo,
                                          float* __restrict__ Cf,
                                          char* sm, int bm, int bn)
{
    const uint32_t smb = smem_to_u32(sm);
    const int tid  = threadIdx.x;
    const int lane = tid & 31;
    const int wid  = tid >> 5;
    const int warp_m = wid & 3;
    const int warp_n = wid >> 2;

    float acc[4][8][4];
#pragma unroll
    for (int mi = 0; mi < 4; ++mi)
#pragma unroll
        for (int nj = 0; nj < 8; ++nj)
#pragma unroll
            for (int e = 0; e < 4; ++e) acc[mi][nj][e] = 0.f;

    auto issue = [&](int c, int j) {
        const int koff = c * 32;
        const uint32_t sb = smb + (uint32_t)j * STAGE_B;
#pragma unroll
        for (int u = tid; u < 1024; u += 256) {
            const int row = u >> 2, cc = u & 3;
            const uint32_t so = (uint32_t)(row * GP + cc * 16);
            const size_t g = (size_t)(bm + row) * D_MODEL + koff + cc * 8;
            CP_ASYNC16(sb + OFF_AH + so, Ah + g);
            CP_ASYNC16(sb + OFF_AL + so, Al + g);
        }
#pragma unroll
        for (int u = tid; u < 512; u += 256) {
            const int row = u >> 2, cc = u & 3;
            const uint32_t so = (uint32_t)(row * GP + cc * 16);
            const size_t g = (size_t)(bn + row) * D_MODEL + koff + cc * 8;
            CP_ASYNC16(sb + OFF_BH + so, Bh + g);
            CP_ASYNC16(sb + OFF_BL + so, Bl + g);
        }
        CP_COMMIT();
    };

    const uint32_t a_lane = (uint32_t)((lane & 15) * GP + (lane >> 4) * 16);
    const uint32_t b_lane = (uint32_t)(((lane & 7) + ((lane >> 4) << 3)) * GP + ((lane >> 3) & 1) * 16);
    const uint32_t aH_base = smb + OFF_AH + (uint32_t)(warp_m * 64 * GP) + a_lane;
    const uint32_t aL_base = smb + OFF_AL + (uint32_t)(warp_m * 64 * GP) + a_lane;
    const uint32_t bH_base = smb + OFF_BH + (uint32_t)(warp_n * 64 * GP) + b_lane;
    const uint32_t bL_base = smb + OFF_BL + (uint32_t)(warp_n * 64 * GP) + b_lane;

    const int NCHUNK = D_MODEL / 32;   // 32
    issue(0, 0);

    for (int c = 0; c < NCHUNK; ++c) {
        const int j = c & 1;
        if (c + 1 < NCHUNK) { issue(c + 1, (c + 1) & 1); CP_WAIT1(); }
        else                { CP_WAIT0(); }
        __syncthreads();

        const uint32_t stg = (uint32_t)j * STAGE_B;
#pragma unroll
        for (int ks = 0; ks < 2; ++ks) {
            const uint32_t kb = (uint32_t)(ks * 32);
            uint32_t ah[4][4], al[4][4];
#pragma unroll
            for (int mi = 0; mi < 4; ++mi) {
                ldm_x4(ah[mi], aH_base + stg + kb + (uint32_t)(mi * 16 * GP));
                ldm_x4(al[mi], aL_base + stg + kb + (uint32_t)(mi * 16 * GP));
            }
#pragma unroll
            for (int nb = 0; nb < 4; ++nb) {
                uint32_t bhf[4], blf[4];
                ldm_x4(bhf, bH_base + stg + kb + (uint32_t)(nb * 16 * GP));
                ldm_x4(blf, bL_base + stg + kb + (uint32_t)(nb * 16 * GP));
#pragma unroll
                for (int mi = 0; mi < 4; ++mi) {
                    mma_bf16(acc[mi][2 * nb],     ah[mi], bhf[0], bhf[1]);
                    mma_bf16(acc[mi][2 * nb + 1], ah[mi], bhf[2], bhf[3]);
                }
#pragma unroll
                for (int mi = 0; mi < 4; ++mi) {
                    mma_bf16(acc[mi][2 * nb],     ah[mi], blf[0], blf[1]);
                    mma_bf16(acc[mi][2 * nb + 1], ah[mi], blf[2], blf[3]);
                }
#pragma unroll
                for (int mi = 0; mi < 4; ++mi) {
                    mma_bf16(acc[mi][2 * nb],     al[mi], bhf[0], bhf[1]);
                    mma_bf16(acc[mi][2 * nb + 1], al[mi], bhf[2], bhf[3]);
                }
            }
        }
        __syncthreads();
    }

    const int rbase = bm + warp_m * 64;
    const int cbase = bn + warp_n * 64;
#pragma unroll
    for (int mi = 0; mi < 4; ++mi) {
#pragma unroll
        for (int nj = 0; nj < 8; ++nj) {
            const int r0 = rbase + mi * 16 + (lane >> 2);
            const int cc = cbase + nj * 8 + 2 * (lane & 3);
            const float b0 = bias[cc], b1 = bias[cc + 1];
            const float v0 = acc[mi][nj][0] + b0, v1 = acc[mi][nj][1] + b1;
            const float v2 = acc[mi][nj][2] + b0, v3 = acc[mi][nj][3] + b1;
            if (Cf) {
                float2 w0, w1;
                w0.x = v0; w0.y = v1; w1.x = v2; w1.y = v3;
                *reinterpret_cast<float2*>(Cf + (size_t)r0 * D_MODEL + cc) = w0;
                *reinterpret_cast<float2*>(Cf + (size_t)(r0 + 8) * D_MODEL + cc) = w1;
            } else {
                uint32_t hp0 = cvt2bf(v1, v0);
                uint32_t hp1 = cvt2bf(v3, v2);
                float h0 = __uint_as_float(hp0 << 16), h1 = __uint_as_float(hp0 & 0xFFFF0000u);
                float h2 = __uint_as_float(hp1 << 16), h3 = __uint_as_float(hp1 & 0xFFFF0000u);
                uint32_t lp0 = cvt2bf(v1 - h1, v0 - h0);
                uint32_t lp1 = cvt2bf(v3 - h3, v2 - h2);
                *reinterpret_cast<uint32_t*>(Chi + (size_t)r0 * D_MODEL + cc) = hp0;
                *reinterpret_cast<uint32_t*>(Chi + (size_t)(r0 + 8) * D_MODEL + cc) = hp1;
                *reinterpret_cast<uint32_t*>(Clo + (size_t)r0 * D_MODEL + cc) = lp0;
                *reinterpret_cast<uint32_t*>(Clo + (size_t)(r0 + 8) * D_MODEL + cc) = lp1;
            }
        }
    }
}

// fused Q/K/V projection (z selects input/weight/output)
__global__ __launch_bounds__(256, 1)
void gemm_qkv_kernel(const __nv_bfloat16* __restrict__ Ah3, const __nv_bfloat16* __restrict__ Al3,
                     const __nv_bfloat16* __restrict__ Wh4, const __nv_bfloat16* __restrict__ Wl4,
                     const float* __restrict__ bq, const float* __restrict__ bk,
                     const float* __restrict__ bv,
                     __nv_bfloat16* __restrict__ Qh, __nv_bfloat16* __restrict__ Ql,
                     __nv_bfloat16* __restrict__ Kh, __nv_bfloat16* __restrict__ Kl,
                     __nv_bfloat16* __restrict__ Vh, __nv_bfloat16* __restrict__ Vl)
{
    extern __shared__ char sm[];
    const int z = blockIdx.z;
    const float* bias = (z == 0) ? bq : (z == 1) ? bk : bv;
    __nv_bfloat16* Chi = (z == 0) ? Qh : (z == 1) ? Kh : Vh;
    __nv_bfloat16* Clo = (z == 0) ? Ql : (z == 1) ? Kl : Vl;
    gemm_core(Ah3 + (size_t)z * ASZ, Al3 + (size_t)z * ASZ,
              Wh4 + (size_t)z * WSZ, Wl4 + (size_t)z * WSZ,
              bias, Chi, Clo, nullptr, sm, blockIdx.y * 256, blockIdx.x * 128);
}

// output projection (f32 out)
__global__ __launch_bounds__(256, 1)
void gemm_out_kernel(const __nv_bfloat16* __restrict__ Ah, const __nv_bfloat16* __restrict__ Al,
                     const __nv_bfloat16* __restrict__ Bh, const __nv_bfloat16* __restrict__ Bl,
                     const float* __restrict__ bias, float* __restrict__ Cf)
{
    extern __shared__ char sm[];
    gemm_core(Ah, Al, Bh, Bl, bias, nullptr, nullptr, Cf,
              sm, blockIdx.y * 256, blockIdx.x * 128);
}

// =====================================================================
// mma.sync flash attention (unchanged from R4)
// =====================================================================
#define QTERM_B  18432               // 128*72*2
#define KVARR_B  9216                // 64*72*2
#define STG_B    (4 * KVARR_B + 256)
#define FL_SMEM  (2 * QTERM_B + 2 * STG_B)

__global__ __launch_bounds__(256, 1)
void flash_tc_kernel(const __nv_bfloat16* __restrict__ Qh_g, const __nv_bfloat16* __restrict__ Ql_g,
                     const __nv_bfloat16* __restrict__ Kh_g, const __nv_bfloat16* __restrict__ Kl_g,
                     const __nv_bfloat16* __restrict__ Vh_g, const __nv_bfloat16* __restrict__ Vl_g,
                     const int* __restrict__ mask, const int* __restrict__ causal_p,
                     __nv_bfloat16* __restrict__ Oh_g, __nv_bfloat16* __restrict__ Ol_g)
{
    extern __shared__ char smc[];
    const uint32_t smb = smem_to_u32(smc);
    const int tid = threadIdx.x, lane = tid & 31, warp = tid >> 5;
    const int qb = (int)(gridDim.x - 1 - blockIdx.x);
    const int bh = blockIdx.y, b = bh >> 4, h = bh & 15;
    const int causal = *causal_p;
    const int kend = causal ? (2 * qb + 1) : (T_ / 64 - 1);
    const int rowg0 = b * T_ + qb * 128;

    auto issue_kv = [&](int kt, int s) {
        const uint32_t sb = smb + 2u * QTERM_B + (uint32_t)s * STG_B;
        const int tk0 = b * T_ + kt * 64;
#pragma unroll
        for (int u = tid; u < 2048; u += 256) {
            const int arr = u >> 9, rem = u & 511;
            const int row = rem >> 3, c = rem & 7;
            const __nv_bfloat16* base = (arr == 0) ? Kh_g : (arr == 1) ? Kl_g
                                       : (arr == 2) ? Vh_g : Vl_g;
            CP_ASYNC16(sb + (uint32_t)(arr * KVARR_B + row * 144 + c * 16),
                       base + ((size_t)(tk0 + row) * D_MODEL + h * 64 + c * 8));
        }
        if (tid < 64) {
            float mv = (mask[tk0 + tid] == 0) ? -1e30f : 0.f;
            reinterpret_cast<float*>(smc + 2 * QTERM_B + s * STG_B + 4 * KVARR_B)[tid] = mv;
        }
    };

    {
#pragma unroll
        for (int u = tid; u < 2048; u += 256) {
            const int term = u >> 10, rem = u & 1023;
            const int row = rem >> 3, c = rem & 7;
            const __nv_bfloat16* src = (term ? Ql_g : Qh_g)
                + ((size_t)(rowg0 + row) * D_MODEL + h * 64 + c * 8);
            CP_ASYNC16(smb + (uint32_t)(term * QTERM_B + row * 144 + c * 16), src);
        }
        issue_kv(0, 0);
        CP_COMMIT();
    }

    const uint32_t a_lane = (uint32_t)((lane & 15) * 144 + (lane >> 4) * 16);
    const uint32_t b_lane = (uint32_t)(((lane & 7) + ((lane >> 4) << 3)) * 144 + ((lane >> 3) & 1) * 16);

    uint32_t qhf[4][4], qlf[4][4];
    float o[8][4];
#pragma unroll
    for (int nd = 0; nd < 8; ++nd)
#pragma unroll
        for (int e = 0; e < 4; ++e) o[nd][e] = 0.f;
    float m0 = -1e30f, m1 = -1e30f, l0 = 0.f, l1 = 0.f;

    const int r_in_warp = lane >> 2;
    const int rg0 = qb * 128 + warp * 16 + r_in_warp;
    const int rg1 = rg0 + 8;
    const int colb = 2 * (lane & 3);

    for (int kt = 0; kt <= kend; ++kt) {
        CP_WAIT0();
        __syncthreads();

        if (kt == 0) {
            const uint32_t qs = smb + (uint32_t)(warp * 16 * 144);
#pragma unroll
            for (int ks = 0; ks < 4; ++ks) {
                ldm_x4(qhf[ks], qs + a_lane + (uint32_t)(ks * 32));
                ldm_x4(qlf[ks], qs + QTERM_B + a_lane + (uint32_t)(ks * 32));
            }
        }

        const int j = kt & 1;
        const uint32_t sb = smb + 2u * QTERM_B + (uint32_t)j * STG_B;
        const float* madd = reinterpret_cast<const float*>(smc + 2 * QTERM_B + j * STG_B + 4 * KVARR_B);

        float c[8][4];
#pragma unroll
        for (int nj = 0; nj < 8; ++nj)
#pragma unroll
            for (int e = 0; e < 4; ++e) c[nj][e] = 0.f;

#pragma unroll
        for (int ks = 0; ks < 4; ++ks) {
            const uint32_t kb = (uint32_t)(ks * 32);
#pragma unroll
            for (int nb = 0; nb < 4; ++nb) {
                uint32_t rh[4], rl[4];
                ldm_x4(rh, sb + 0 * KVARR_B + b_lane + (uint32_t)(nb * 2304) + kb);
                ldm_x4(rl, sb + 1 * KVARR_B + b_lane + (uint32_t)(nb * 2304) + kb);
                mma_bf16(c[2 * nb],     qhf[ks], rh[0], rh[1]);
                mma_bf16(c[2 * nb],     qhf[ks], rl[0], rl[1]);
                mma_bf16(c[2 * nb],     qlf[ks], rh[0], rh[1]);
                mma_bf16(c[2 * nb + 1], qhf[ks], rh[2], rh[3]);
                mma_bf16(c[2 * nb + 1], qhf[ks], rl[2], rl[3]);
                mma_bf16(c[2 * nb + 1], qlf[ks], rh[2], rh[3]);
            }
        }

        const bool diag = (causal != 0) && (kt >= 2 * qb);
        float mx0 = -1e30f, mx1 = -1e30f;
#pragma unroll
        for (int nj = 0; nj < 8; ++nj) {
            const int cl = nj * 8 + colb;
            const int cg = kt * 64 + cl;
            const float ma0 = madd[cl], ma1 = madd[cl + 1];
            float s0 = fmaf(c[nj][0], 0.125f, ma0);
            float s1 = fmaf(c[nj][1], 0.125f, ma1);
            float s2 = fmaf(c[nj][2], 0.125f, ma0);
            float s3 = fmaf(c[nj][3], 0.125f, ma1);
            if (diag) {
                if (cg > rg0)     s0 = -1e30f;
                if (cg + 1 > rg0) s1 = -1e30f;
                if (cg > rg1)     s2 = -1e30f;
                if (cg + 1 > rg1) s3 = -1e30f;
            }
            c[nj][0] = s0; c[nj][1] = s1; c[nj][2] = s2; c[nj][3] = s3;
            mx0 = fmaxf(mx0, fmaxf(s0, s1));
            mx1 = fmaxf(mx1, fmaxf(s2, s3));
        }
        mx0 = fmaxf(mx0, __shfl_xor_sync(0xffffffffu, mx0, 1));
        mx0 = fmaxf(mx0, __shfl_xor_sync(0xffffffffu, mx0, 2));
        mx1 = fmaxf(mx1, __shfl_xor_sync(0xffffffffu, mx1, 1));
        mx1 = fmaxf(mx1, __shfl_xor_sync(0xffffffffu, mx1, 2));

        const float mn0 = fmaxf(m0, mx0), mn1 = fmaxf(m1, mx1);
        const float al0 = fast_exp(m0 - mn0), al1 = fast_exp(m1 - mn1);
        float rs0 = 0.f, rs1 = 0.f;
#pragma unroll
        for (int nj = 0; nj < 8; ++nj) {
            float p0 = fast_exp(c[nj][0] - mn0);
            float p1 = fast_exp(c[nj][1] - mn0);
            float p2 = fast_exp(c[nj][2] - mn1);
            float p3 = fast_exp(c[nj][3] - mn1);
            c[nj][0] = p0; c[nj][1] = p1; c[nj][2] = p2; c[nj][3] = p3;
            rs0 += p0 + p1; rs1 += p2 + p3;
        }
        rs0 += __shfl_xor_sync(0xffffffffu, rs0, 1);
        rs0 += __shfl_xor_sync(0xffffffffu, rs0, 2);
        rs1 += __shfl_xor_sync(0xffffffffu, rs1, 1);
        rs1 += __shfl_xor_sync(0xffffffffu, rs1, 2);
        l0 = l0 * al0 + rs0; m0 = mn0;
        l1 = l1 * al1 + rs1; m1 = mn1;
#pragma unroll
        for (int nd = 0; nd < 8; ++nd) {
            o[nd][0] *= al0; o[nd][1] *= al0;
            o[nd][2] *= al1; o[nd][3] *= al1;
        }

        uint32_t pfh[4][4], pfl[4][4];
#pragma unroll
        for (int ks = 0; ks < 4; ++ks) {
#pragma unroll
            for (int half = 0; half < 2; ++half) {
                const int nj = 2 * ks + half;
                uint32_t hpA = cvt2bf(c[nj][1], c[nj][0]);
                uint32_t hpB = cvt2bf(c[nj][3], c[nj][2]);
                float hA0 = __uint_as_float(hpA << 16), hA1 = __uint_as_float(hpA & 0xFFFF0000u);
                float hB0 = __uint_as_float(hpB << 16), hB1 = __uint_as_float(hpB & 0xFFFF0000u);
                uint32_t lpA = cvt2bf(c[nj][1] - hA1, c[nj][0] - hA0);
                uint32_t lpB = cvt2bf(c[nj][3] - hB1, c[nj][2] - hB0);
                pfh[ks][2 * half + 0] = hpA; pfh[ks][2 * half + 1] = hpB;
                pfl[ks][2 * half + 0] = lpA; pfl[ks][2 * half + 1] = lpB;
            }
        }

        const uint32_t v_lane = (uint32_t)((lane & 15) * 144 + (lane >> 4) * 16);
#pragma unroll
        for (int ks = 0; ks < 4; ++ks) {
#pragma unroll
            for (int nb = 0; nb < 4; ++nb) {
                uint32_t vh[4], vl[4];
                const uint32_t va = sb + 2u * KVARR_B + v_lane
                                  + (uint32_t)(ks * 16 * 144) + (uint32_t)(nb * 32);
                ldm_x4_t(vh, va);
                ldm_x4_t(vl, va + KVARR_B);
                mma_bf16(o[2 * nb],     pfh[ks], vh[0], vh[1]);
                mma_bf16(o[2 * nb],     pfh[ks], vl[0], vl[1]);
                mma_bf16(o[2 * nb],     pfl[ks], vh[0], vh[1]);
                mma_bf16(o[2 * nb + 1], pfh[ks], vh[2], vh[3]);
                mma_bf16(o[2 * nb + 1], pfh[ks], vl[2], vl[3]);
                mma_bf16(o[2 * nb + 1], pfl[ks], vh[2], vh[3]);
            }
        }

        __syncthreads();
        if (kt + 1 <= kend) { issue_kv(kt + 1, (kt + 1) & 1); CP_COMMIT(); }
    }

    const float inv0 = __fdividef(1.f, l0);
    const float inv1 = __fdividef(1.f, l1);
    const size_t gr0 = (size_t)(rowg0 + warp * 16 + r_in_warp) * D_MODEL + h * 64;
    const size_t gr1 = gr0 + 8 * D_MODEL;
#pragma unroll
    for (int nd = 0; nd < 8; ++nd) {
        const int cc = nd * 8 + colb;
        float v0 = o[nd][0] * inv0, v1 = o[nd][1] * inv0;
        float v2 = o[nd][2] * inv1, v3 = o[nd][3] * inv1;
        uint32_t hp0 = cvt2bf(v1, v0);
        uint32_t hp1 = cvt2bf(v3, v2);
        float h0 = __uint_as_float(hp0 << 16), h1 = __uint_as_float(hp0 & 0xFFFF0000u);
        float h2 = __uint_as_float(hp1 << 16), h3 = __uint_as_float(hp1 & 0xFFFF0000u);
        uint32_t lp0 = cvt2bf(v1 - h1, v0 - h0);
        uint32_t lp1 = cvt2bf(v3 - h3, v2 - h2);
        *reinterpret_cast<uint32_t*>(Oh_g + gr0 + cc) = hp0;
        *reinterpret_cast<uint32_t*>(Oh_g + gr1 + cc) = hp1;
        *reinterpret_cast<uint32_t*>(Ol_g + gr0 + cc) = lp0;
        *reinterpret_cast<uint32_t*>(Ol_g + gr1 + cc) = lp1;
    }
}

// =====================================================================
// launch
// =====================================================================
extern "C" void kernel_launch(void* const* d_in, const int* in_sizes, int n_in,
                              void* d_out, int out_size)
{
    const float* q    = (const float*)d_in[0];
    const float* k    = (const float*)d_in[1];
    const float* v    = (const float*)d_in[2];
    const float* Wq   = (const float*)d_in[3];
    const float* bq   = (const float*)d_in[4];
    const float* Wk   = (const float*)d_in[5];
    const float* bk   = (const float*)d_in[6];
    const float* Wv   = (const float*)d_in[7];
    const float* bv   = (const float*)d_in[8];
    const float* Wo   = (const float*)d_in[9];
    const float* bo   = (const float*)d_in[10];
    const int*   mask = (const int*)d_in[11];
    const int*   causal = (const int*)d_in[12];
    float* out = (float*)d_out;

    __nv_bfloat16 *Ah, *Al, *Wh, *Wl, *Qh, *Ql, *Kh, *Kl, *Vh, *Vl, *Anh, *Anl;
    cudaGetSymbolAddress((void**)&Ah, g_Ah);
    cudaGetSymbolAddress((void**)&Al, g_Al);
    cudaGetSymbolAddress((void**)&Wh, g_Wh);
    cudaGetSymbolAddress((void**)&Wl, g_Wl);
    cudaGetSymbolAddress((void**)&Qh, g_Qh);
    cudaGetSymbolAddress((void**)&Ql, g_Ql);
    cudaGetSymbolAddress((void**)&Kh, g_Kh);
    cudaGetSymbolAddress((void**)&Kl, g_Kl);
    cudaGetSymbolAddress((void**)&Vh, g_Vh);
    cudaGetSymbolAddress((void**)&Vl, g_Vl);
    cudaGetSymbolAddress((void**)&Anh, g_Anh);
    cudaGetSymbolAddress((void**)&Anl, g_Anl);

    cudaFuncSetAttribute(gemm_qkv_kernel,
                         cudaFuncAttributeMaxDynamicSharedMemorySize, GEMM_SMEM);
    cudaFuncSetAttribute(gemm_out_kernel,
                         cudaFuncAttributeMaxDynamicSharedMemorySize, GEMM_SMEM);
    cudaFuncSetAttribute(flash_tc_kernel,
                         cudaFuncAttributeMaxDynamicSharedMemorySize, FL_SMEM);

    const int nA4 = ASZ / 4;
    const int nW4 = WSZ / 4;

    // splits: q,k,v -> Ah/Al slab; Wq..Wo -> Wh/Wl slab
    split3_kernel<<<dim3(nA4 / 256, 1, 3), 256>>>(q, k, v, Ah, Al);
    split4_kernel<<<dim3(nW4 / 256, 1, 4), 256>>>(Wq, Wk, Wv, Wo, Wh, Wl);

    // fused Q/K/V projections
    gemm_qkv_kernel<<<dim3(D_MODEL / 128, M_ROWS / 256, 3), 256, GEMM_SMEM>>>(
        Ah, Al, Wh, Wl, bq, bk, bv, Qh, Ql, Kh, Kl, Vh, Vl);

    // attention
    dim3 fgrid(T_ / 128, B_ * N_HEADS);
    flash_tc_kernel<<<fgrid, 256, FL_SMEM>>>(Qh, Ql, Kh, Kl, Vh, Vl, mask, causal, Anh, Anl);

    // output projection
    gemm_out_kernel<<<dim3(D_MODEL / 128, M_ROWS / 256), 256, GEMM_SMEM>>>(
        Anh, Anl, Wh + (size_t)3 * WSZ, Wl + (size_t)3 * WSZ, bo, out);
}

// round 6
// speedup vs baseline: 2.8862x; 1.0463x over previous
#include <cuda_runtime.h>
#include <cuda_bf16.h>
#include <cstdint>

#define D_MODEL 1024
#define N_HEADS 16
#define D_K     64
#define B_      2
#define T_      2048
#define M_ROWS  (B_ * T_)      // 4096
#define ASZ     (M_ROWS * D_MODEL)
#define WSZ     (D_MODEL * D_MODEL)

// ---------------- scratch (static device globals: allowed) ----------------
__device__ __nv_bfloat16 g_Ah[3 * ASZ];
__device__ __nv_bfloat16 g_Al[3 * ASZ];
__device__ __nv_bfloat16 g_Wh[4 * WSZ];
__device__ __nv_bfloat16 g_Wl[4 * WSZ];
__device__ __nv_bfloat16 g_Qh[ASZ];
__device__ __nv_bfloat16 g_Ql[ASZ];
__device__ __nv_bfloat16 g_Kh[ASZ];
__device__ __nv_bfloat16 g_Kl[ASZ];
__device__ __nv_bfloat16 g_Vh[ASZ];
__device__ __nv_bfloat16 g_Vl[ASZ];
__device__ __nv_bfloat16 g_Anh[ASZ];
__device__ __nv_bfloat16 g_Anl[ASZ];

// =====================================================================
// portable tensor-core helpers (valid on plain sm_103 target)
// =====================================================================
__device__ __forceinline__ uint32_t smem_to_u32(const void* p) {
    uint32_t a;
    asm("{ .reg .u64 t; cvta.to.shared.u64 t, %1; cvt.u32.u64 %0, t; }" : "=r"(a) : "l"(p));
    return a;
}

__device__ __forceinline__ void ldm_x4(uint32_t* r, uint32_t addr) {
    asm volatile("ldmatrix.sync.aligned.m8n8.x4.shared.b16 {%0,%1,%2,%3}, [%4];"
                 : "=r"(r[0]), "=r"(r[1]), "=r"(r[2]), "=r"(r[3]) : "r"(addr));
}
__device__ __forceinline__ void ldm_x4_t(uint32_t* r, uint32_t addr) {
    asm volatile("ldmatrix.sync.aligned.m8n8.x4.trans.shared.b16 {%0,%1,%2,%3}, [%4];"
                 : "=r"(r[0]), "=r"(r[1]), "=r"(r[2]), "=r"(r[3]) : "r"(addr));
}

__device__ __forceinline__ void mma_bf16(float* c, const uint32_t* a, uint32_t b0, uint32_t b1) {
    asm volatile("mma.sync.aligned.m16n8k16.row.col.f32.bf16.bf16.f32 "
                 "{%0,%1,%2,%3}, {%4,%5,%6,%7}, {%8,%9}, {%0,%1,%2,%3};"
                 : "+f"(c[0]), "+f"(c[1]), "+f"(c[2]), "+f"(c[3])
                 : "r"(a[0]), "r"(a[1]), "r"(a[2]), "r"(a[3]), "r"(b0), "r"(b1));
}

#define CP_ASYNC16(saddr, gptr) \
    asm volatile("cp.async.cg.shared.global [%0], [%1], 16;" :: "r"(saddr), "l"(gptr))
#define CP_COMMIT() asm volatile("cp.async.commit_group;" ::: "memory")
#define CP_WAIT1()  asm volatile("cp.async.wait_group 1;" ::: "memory")
#define CP_WAIT0()  asm volatile("cp.async.wait_group 0;" ::: "memory")

__device__ __forceinline__ uint32_t cvt2bf(float hi, float lo) {
    uint32_t r;
    asm("cvt.rn.bf16x2.f32 %0, %1, %2;" : "=r"(r) : "f"(hi), "f"(lo));
    return r;
}

// MUFU exp2 (runs on MUFU pipe, overlaps tensor/fma)
__device__ __forceinline__ float ex2f(float x) {
    float y;
    asm("ex2.approx.f32 %0, %1;" : "=f"(y) : "f"(x));
    return y;
}

// =====================================================================
// fused fp32 -> bf16 (hi, lo) splits, z-indexed over inputs
// =====================================================================
__device__ __forceinline__ void split_one(const float* __restrict__ x,
                                          __nv_bfloat16* __restrict__ hi,
                                          __nv_bfloat16* __restrict__ lo, int i)
{
    float4 v = reinterpret_cast<const float4*>(x)[i];
    __nv_bfloat16 h0 = __float2bfloat16(v.x);
    __nv_bfloat16 h1 = __float2bfloat16(v.y);
    __nv_bfloat16 h2 = __float2bfloat16(v.z);
    __nv_bfloat16 h3 = __float2bfloat16(v.w);
    __nv_bfloat16 l0 = __float2bfloat16(v.x - __bfloat162float(h0));
    __nv_bfloat16 l1 = __float2bfloat16(v.y - __bfloat162float(h1));
    __nv_bfloat16 l2 = __float2bfloat16(v.z - __bfloat162float(h2));
    __nv_bfloat16 l3 = __float2bfloat16(v.w - __bfloat162float(h3));
    __nv_bfloat162* hp = reinterpret_cast<__nv_bfloat162*>(hi) + i * 2;
    __nv_bfloat162* lp = reinterpret_cast<__nv_bfloat162*>(lo) + i * 2;
    hp[0] = __nv_bfloat162(h0, h1);
    hp[1] = __nv_bfloat162(h2, h3);
    lp[0] = __nv_bfloat162(l0, l1);
    lp[1] = __nv_bfloat162(l2, l3);
}

__global__ __launch_bounds__(256)
void split3_kernel(const float* __restrict__ q, const float* __restrict__ k,
                   const float* __restrict__ v,
                   __nv_bfloat16* __restrict__ hi, __nv_bfloat16* __restrict__ lo)
{
    const int z = blockIdx.z;
    const float* x = (z == 0) ? q : (z == 1) ? k : v;
    int i = blockIdx.x * blockDim.x + threadIdx.x;
    split_one(x, hi + (size_t)z * ASZ, lo + (size_t)z * ASZ, i);
}

__global__ __launch_bounds__(256)
void split4_kernel(const float* __restrict__ w0, const float* __restrict__ w1,
                   const float* __restrict__ w2, const float* __restrict__ w3,
                   __nv_bfloat16* __restrict__ hi, __nv_bfloat16* __restrict__ lo)
{
    const int z = blockIdx.z;
    const float* x = (z == 0) ? w0 : (z == 1) ? w1 : (z == 2) ? w2 : w3;
    int i = blockIdx.x * blockDim.x + threadIdx.x;
    split_one(x, hi + (size_t)z * WSZ, lo + (size_t)z * WSZ, i);
}

// =====================================================================
// mma.sync GEMM core: CTA tile 256x128, BK=32, 8 warps (4m x 2n), warp 64x64
// 3-stage cp.async pipeline, one __syncthreads per chunk.
// =====================================================================
#define GP        80
#define AT_B      (256 * GP)           // 20480
#define BT_B      (128 * GP)           // 10240
#define OFF_AH    0
#define OFF_AL    AT_B
#define OFF_BH    (2 * AT_B)
#define OFF_BL    (2 * AT_B + BT_B)
#define STAGE_B   (2 * AT_B + 2 * BT_B)  // 61440
#define NSTAGE    3
#define GEMM_SMEM (NSTAGE * STAGE_B)     // 184320

__device__ __forceinline__ void gemm_core(const __nv_bfloat16* __restrict__ Ah,
                                          const __nv_bfloat16* __restrict__ Al,
                                          const __nv_bfloat16* __restrict__ Bh,
                                          const __nv_bfloat16* __restrict__ Bl,
                                          const float* __restrict__ bias,
                                          __nv_bfloat16* __restrict__ Chi,
                                          __nv_bfloat16* __restrict__ Clo,
                                          float* __restrict__ Cf,
                                          char* sm, int bm, int bn)
{
    const uint32_t smb = smem_to_u32(sm);
    const int tid  = threadIdx.x;
    const int lane = tid & 31;
    const int wid  = tid >> 5;
    const int warp_m = wid & 3;
    const int warp_n = wid >> 2;

    float acc[4][8][4];
#pragma unroll
    for (int mi = 0; mi < 4; ++mi)
#pragma unroll
        for (int nj = 0; nj < 8; ++nj)
#pragma unroll
            for (int e = 0; e < 4; ++e) acc[mi][nj][e] = 0.f;

    auto issue = [&](int c, int j) {
        const int koff = c * 32;
        const uint32_t sb = smb + (uint32_t)j * STAGE_B;
#pragma unroll
        for (int u = tid; u < 1024; u += 256) {
            const int row = u >> 2, cc = u & 3;
            const uint32_t so = (uint32_t)(row * GP + cc * 16);
            const size_t g = (size_t)(bm + row) * D_MODEL + koff + cc * 8;
            CP_ASYNC16(sb + OFF_AH + so, Ah + g);
            CP_ASYNC16(sb + OFF_AL + so, Al + g);
        }
#pragma unroll
        for (int u = tid; u < 512; u += 256) {
            const int row = u >> 2, cc = u & 3;
            const uint32_t so = (uint32_t)(row * GP + cc * 16);
            const size_t g = (size_t)(bn + row) * D_MODEL + koff + cc * 8;
            CP_ASYNC16(sb + OFF_BH + so, Bh + g);
            CP_ASYNC16(sb + OFF_BL + so, Bl + g);
        }
        CP_COMMIT();
    };

    const uint32_t a_lane = (uint32_t)((lane & 15) * GP + (lane >> 4) * 16);
    const uint32_t b_lane = (uint32_t)(((lane & 7) + ((lane >> 4) << 3)) * GP + ((lane >> 3) & 1) * 16);
    const uint32_t aH_base = smb + OFF_AH + (uint32_t)(warp_m * 64 * GP) + a_lane;
    const uint32_t aL_base = smb + OFF_AL + (uint32_t)(warp_m * 64 * GP) + a_lane;
    const uint32_t bH_base = smb + OFF_BH + (uint32_t)(warp_n * 64 * GP) + b_lane;
    const uint32_t bL_base = smb + OFF_BL + (uint32_t)(warp_n * 64 * GP) + b_lane;

    const int NCHUNK = D_MODEL / 32;   // 32
    issue(0, 0);
    issue(1, 1);

    for (int c = 0; c < NCHUNK; ++c) {
        const int j = c % NSTAGE;
        if (c == NCHUNK - 1) { CP_WAIT0(); } else { CP_WAIT1(); }
        __syncthreads();
        if (c + 2 < NCHUNK) issue(c + 2, (c + 2) % NSTAGE);

        const uint32_t stg = (uint32_t)j * STAGE_B;
#pragma unroll
        for (int ks = 0; ks < 2; ++ks) {
            const uint32_t kb = (uint32_t)(ks * 32);
            uint32_t ah[4][4], al[4][4];
#pragma unroll
            for (int mi = 0; mi < 4; ++mi) {
                ldm_x4(ah[mi], aH_base + stg + kb + (uint32_t)(mi * 16 * GP));
                ldm_x4(al[mi], aL_base + stg + kb + (uint32_t)(mi * 16 * GP));
            }
#pragma unroll
            for (int nb = 0; nb < 4; ++nb) {
                uint32_t bhf[4], blf[4];
                ldm_x4(bhf, bH_base + stg + kb + (uint32_t)(nb * 16 * GP));
                ldm_x4(blf, bL_base + stg + kb + (uint32_t)(nb * 16 * GP));
#pragma unroll
                for (int mi = 0; mi < 4; ++mi) {
                    mma_bf16(acc[mi][2 * nb],     ah[mi], bhf[0], bhf[1]);
                    mma_bf16(acc[mi][2 * nb + 1], ah[mi], bhf[2], bhf[3]);
                }
#pragma unroll
                for (int mi = 0; mi < 4; ++mi) {
                    mma_bf16(acc[mi][2 * nb],     ah[mi], blf[0], blf[1]);
                    mma_bf16(acc[mi][2 * nb + 1], ah[mi], blf[2], blf[3]);
                }
#pragma unroll
                for (int mi = 0; mi < 4; ++mi) {
                    mma_bf16(acc[mi][2 * nb],     al[mi], bhf[0], bhf[1]);
                    mma_bf16(acc[mi][2 * nb + 1], al[mi], bhf[2], bhf[3]);
                }
            }
        }
    }

    const int rbase = bm + warp_m * 64;
    const int cbase = bn + warp_n * 64;
#pragma unroll
    for (int mi = 0; mi < 4; ++mi) {
#pragma unroll
        for (int nj = 0; nj < 8; ++nj) {
            const int r0 = rbase + mi * 16 + (lane >> 2);
            const int cc = cbase + nj * 8 + 2 * (lane & 3);
            const float b0 = bias[cc], b1 = bias[cc + 1];
            const float v0 = acc[mi][nj][0] + b0, v1 = acc[mi][nj][1] + b1;
            const float v2 = acc[mi][nj][2] + b0, v3 = acc[mi][nj][3] + b1;
            if (Cf) {
                float2 w0, w1;
                w0.x = v0; w0.y = v1; w1.x = v2; w1.y = v3;
                *reinterpret_cast<float2*>(Cf + (size_t)r0 * D_MODEL + cc) = w0;
                *reinterpret_cast<float2*>(Cf + (size_t)(r0 + 8) * D_MODEL + cc) = w1;
            } else {
                uint32_t hp0 = cvt2bf(v1, v0);
                uint32_t hp1 = cvt2bf(v3, v2);
                float h0 = __uint_as_float(hp0 << 16), h1 = __uint_as_float(hp0 & 0xFFFF0000u);
                float h2 = __uint_as_float(hp1 << 16), h3 = __uint_as_float(hp1 & 0xFFFF0000u);
                uint32_t lp0 = cvt2bf(v1 - h1, v0 - h0);
                uint32_t lp1 = cvt2bf(v3 - h3, v2 - h2);
                *reinterpret_cast<uint32_t*>(Chi + (size_t)r0 * D_MODEL + cc) = hp0;
                *reinterpret_cast<uint32_t*>(Chi + (size_t)(r0 + 8) * D_MODEL + cc) = hp1;
                *reinterpret_cast<uint32_t*>(Clo + (size_t)r0 * D_MODEL + cc) = lp0;
                *reinterpret_cast<uint32_t*>(Clo + (size_t)(r0 + 8) * D_MODEL + cc) = lp1;
            }
        }
    }
}

__global__ __launch_bounds__(256, 1)
void gemm_qkv_kernel(const __nv_bfloat16* __restrict__ Ah3, const __nv_bfloat16* __restrict__ Al3,
                     const __nv_bfloat16* __restrict__ Wh4, const __nv_bfloat16* __restrict__ Wl4,
                     const float* __restrict__ bq, const float* __restrict__ bk,
                     const float* __restrict__ bv,
                     __nv_bfloat16* __restrict__ Qh, __nv_bfloat16* __restrict__ Ql,
                     __nv_bfloat16* __restrict__ Kh, __nv_bfloat16* __restrict__ Kl,
                     __nv_bfloat16* __restrict__ Vh, __nv_bfloat16* __restrict__ Vl)
{
    extern __shared__ char sm[];
    const int z = blockIdx.z;
    const float* bias = (z == 0) ? bq : (z == 1) ? bk : bv;
    __nv_bfloat16* Chi = (z == 0) ? Qh : (z == 1) ? Kh : Vh;
    __nv_bfloat16* Clo = (z == 0) ? Ql : (z == 1) ? Kl : Vl;
    gemm_core(Ah3 + (size_t)z * ASZ, Al3 + (size_t)z * ASZ,
              Wh4 + (size_t)z * WSZ, Wl4 + (size_t)z * WSZ,
              bias, Chi, Clo, nullptr, sm, blockIdx.y * 256, blockIdx.x * 128);
}

__global__ __launch_bounds__(256, 1)
void gemm_out_kernel(const __nv_bfloat16* __restrict__ Ah, const __nv_bfloat16* __restrict__ Al,
                     const __nv_bfloat16* __restrict__ Bh, const __nv_bfloat16* __restrict__ Bl,
                     const float* __restrict__ bias, float* __restrict__ Cf)
{
    extern __shared__ char sm[];
    gemm_core(Ah, Al, Bh, Bl, bias, nullptr, nullptr, Cf,
              sm, blockIdx.y * 256, blockIdx.x * 128);
}

// =====================================================================
// mma.sync flash attention — 2 CTAs/SM target (<=128 regs), ex2 softmax
// =====================================================================
#define QTERM_B  18432               // 128*72*2
#define KVARR_B  9216                // 64*72*2
#define STG_B    (4 * KVARR_B + 256)
#define FL_SMEM  (2 * QTERM_B + 2 * STG_B)   // 111104
#define SCL2E    0.180336879f        // 0.125 * log2(e)

__global__ __launch_bounds__(256, 2)
void flash_tc_kernel(const __nv_bfloat16* __restrict__ Qh_g, const __nv_bfloat16* __restrict__ Ql_g,
                     const __nv_bfloat16* __restrict__ Kh_g, const __nv_bfloat16* __restrict__ Kl_g,
                     const __nv_bfloat16* __restrict__ Vh_g, const __nv_bfloat16* __restrict__ Vl_g,
                     const int* __restrict__ mask, const int* __restrict__ causal_p,
                     __nv_bfloat16* __restrict__ Oh_g, __nv_bfloat16* __restrict__ Ol_g)
{
    extern __shared__ char smc[];
    const uint32_t smb = smem_to_u32(smc);
    const int tid = threadIdx.x, lane = tid & 31, warp = tid >> 5;
    const int qb = (int)(gridDim.x - 1 - blockIdx.x);
    const int bh = blockIdx.y, b = bh >> 4, h = bh & 15;
    const int causal = *causal_p;
    const int kend = causal ? (2 * qb + 1) : (T_ / 64 - 1);
    const int rowg0 = b * T_ + qb * 128;

    auto issue_kv = [&](int kt, int s) {
        const uint32_t sb = smb + 2u * QTERM_B + (uint32_t)s * STG_B;
        const int tk0 = b * T_ + kt * 64;
#pragma unroll
        for (int u = tid; u < 2048; u += 256) {
            const int arr = u >> 9, rem = u & 511;
            const int row = rem >> 3, c = rem & 7;
            const __nv_bfloat16* base = (arr == 0) ? Kh_g : (arr == 1) ? Kl_g
                                       : (arr == 2) ? Vh_g : Vl_g;
            CP_ASYNC16(sb + (uint32_t)(arr * KVARR_B + row * 144 + c * 16),
                       base + ((size_t)(tk0 + row) * D_MODEL + h * 64 + c * 8));
        }
        if (tid < 64) {
            float mv = (mask[tk0 + tid] == 0) ? -1e30f : 0.f;
            reinterpret_cast<float*>(smc + 2 * QTERM_B + s * STG_B + 4 * KVARR_B)[tid] = mv;
        }
    };

    {
#pragma unroll
        for (int u = tid; u < 2048; u += 256) {
            const int term = u >> 10, rem = u & 1023;
            const int row = rem >> 3, c = rem & 7;
            const __nv_bfloat16* src = (term ? Ql_g : Qh_g)
                + ((size_t)(rowg0 + row) * D_MODEL + h * 64 + c * 8);
            CP_ASYNC16(smb + (uint32_t)(term * QTERM_B + row * 144 + c * 16), src);
        }
        issue_kv(0, 0);
        CP_COMMIT();
    }

    const uint32_t a_lane = (uint32_t)((lane & 15) * 144 + (lane >> 4) * 16);
    const uint32_t b_lane = (uint32_t)(((lane & 7) + ((lane >> 4) << 3)) * 144 + ((lane >> 3) & 1) * 16);
    const uint32_t qsH = smb + (uint32_t)(warp * 16 * 144) + a_lane;
    const uint32_t qsL = qsH + QTERM_B;

    uint32_t qhf[4][4];        // Q-high fragments persistent; Q-low reloaded per ks
    float o[8][4];
#pragma unroll
    for (int nd = 0; nd < 8; ++nd)
#pragma unroll
        for (int e = 0; e < 4; ++e) o[nd][e] = 0.f;
    float m0 = -1e30f, m1 = -1e30f, l0 = 0.f, l1 = 0.f;

    const int r_in_warp = lane >> 2;
    const int rg0 = qb * 128 + warp * 16 + r_in_warp;
    const int rg1 = rg0 + 8;
    const int colb = 2 * (lane & 3);

    for (int kt = 0; kt <= kend; ++kt) {
        CP_WAIT0();
        __syncthreads();

        if (kt == 0) {
#pragma unroll
            for (int ks = 0; ks < 4; ++ks)
                ldm_x4(qhf[ks], qsH + (uint32_t)(ks * 32));
        }

        const int j = kt & 1;
        const uint32_t sb = smb + 2u * QTERM_B + (uint32_t)j * STG_B;
        const float* madd = reinterpret_cast<const float*>(smc + 2 * QTERM_B + j * STG_B + 4 * KVARR_B);

        // ---- S = Q K^T (3-term) ----
        float c[8][4];
#pragma unroll
        for (int nj = 0; nj < 8; ++nj)
#pragma unroll
            for (int e = 0; e < 4; ++e) c[nj][e] = 0.f;

#pragma unroll
        for (int ks = 0; ks < 4; ++ks) {
            const uint32_t kb = (uint32_t)(ks * 32);
            uint32_t qlf[4];
            ldm_x4(qlf, qsL + kb);
#pragma unroll
            for (int nb = 0; nb < 4; ++nb) {
                uint32_t rh[4], rl[4];
                ldm_x4(rh, sb + 0 * KVARR_B + b_lane + (uint32_t)(nb * 2304) + kb);
                ldm_x4(rl, sb + 1 * KVARR_B + b_lane + (uint32_t)(nb * 2304) + kb);
                mma_bf16(c[2 * nb],     qhf[ks], rh[0], rh[1]);
                mma_bf16(c[2 * nb],     qhf[ks], rl[0], rl[1]);
                mma_bf16(c[2 * nb],     qlf,     rh[0], rh[1]);
                mma_bf16(c[2 * nb + 1], qhf[ks], rh[2], rh[3]);
                mma_bf16(c[2 * nb + 1], qhf[ks], rl[2], rl[3]);
                mma_bf16(c[2 * nb + 1], qlf,     rh[2], rh[3]);
            }
        }

        // ---- scale (log2 domain) + mask + online softmax via ex2 ----
        const bool diag = (causal != 0) && (kt >= 2 * qb);
        float mx0 = -1e30f, mx1 = -1e30f;
#pragma unroll
        for (int nj = 0; nj < 8; ++nj) {
            const int cl = nj * 8 + colb;
            const int cg = kt * 64 + cl;
            const float ma0 = madd[cl], ma1 = madd[cl + 1];
            float s0 = fmaf(c[nj][0], SCL2E, ma0);
            float s1 = fmaf(c[nj][1], SCL2E, ma1);
            float s2 = fmaf(c[nj][2], SCL2E, ma0);
            float s3 = fmaf(c[nj][3], SCL2E, ma1);
            if (diag) {
                if (cg > rg0)     s0 = -1e30f;
                if (cg + 1 > rg0) s1 = -1e30f;
                if (cg > rg1)     s2 = -1e30f;
                if (cg + 1 > rg1) s3 = -1e30f;
            }
            c[nj][0] = s0; c[nj][1] = s1; c[nj][2] = s2; c[nj][3] = s3;
            mx0 = fmaxf(mx0, fmaxf(s0, s1));
            mx1 = fmaxf(mx1, fmaxf(s2, s3));
        }
        mx0 = fmaxf(mx0, __shfl_xor_sync(0xffffffffu, mx0, 1));
        mx0 = fmaxf(mx0, __shfl_xor_sync(0xffffffffu, mx0, 2));
        mx1 = fmaxf(mx1, __shfl_xor_sync(0xffffffffu, mx1, 1));
        mx1 = fmaxf(mx1, __shfl_xor_sync(0xffffffffu, mx1, 2));

        const float mn0 = fmaxf(m0, mx0), mn1 = fmaxf(m1, mx1);
        const float al0 = ex2f(m0 - mn0), al1 = ex2f(m1 - mn1);
        float rs0 = 0.f, rs1 = 0.f;
#pragma unroll
        for (int nj = 0; nj < 8; ++nj) {
            float p0 = ex2f(c[nj][0] - mn0);
            float p1 = ex2f(c[nj][1] - mn0);
            float p2 = ex2f(c[nj][2] - mn1);
            float p3 = ex2f(c[nj][3] - mn1);
            c[nj][0] = p0; c[nj][1] = p1; c[nj][2] = p2; c[nj][3] = p3;
            rs0 += p0 + p1; rs1 += p2 + p3;
        }
        rs0 += __shfl_xor_sync(0xffffffffu, rs0, 1);
        rs0 += __shfl_xor_sync(0xffffffffu, rs0, 2);
        rs1 += __shfl_xor_sync(0xffffffffu, rs1, 1);
        rs1 += __shfl_xor_sync(0xffffffffu, rs1, 2);
        l0 = l0 * al0 + rs0; m0 = mn0;
        l1 = l1 * al1 + rs1; m1 = mn1;
#pragma unroll
        for (int nd = 0; nd < 8; ++nd) {
            o[nd][0] *= al0; o[nd][1] *= al0;
            o[nd][2] *= al1; o[nd][3] *= al1;
        }

        // ---- O += P V (3-term), P split fused per-ks ----
        const uint32_t v_lane = (uint32_t)((lane & 15) * 144 + (lane >> 4) * 16);
#pragma unroll
        for (int ks = 0; ks < 4; ++ks) {
            uint32_t pfh[4], pfl[4];
#pragma unroll
            for (int half = 0; half < 2; ++half) {
                const int nj = 2 * ks + half;
                uint32_t hpA = cvt2bf(c[nj][1], c[nj][0]);
                uint32_t hpB = cvt2bf(c[nj][3], c[nj][2]);
                float hA0 = __uint_as_float(hpA << 16), hA1 = __uint_as_float(hpA & 0xFFFF0000u);
                float hB0 = __uint_as_float(hpB << 16), hB1 = __uint_as_float(hpB & 0xFFFF0000u);
                pfh[2 * half + 0] = hpA; pfh[2 * half + 1] = hpB;
                pfl[2 * half + 0] = cvt2bf(c[nj][1] - hA1, c[nj][0] - hA0);
                pfl[2 * half + 1] = cvt2bf(c[nj][3] - hB1, c[nj][2] - hB0);
            }
#pragma unroll
            for (int nb = 0; nb < 4; ++nb) {
                uint32_t vh[4], vl[4];
                const uint32_t va = sb + 2u * KVARR_B + v_lane
                                  + (uint32_t)(ks * 16 * 144) + (uint32_t)(nb * 32);
                ldm_x4_t(vh, va);
                ldm_x4_t(vl, va + KVARR_B);
                mma_bf16(o[2 * nb],     pfh, vh[0], vh[1]);
                mma_bf16(o[2 * nb],     pfh, vl[0], vl[1]);
                mma_bf16(o[2 * nb],     pfl, vh[0], vh[1]);
                mma_bf16(o[2 * nb + 1], pfh, vh[2], vh[3]);
                mma_bf16(o[2 * nb + 1], pfh, vl[2], vl[3]);
                mma_bf16(o[2 * nb + 1], pfl, vh[2], vh[3]);
            }
        }

        __syncthreads();
        if (kt + 1 <= kend) { issue_kv(kt + 1, (kt + 1) & 1); CP_COMMIT(); }
    }

    const float inv0 = __fdividef(1.f, l0);
    const float inv1 = __fdividef(1.f, l1);
    const size_t gr0 = (size_t)(rowg0 + warp * 16 + r_in_warp) * D_MODEL + h * 64;
    const size_t gr1 = gr0 + 8 * D_MODEL;
#pragma unroll
    for (int nd = 0; nd < 8; ++nd) {
        const int cc = nd * 8 + colb;
        float v0 = o[nd][0] * inv0, v1 = o[nd][1] * inv0;
        float v2 = o[nd][2] * inv1, v3 = o[nd][3] * inv1;
        uint32_t hp0 = cvt2bf(v1, v0);
        uint32_t hp1 = cvt2bf(v3, v2);
        float h0 = __uint_as_float(hp0 << 16), h1 = __uint_as_float(hp0 & 0xFFFF0000u);
        float h2 = __uint_as_float(hp1 << 16), h3 = __uint_as_float(hp1 & 0xFFFF0000u);
        uint32_t lp0 = cvt2bf(v1 - h1, v0 - h0);
        uint32_t lp1 = cvt2bf(v3 - h3, v2 - h2);
        *reinterpret_cast<uint32_t*>(Oh_g + gr0 + cc) = hp0;
        *reinterpret_cast<uint32_t*>(Oh_g + gr1 + cc) = hp1;
        *reinterpret_cast<uint32_t*>(Ol_g + gr0 + cc) = lp0;
        *reinterpret_cast<uint32_t*>(Ol_g + gr1 + cc) = lp1;
    }
}

// =====================================================================
// launch
// =====================================================================
extern "C" void kernel_launch(void* const* d_in, const int* in_sizes, int n_in,
                              void* d_out, int out_size)
{
    const float* q    = (const float*)d_in[0];
    const float* k    = (const float*)d_in[1];
    const float* v    = (const float*)d_in[2];
    const float* Wq   = (const float*)d_in[3];
    const float* bq   = (const float*)d_in[4];
    const float* Wk   = (const float*)d_in[5];
    const float* bk   = (const float*)d_in[6];
    const float* Wv   = (const float*)d_in[7];
    const float* bv   = (const float*)d_in[8];
    const float* Wo   = (const float*)d_in[9];
    const float* bo   = (const float*)d_in[10];
    const int*   mask = (const int*)d_in[11];
    const int*   causal = (const int*)d_in[12];
    float* out = (float*)d_out;

    __nv_bfloat16 *Ah, *Al, *Wh, *Wl, *Qh, *Ql, *Kh, *Kl, *Vh, *Vl, *Anh, *Anl;
    cudaGetSymbolAddress((void**)&Ah, g_Ah);
    cudaGetSymbolAddress((void**)&Al, g_Al);
    cudaGetSymbolAddress((void**)&Wh, g_Wh);
    cudaGetSymbolAddress((void**)&Wl, g_Wl);
    cudaGetSymbolAddress((void**)&Qh, g_Qh);
    cudaGetSymbolAddress((void**)&Ql, g_Ql);
    cudaGetSymbolAddress((void**)&Kh, g_Kh);
    cudaGetSymbolAddress((void**)&Kl, g_Kl);
    cudaGetSymbolAddress((void**)&Vh, g_Vh);
    cudaGetSymbolAddress((void**)&Vl, g_Vl);
    cudaGetSymbolAddress((void**)&Anh, g_Anh);
    cudaGetSymbolAddress((void**)&Anl, g_Anl);

    cudaFuncSetAttribute(gemm_qkv_kernel,
                         cudaFuncAttributeMaxDynamicSharedMemorySize, GEMM_SMEM);
    cudaFuncSetAttribute(gemm_out_kernel,
                         cudaFuncAttributeMaxDynamicSharedMemorySize, GEMM_SMEM);
    cudaFuncSetAttribute(flash_tc_kernel,
                         cudaFuncAttributeMaxDynamicSharedMemorySize, FL_SMEM);

    const int nA4 = ASZ / 4;
    const int nW4 = WSZ / 4;

    split3_kernel<<<dim3(nA4 / 256, 1, 3), 256>>>(q, k, v, Ah, Al);
    split4_kernel<<<dim3(nW4 / 256, 1, 4), 256>>>(Wq, Wk, Wv, Wo, Wh, Wl);

    gemm_qkv_kernel<<<dim3(D_MODEL / 128, M_ROWS / 256, 3), 256, GEMM_SMEM>>>(
        Ah, Al, Wh, Wl, bq, bk, bv, Qh, Ql, Kh, Kl, Vh, Vl);

    dim3 fgrid(T_ / 128, B_ * N_HEADS);
    flash_tc_kernel<<<fgrid, 256, FL_SMEM>>>(Qh, Ql, Kh, Kl, Vh, Vl, mask, causal, Anh, Anl);

    gemm_out_kernel<<<dim3(D_MODEL / 128, M_ROWS / 256), 256, GEMM_SMEM>>>(
        Anh, Anl, Wh + (size_t)3 * WSZ, Wl + (size_t)3 * WSZ, bo, out);
}

// round 7
// speedup vs baseline: 2.9134x; 1.0094x over previous
#include <cuda_runtime.h>
#include <cuda_bf16.h>
#include <cstdint>

#define D_MODEL 1024
#define N_HEADS 16
#define D_K     64
#define B_      2
#define T_      2048
#define M_ROWS  (B_ * T_)      // 4096
#define ASZ     (M_ROWS * D_MODEL)
#define WSZ     (D_MODEL * D_MODEL)

// ---------------- scratch (static device globals: allowed) ----------------
__device__ __nv_bfloat16 g_Ah[3 * ASZ];
__device__ __nv_bfloat16 g_Al[3 * ASZ];
__device__ __nv_bfloat16 g_Wh[4 * WSZ];
__device__ __nv_bfloat16 g_Wl[4 * WSZ];
__device__ __nv_bfloat16 g_Qh[ASZ];
__device__ __nv_bfloat16 g_Ql[ASZ];
__device__ __nv_bfloat16 g_Kh[ASZ];
__device__ __nv_bfloat16 g_Kl[ASZ];
__device__ __nv_bfloat16 g_Vh[ASZ];
__device__ __nv_bfloat16 g_Vl[ASZ];
__device__ __nv_bfloat16 g_Anh[ASZ];
__device__ __nv_bfloat16 g_Anl[ASZ];

// =====================================================================
// portable tensor-core helpers (valid on plain sm_103 target)
// =====================================================================
__device__ __forceinline__ uint32_t smem_to_u32(const void* p) {
    uint32_t a;
    asm("{ .reg .u64 t; cvta.to.shared.u64 t, %1; cvt.u32.u64 %0, t; }" : "=r"(a) : "l"(p));
    return a;
}

__device__ __forceinline__ void ldm_x4(uint32_t* r, uint32_t addr) {
    asm volatile("ldmatrix.sync.aligned.m8n8.x4.shared.b16 {%0,%1,%2,%3}, [%4];"
                 : "=r"(r[0]), "=r"(r[1]), "=r"(r[2]), "=r"(r[3]) : "r"(addr));
}
__device__ __forceinline__ void ldm_x4_t(uint32_t* r, uint32_t addr) {
    asm volatile("ldmatrix.sync.aligned.m8n8.x4.trans.shared.b16 {%0,%1,%2,%3}, [%4];"
                 : "=r"(r[0]), "=r"(r[1]), "=r"(r[2]), "=r"(r[3]) : "r"(addr));
}

__device__ __forceinline__ void mma_bf16(float* c, const uint32_t* a, uint32_t b0, uint32_t b1) {
    asm volatile("mma.sync.aligned.m16n8k16.row.col.f32.bf16.bf16.f32 "
                 "{%0,%1,%2,%3}, {%4,%5,%6,%7}, {%8,%9}, {%0,%1,%2,%3};"
                 : "+f"(c[0]), "+f"(c[1]), "+f"(c[2]), "+f"(c[3])
                 : "r"(a[0]), "r"(a[1]), "r"(a[2]), "r"(a[3]), "r"(b0), "r"(b1));
}

#define CP_ASYNC16(saddr, gptr) \
    asm volatile("cp.async.cg.shared.global [%0], [%1], 16;" :: "r"(saddr), "l"(gptr))
#define CP_COMMIT() asm volatile("cp.async.commit_group;" ::: "memory")
#define CP_WAIT1()  asm volatile("cp.async.wait_group 1;" ::: "memory")
#define CP_WAIT0()  asm volatile("cp.async.wait_group 0;" ::: "memory")

__device__ __forceinline__ uint32_t cvt2bf(float hi, float lo) {
    uint32_t r;
    asm("cvt.rn.bf16x2.f32 %0, %1, %2;" : "=r"(r) : "f"(hi), "f"(lo));
    return r;
}

// MUFU exp2 (runs on MUFU pipe, overlaps tensor/fma)
__device__ __forceinline__ float ex2f(float x) {
    float y;
    asm("ex2.approx.f32 %0, %1;" : "=f"(y) : "f"(x));
    return y;
}

// =====================================================================
// fused fp32 -> bf16 (hi, lo) splits, z-indexed over inputs
// =====================================================================
__device__ __forceinline__ void split_one(const float* __restrict__ x,
                                          __nv_bfloat16* __restrict__ hi,
                                          __nv_bfloat16* __restrict__ lo, int i)
{
    float4 v = reinterpret_cast<const float4*>(x)[i];
    __nv_bfloat16 h0 = __float2bfloat16(v.x);
    __nv_bfloat16 h1 = __float2bfloat16(v.y);
    __nv_bfloat16 h2 = __float2bfloat16(v.z);
    __nv_bfloat16 h3 = __float2bfloat16(v.w);
    __nv_bfloat16 l0 = __float2bfloat16(v.x - __bfloat162float(h0));
    __nv_bfloat16 l1 = __float2bfloat16(v.y - __bfloat162float(h1));
    __nv_bfloat16 l2 = __float2bfloat16(v.z - __bfloat162float(h2));
    __nv_bfloat16 l3 = __float2bfloat16(v.w - __bfloat162float(h3));
    __nv_bfloat162* hp = reinterpret_cast<__nv_bfloat162*>(hi) + i * 2;
    __nv_bfloat162* lp = reinterpret_cast<__nv_bfloat162*>(lo) + i * 2;
    hp[0] = __nv_bfloat162(h0, h1);
    hp[1] = __nv_bfloat162(h2, h3);
    lp[0] = __nv_bfloat162(l0, l1);
    lp[1] = __nv_bfloat162(l2, l3);
}

__global__ __launch_bounds__(256)
void split3_kernel(const float* __restrict__ q, const float* __restrict__ k,
                   const float* __restrict__ v,
                   __nv_bfloat16* __restrict__ hi, __nv_bfloat16* __restrict__ lo)
{
    const int z = blockIdx.z;
    const float* x = (z == 0) ? q : (z == 1) ? k : v;
    int i = blockIdx.x * blockDim.x + threadIdx.x;
    split_one(x, hi + (size_t)z * ASZ, lo + (size_t)z * ASZ, i);
}

__global__ __launch_bounds__(256)
void split4_kernel(const float* __restrict__ w0, const float* __restrict__ w1,
                   const float* __restrict__ w2, const float* __restrict__ w3,
                   __nv_bfloat16* __restrict__ hi, __nv_bfloat16* __restrict__ lo)
{
    const int z = blockIdx.z;
    const float* x = (z == 0) ? w0 : (z == 1) ? w1 : (z == 2) ? w2 : w3;
    int i = blockIdx.x * blockDim.x + threadIdx.x;
    split_one(x, hi + (size_t)z * WSZ, lo + (size_t)z * WSZ, i);
}

// =====================================================================
// mma.sync GEMM core: CTA tile 128x128, BK=32, 8 warps (2m x 4n), warp 64x32
// 2 CTAs/SM, 2-stage cp.async pipeline.
// =====================================================================
#define GP        80
#define TERM_B    (128 * GP)           // 10240
#define OFF_AH    0
#define OFF_AL    TERM_B
#define OFF_BH    (2 * TERM_B)
#define OFF_BL    (3 * TERM_B)
#define STAGE_B   (4 * TERM_B)         // 40960
#define GEMM_SMEM (2 * STAGE_B)        // 81920

__device__ __forceinline__ void gemm_core(const __nv_bfloat16* __restrict__ Ah,
                                          const __nv_bfloat16* __restrict__ Al,
                                          const __nv_bfloat16* __restrict__ Bh,
                                          const __nv_bfloat16* __restrict__ Bl,
                                          const float* __restrict__ bias,
                                          __nv_bfloat16* __restrict__ Chi,
                                          __nv_bfloat16* __restrict__ Clo,
                                          float* __restrict__ Cf,
                                          char* sm, int bm, int bn)
{
    const uint32_t smb = smem_to_u32(sm);
    const int tid  = threadIdx.x;
    const int lane = tid & 31;
    const int wid  = tid >> 5;
    const int warp_m = wid >> 2;   // 0..1
    const int warp_n = wid & 3;    // 0..3

    float acc[4][4][4];
#pragma unroll
    for (int mi = 0; mi < 4; ++mi)
#pragma unroll
        for (int nj = 0; nj < 4; ++nj)
#pragma unroll
            for (int e = 0; e < 4; ++e) acc[mi][nj][e] = 0.f;

    auto issue = [&](int c, int j) {
        const int koff = c * 32;
        const uint32_t sb = smb + (uint32_t)j * STAGE_B;
#pragma unroll
        for (int u = tid; u < 512; u += 256) {
            const int row = u >> 2, cc = u & 3;
            const uint32_t so = (uint32_t)(row * GP + cc * 16);
            const size_t gA = (size_t)(bm + row) * D_MODEL + koff + cc * 8;
            const size_t gB = (size_t)(bn + row) * D_MODEL + koff + cc * 8;
            CP_ASYNC16(sb + OFF_AH + so, Ah + gA);
            CP_ASYNC16(sb + OFF_AL + so, Al + gA);
            CP_ASYNC16(sb + OFF_BH + so, Bh + gB);
            CP_ASYNC16(sb + OFF_BL + so, Bl + gB);
        }
        CP_COMMIT();
    };

    const uint32_t a_lane = (uint32_t)((lane & 15) * GP + (lane >> 4) * 16);
    const uint32_t b_lane = (uint32_t)(((lane & 7) + ((lane >> 4) << 3)) * GP + ((lane >> 3) & 1) * 16);
    const uint32_t aH_base = smb + OFF_AH + (uint32_t)(warp_m * 64 * GP) + a_lane;
    const uint32_t aL_base = smb + OFF_AL + (uint32_t)(warp_m * 64 * GP) + a_lane;
    const uint32_t bH_base = smb + OFF_BH + (uint32_t)(warp_n * 32 * GP) + b_lane;
    const uint32_t bL_base = smb + OFF_BL + (uint32_t)(warp_n * 32 * GP) + b_lane;

    const int NCHUNK = D_MODEL / 32;   // 32
    issue(0, 0);

    for (int c = 0; c < NCHUNK; ++c) {
        const int j = c & 1;
        if (c + 1 < NCHUNK) { issue(c + 1, 1 - j); CP_WAIT1(); }
        else                { CP_WAIT0(); }
        __syncthreads();

        const uint32_t stg = (uint32_t)j * STAGE_B;
#pragma unroll
        for (int ks = 0; ks < 2; ++ks) {
            const uint32_t kb = (uint32_t)(ks * 32);
            uint32_t ah[4][4], al[4][4], bhv[4][2], blv[4][2];
#pragma unroll
            for (int mi = 0; mi < 4; ++mi) {
                ldm_x4(ah[mi], aH_base + stg + kb + (uint32_t)(mi * 16 * GP));
                ldm_x4(al[mi], aL_base + stg + kb + (uint32_t)(mi * 16 * GP));
            }
#pragma unroll
            for (int p = 0; p < 2; ++p) {
                uint32_t r[4];
                ldm_x4(r, bH_base + stg + kb + (uint32_t)(p * 16 * GP));
                bhv[p * 2 + 0][0] = r[0]; bhv[p * 2 + 0][1] = r[1];
                bhv[p * 2 + 1][0] = r[2]; bhv[p * 2 + 1][1] = r[3];
                ldm_x4(r, bL_base + stg + kb + (uint32_t)(p * 16 * GP));
                blv[p * 2 + 0][0] = r[0]; blv[p * 2 + 0][1] = r[1];
                blv[p * 2 + 1][0] = r[2]; blv[p * 2 + 1][1] = r[3];
            }
#pragma unroll
            for (int mi = 0; mi < 4; ++mi)
#pragma unroll
                for (int nj = 0; nj < 4; ++nj)
                    mma_bf16(acc[mi][nj], ah[mi], bhv[nj][0], bhv[nj][1]);
#pragma unroll
            for (int mi = 0; mi < 4; ++mi)
#pragma unroll
                for (int nj = 0; nj < 4; ++nj)
                    mma_bf16(acc[mi][nj], ah[mi], blv[nj][0], blv[nj][1]);
#pragma unroll
            for (int mi = 0; mi < 4; ++mi)
#pragma unroll
                for (int nj = 0; nj < 4; ++nj)
                    mma_bf16(acc[mi][nj], al[mi], bhv[nj][0], bhv[nj][1]);
        }
        __syncthreads();
    }

    const int rbase = bm + warp_m * 64;
    const int cbase = bn + warp_n * 32;
#pragma unroll
    for (int mi = 0; mi < 4; ++mi) {
#pragma unroll
        for (int nj = 0; nj < 4; ++nj) {
            const int r0 = rbase + mi * 16 + (lane >> 2);
            const int cc = cbase + nj * 8 + 2 * (lane & 3);
            const float b0 = bias[cc], b1 = bias[cc + 1];
            const float v0 = acc[mi][nj][0] + b0, v1 = acc[mi][nj][1] + b1;
            const float v2 = acc[mi][nj][2] + b0, v3 = acc[mi][nj][3] + b1;
            if (Cf) {
                float2 w0, w1;
                w0.x = v0; w0.y = v1; w1.x = v2; w1.y = v3;
                *reinterpret_cast<float2*>(Cf + (size_t)r0 * D_MODEL + cc) = w0;
                *reinterpret_cast<float2*>(Cf + (size_t)(r0 + 8) * D_MODEL + cc) = w1;
            } else {
                uint32_t hp0 = cvt2bf(v1, v0);
                uint32_t hp1 = cvt2bf(v3, v2);
                float h0 = __uint_as_float(hp0 << 16), h1 = __uint_as_float(hp0 & 0xFFFF0000u);
                float h2 = __uint_as_float(hp1 << 16), h3 = __uint_as_float(hp1 & 0xFFFF0000u);
                uint32_t lp0 = cvt2bf(v1 - h1, v0 - h0);
                uint32_t lp1 = cvt2bf(v3 - h3, v2 - h2);
                *reinterpret_cast<uint32_t*>(Chi + (size_t)r0 * D_MODEL + cc) = hp0;
                *reinterpret_cast<uint32_t*>(Chi + (size_t)(r0 + 8) * D_MODEL + cc) = hp1;
                *reinterpret_cast<uint32_t*>(Clo + (size_t)r0 * D_MODEL + cc) = lp0;
                *reinterpret_cast<uint32_t*>(Clo + (size_t)(r0 + 8) * D_MODEL + cc) = lp1;
            }
        }
    }
}

__global__ __launch_bounds__(256, 2)
void gemm_qkv_kernel(const __nv_bfloat16* __restrict__ Ah3, const __nv_bfloat16* __restrict__ Al3,
                     const __nv_bfloat16* __restrict__ Wh4, const __nv_bfloat16* __restrict__ Wl4,
                     const float* __restrict__ bq, const float* __restrict__ bk,
                     const float* __restrict__ bv,
                     __nv_bfloat16* __restrict__ Qh, __nv_bfloat16* __restrict__ Ql,
                     __nv_bfloat16* __restrict__ Kh, __nv_bfloat16* __restrict__ Kl,
                     __nv_bfloat16* __restrict__ Vh, __nv_bfloat16* __restrict__ Vl)
{
    extern __shared__ char sm[];
    const int z = blockIdx.z;
    const float* bias = (z == 0) ? bq : (z == 1) ? bk : bv;
    __nv_bfloat16* Chi = (z == 0) ? Qh : (z == 1) ? Kh : Vh;
    __nv_bfloat16* Clo = (z == 0) ? Ql : (z == 1) ? Kl : Vl;
    gemm_core(Ah3 + (size_t)z * ASZ, Al3 + (size_t)z * ASZ,
              Wh4 + (size_t)z * WSZ, Wl4 + (size_t)z * WSZ,
              bias, Chi, Clo, nullptr, sm, blockIdx.y * 128, blockIdx.x * 128);
}

__global__ __launch_bounds__(256, 2)
void gemm_out_kernel(const __nv_bfloat16* __restrict__ Ah, const __nv_bfloat16* __restrict__ Al,
                     const __nv_bfloat16* __restrict__ Bh, const __nv_bfloat16* __restrict__ Bl,
                     const float* __restrict__ bias, float* __restrict__ Cf)
{
    extern __shared__ char sm[];
    gemm_core(Ah, Al, Bh, Bl, bias, nullptr, nullptr, Cf,
              sm, blockIdx.y * 128, blockIdx.x * 128);
}

// =====================================================================
// mma.sync flash attention — 2 CTAs/SM, ex2 softmax, single sync/tile
// =====================================================================
#define QTERM_B  18432               // 128*72*2
#define KVARR_B  9216                // 64*72*2
#define STG_B    (4 * KVARR_B + 256)
#define FL_SMEM  (2 * QTERM_B + 2 * STG_B)   // 111104
#define SCL2E    0.180336879f        // 0.125 * log2(e)

__global__ __launch_bounds__(256, 2)
void flash_tc_kernel(const __nv_bfloat16* __restrict__ Qh_g, const __nv_bfloat16* __restrict__ Ql_g,
                     const __nv_bfloat16* __restrict__ Kh_g, const __nv_bfloat16* __restrict__ Kl_g,
                     const __nv_bfloat16* __restrict__ Vh_g, const __nv_bfloat16* __restrict__ Vl_g,
                     const int* __restrict__ mask, const int* __restrict__ causal_p,
                     __nv_bfloat16* __restrict__ Oh_g, __nv_bfloat16* __restrict__ Ol_g)
{
    extern __shared__ char smc[];
    const uint32_t smb = smem_to_u32(smc);
    const int tid = threadIdx.x, lane = tid & 31, warp = tid >> 5;
    const int qb = (int)(gridDim.x - 1 - blockIdx.x);
    const int bh = blockIdx.y, b = bh >> 4, h = bh & 15;
    const int causal = *causal_p;
    const int kend = causal ? (2 * qb + 1) : (T_ / 64 - 1);
    const int rowg0 = b * T_ + qb * 128;

    auto issue_kv = [&](int kt, int s) {
        const uint32_t sb = smb + 2u * QTERM_B + (uint32_t)s * STG_B;
        const int tk0 = b * T_ + kt * 64;
#pragma unroll
        for (int u = tid; u < 2048; u += 256) {
            const int arr = u >> 9, rem = u & 511;
            const int row = rem >> 3, c = rem & 7;
            const __nv_bfloat16* base = (arr == 0) ? Kh_g : (arr == 1) ? Kl_g
                                       : (arr == 2) ? Vh_g : Vl_g;
            CP_ASYNC16(sb + (uint32_t)(arr * KVARR_B + row * 144 + c * 16),
                       base + ((size_t)(tk0 + row) * D_MODEL + h * 64 + c * 8));
        }
        if (tid < 64) {
            float mv = (mask[tk0 + tid] == 0) ? -1e30f : 0.f;
            reinterpret_cast<float*>(smc + 2 * QTERM_B + s * STG_B + 4 * KVARR_B)[tid] = mv;
        }
    };

    {
#pragma unroll
        for (int u = tid; u < 2048; u += 256) {
            const int term = u >> 10, rem = u & 1023;
            const int row = rem >> 3, c = rem & 7;
            const __nv_bfloat16* src = (term ? Ql_g : Qh_g)
                + ((size_t)(rowg0 + row) * D_MODEL + h * 64 + c * 8);
            CP_ASYNC16(smb + (uint32_t)(term * QTERM_B + row * 144 + c * 16), src);
        }
        issue_kv(0, 0);
        CP_COMMIT();
    }

    const uint32_t a_lane = (uint32_t)((lane & 15) * 144 + (lane >> 4) * 16);
    const uint32_t b_lane = (uint32_t)(((lane & 7) + ((lane >> 4) << 3)) * 144 + ((lane >> 3) & 1) * 16);
    const uint32_t qsH = smb + (uint32_t)(warp * 16 * 144) + a_lane;
    const uint32_t qsL = qsH + QTERM_B;

    uint32_t qhf[4][4];
    float o[8][4];
#pragma unroll
    for (int nd = 0; nd < 8; ++nd)
#pragma unroll
        for (int e = 0; e < 4; ++e) o[nd][e] = 0.f;
    float m0 = -1e30f, m1 = -1e30f, l0 = 0.f, l1 = 0.f;

    const int r_in_warp = lane >> 2;
    const int rg0 = qb * 128 + warp * 16 + r_in_warp;
    const int rg1 = rg0 + 8;
    const int colb = 2 * (lane & 3);

    for (int kt = 0; kt <= kend; ++kt) {
        CP_WAIT0();
        __syncthreads();
        // prefetch next tile immediately (stage 1-j was last read before the
        // barrier above, so overwriting it now is safe)
        if (kt + 1 <= kend) { issue_kv(kt + 1, (kt + 1) & 1); CP_COMMIT(); }

        if (kt == 0) {
#pragma unroll
            for (int ks = 0; ks < 4; ++ks)
                ldm_x4(qhf[ks], qsH + (uint32_t)(ks * 32));
        }

        const int j = kt & 1;
        const uint32_t sb = smb + 2u * QTERM_B + (uint32_t)j * STG_B;
        const float* madd = reinterpret_cast<const float*>(smc + 2 * QTERM_B + j * STG_B + 4 * KVARR_B);

        // ---- S = Q K^T (3-term) ----
        float c[8][4];
#pragma unroll
        for (int nj = 0; nj < 8; ++nj)
#pragma unroll
            for (int e = 0; e < 4; ++e) c[nj][e] = 0.f;

#pragma unroll
        for (int ks = 0; ks < 4; ++ks) {
            const uint32_t kb = (uint32_t)(ks * 32);
            uint32_t qlf[4];
            ldm_x4(qlf, qsL + kb);
#pragma unroll
            for (int nb = 0; nb < 4; ++nb) {
                uint32_t rh[4], rl[4];
                ldm_x4(rh, sb + 0 * KVARR_B + b_lane + (uint32_t)(nb * 2304) + kb);
                ldm_x4(rl, sb + 1 * KVARR_B + b_lane + (uint32_t)(nb * 2304) + kb);
                mma_bf16(c[2 * nb],     qhf[ks], rh[0], rh[1]);
                mma_bf16(c[2 * nb],     qhf[ks], rl[0], rl[1]);
                mma_bf16(c[2 * nb],     qlf,     rh[0], rh[1]);
                mma_bf16(c[2 * nb + 1], qhf[ks], rh[2], rh[3]);
                mma_bf16(c[2 * nb + 1], qhf[ks], rl[2], rl[3]);
                mma_bf16(c[2 * nb + 1], qlf,     rh[2], rh[3]);
            }
        }

        // ---- scale (log2 domain) + mask + online softmax via ex2 ----
        const bool diag = (causal != 0) && (kt >= 2 * qb);
        float mx0 = -1e30f, mx1 = -1e30f;
#pragma unroll
        for (int nj = 0; nj < 8; ++nj) {
            const int cl = nj * 8 + colb;
            const int cg = kt * 64 + cl;
            const float ma0 = madd[cl], ma1 = madd[cl + 1];
            float s0 = fmaf(c[nj][0], SCL2E, ma0);
            float s1 = fmaf(c[nj][1], SCL2E, ma1);
            float s2 = fmaf(c[nj][2], SCL2E, ma0);
            float s3 = fmaf(c[nj][3], SCL2E, ma1);
            if (diag) {
                if (cg > rg0)     s0 = -1e30f;
                if (cg + 1 > rg0) s1 = -1e30f;
                if (cg > rg1)     s2 = -1e30f;
                if (cg + 1 > rg1) s3 = -1e30f;
            }
            c[nj][0] = s0; c[nj][1] = s1; c[nj][2] = s2; c[nj][3] = s3;
            mx0 = fmaxf(mx0, fmaxf(s0, s1));
            mx1 = fmaxf(mx1, fmaxf(s2, s3));
        }
        mx0 = fmaxf(mx0, __shfl_xor_sync(0xffffffffu, mx0, 1));
        mx0 = fmaxf(mx0, __shfl_xor_sync(0xffffffffu, mx0, 2));
        mx1 = fmaxf(mx1, __shfl_xor_sync(0xffffffffu, mx1, 1));
        mx1 = fmaxf(mx1, __shfl_xor_sync(0xffffffffu, mx1, 2));

        const float mn0 = fmaxf(m0, mx0), mn1 = fmaxf(m1, mx1);
        const float al0 = ex2f(m0 - mn0), al1 = ex2f(m1 - mn1);
        float rs0 = 0.f, rs1 = 0.f;
#pragma unroll
        for (int nj = 0; nj < 8; ++nj) {
            float p0 = ex2f(c[nj][0] - mn0);
            float p1 = ex2f(c[nj][1] - mn0);
            float p2 = ex2f(c[nj][2] - mn1);
            float p3 = ex2f(c[nj][3] - mn1);
            c[nj][0] = p0; c[nj][1] = p1; c[nj][2] = p2; c[nj][3] = p3;
            rs0 += p0 + p1; rs1 += p2 + p3;
        }
        rs0 += __shfl_xor_sync(0xffffffffu, rs0, 1);
        rs0 += __shfl_xor_sync(0xffffffffu, rs0, 2);
        rs1 += __shfl_xor_sync(0xffffffffu, rs1, 1);
        rs1 += __shfl_xor_sync(0xffffffffu, rs1, 2);
        l0 = l0 * al0 + rs0; m0 = mn0;
        l1 = l1 * al1 + rs1; m1 = mn1;
#pragma unroll
        for (int nd = 0; nd < 8; ++nd) {
            o[nd][0] *= al0; o[nd][1] *= al0;
            o[nd][2] *= al1; o[nd][3] *= al1;
        }

        // ---- O += P V (3-term), P split fused per-ks ----
#pragma unroll
        for (int ks = 0; ks < 4; ++ks) {
            uint32_t pfh[4], pfl[4];
#pragma unroll
            for (int half = 0; half < 2; ++half) {
                const int nj = 2 * ks + half;
                uint32_t hpA = cvt2bf(c[nj][1], c[nj][0]);
                uint32_t hpB = cvt2bf(c[nj][3], c[nj][2]);
                float hA0 = __uint_as_float(hpA << 16), hA1 = __uint_as_float(hpA & 0xFFFF0000u);
                float hB0 = __uint_as_float(hpB << 16), hB1 = __uint_as_float(hpB & 0xFFFF0000u);
                pfh[2 * half + 0] = hpA; pfh[2 * half + 1] = hpB;
                pfl[2 * half + 0] = cvt2bf(c[nj][1] - hA1, c[nj][0] - hA0);
                pfl[2 * half + 1] = cvt2bf(c[nj][3] - hB1, c[nj][2] - hB0);
            }
#pragma unroll
            for (int nb = 0; nb < 4; ++nb) {
                uint32_t vh[4], vl[4];
                const uint32_t va = sb + 2u * KVARR_B + a_lane
                                  + (uint32_t)(ks * 16 * 144) + (uint32_t)(nb * 32);
                ldm_x4_t(vh, va);
                ldm_x4_t(vl, va + KVARR_B);
                mma_bf16(o[2 * nb],     pfh, vh[0], vh[1]);
                mma_bf16(o[2 * nb],     pfh, vl[0], vl[1]);
                mma_bf16(o[2 * nb],     pfl, vh[0], vh[1]);
                mma_bf16(o[2 * nb + 1], pfh, vh[2], vh[3]);
                mma_bf16(o[2 * nb + 1], pfh, vl[2], vl[3]);
                mma_bf16(o[2 * nb + 1], pfl, vh[2], vh[3]);
            }
        }
    }

    const float inv0 = __fdividef(1.f, l0);
    const float inv1 = __fdividef(1.f, l1);
    const size_t gr0 = (size_t)(rowg0 + warp * 16 + r_in_warp) * D_MODEL + h * 64;
    const size_t gr1 = gr0 + 8 * D_MODEL;
#pragma unroll
    for (int nd = 0; nd < 8; ++nd) {
        const int cc = nd * 8 + colb;
        float v0 = o[nd][0] * inv0, v1 = o[nd][1] * inv0;
        float v2 = o[nd][2] * inv1, v3 = o[nd][3] * inv1;
        uint32_t hp0 = cvt2bf(v1, v0);
        uint32_t hp1 = cvt2bf(v3, v2);
        float h0 = __uint_as_float(hp0 << 16), h1 = __uint_as_float(hp0 & 0xFFFF0000u);
        float h2 = __uint_as_float(hp1 << 16), h3 = __uint_as_float(hp1 & 0xFFFF0000u);
        uint32_t lp0 = cvt2bf(v1 - h1, v0 - h0);
        uint32_t lp1 = cvt2bf(v3 - h3, v2 - h2);
        *reinterpret_cast<uint32_t*>(Oh_g + gr0 + cc) = hp0;
        *reinterpret_cast<uint32_t*>(Oh_g + gr1 + cc) = hp1;
        *reinterpret_cast<uint32_t*>(Ol_g + gr0 + cc) = lp0;
        *reinterpret_cast<uint32_t*>(Ol_g + gr1 + cc) = lp1;
    }
}

// =====================================================================
// launch
// =====================================================================
extern "C" void kernel_launch(void* const* d_in, const int* in_sizes, int n_in,
                              void* d_out, int out_size)
{
    const float* q    = (const float*)d_in[0];
    const float* k    = (const float*)d_in[1];
    const float* v    = (const float*)d_in[2];
    const float* Wq   = (const float*)d_in[3];
    const float* bq   = (const float*)d_in[4];
    const float* Wk   = (const float*)d_in[5];
    const float* bk   = (const float*)d_in[6];
    const float* Wv   = (const float*)d_in[7];
    const float* bv   = (const float*)d_in[8];
    const float* Wo   = (const float*)d_in[9];
    const float* bo   = (const float*)d_in[10];
    const int*   mask = (const int*)d_in[11];
    const int*   causal = (const int*)d_in[12];
    float* out = (float*)d_out;

    __nv_bfloat16 *Ah, *Al, *Wh, *Wl, *Qh, *Ql, *Kh, *Kl, *Vh, *Vl, *Anh, *Anl;
    cudaGetSymbolAddress((void**)&Ah, g_Ah);
    cudaGetSymbolAddress((void**)&Al, g_Al);
    cudaGetSymbolAddress((void**)&Wh, g_Wh);
    cudaGetSymbolAddress((void**)&Wl, g_Wl);
    cudaGetSymbolAddress((void**)&Qh, g_Qh);
    cudaGetSymbolAddress((void**)&Ql, g_Ql);
    cudaGetSymbolAddress((void**)&Kh, g_Kh);
    cudaGetSymbolAddress((void**)&Kl, g_Kl);
    cudaGetSymbolAddress((void**)&Vh, g_Vh);
    cudaGetSymbolAddress((void**)&Vl, g_Vl);
    cudaGetSymbolAddress((void**)&Anh, g_Anh);
    cudaGetSymbolAddress((void**)&Anl, g_Anl);

    cudaFuncSetAttribute(gemm_qkv_kernel,
                         cudaFuncAttributeMaxDynamicSharedMemorySize, GEMM_SMEM);
    cudaFuncSetAttribute(gemm_out_kernel,
                         cudaFuncAttributeMaxDynamicSharedMemorySize, GEMM_SMEM);
    cudaFuncSetAttribute(flash_tc_kernel,
                         cudaFuncAttributeMaxDynamicSharedMemorySize, FL_SMEM);

    const int nA4 = ASZ / 4;
    const int nW4 = WSZ / 4;

    split3_kernel<<<dim3(nA4 / 256, 1, 3), 256>>>(q, k, v, Ah, Al);
    split4_kernel<<<dim3(nW4 / 256, 1, 4), 256>>>(Wq, Wk, Wv, Wo, Wh, Wl);

    gemm_qkv_kernel<<<dim3(D_MODEL / 128, M_ROWS / 128, 3), 256, GEMM_SMEM>>>(
        Ah, Al, Wh, Wl, bq, bk, bv, Qh, Ql, Kh, Kl, Vh, Vl);

    dim3 fgrid(T_ / 128, B_ * N_HEADS);
    flash_tc_kernel<<<fgrid, 256, FL_SMEM>>>(Qh, Ql, Kh, Kl, Vh, Vl, mask, causal, Anh, Anl);

    gemm_out_kernel<<<dim3(D_MODEL / 128, M_ROWS / 128), 256, GEMM_SMEM>>>(
        Anh, Anl, Wh + (size_t)3 * WSZ, Wl + (size_t)3 * WSZ, bo, out);
}

// round 8
// speedup vs baseline: 3.1649x; 1.0863x over previous
#include <cuda_runtime.h>
#include <cuda_bf16.h>
#include <cstdint>

#define D_MODEL 1024
#define N_HEADS 16
#define D_K     64
#define B_      2
#define T_      2048
#define M_ROWS  (B_ * T_)      // 4096
#define ASZ     (M_ROWS * D_MODEL)
#define WSZ     (D_MODEL * D_MODEL)

// ---------------- scratch (static device globals: allowed) ----------------
__device__ __nv_bfloat16 g_Ah[3 * ASZ];
__device__ __nv_bfloat16 g_Al[3 * ASZ];
__device__ __nv_bfloat16 g_Wh[4 * WSZ];
__device__ __nv_bfloat16 g_Wl[4 * WSZ];
__device__ __nv_bfloat16 g_Qh[ASZ];
__device__ __nv_bfloat16 g_Ql[ASZ];
__device__ __nv_bfloat16 g_Kh[ASZ];
__device__ __nv_bfloat16 g_Kl[ASZ];
__device__ __nv_bfloat16 g_Vh[ASZ];
__device__ __nv_bfloat16 g_Vl[ASZ];
__device__ __nv_bfloat16 g_Anh[ASZ];
__device__ __nv_bfloat16 g_Anl[ASZ];

// =====================================================================
// portable tensor-core helpers (valid on plain sm_103 target)
// =====================================================================
__device__ __forceinline__ uint32_t smem_to_u32(const void* p) {
    uint32_t a;
    asm("{ .reg .u64 t; cvta.to.shared.u64 t, %1; cvt.u32.u64 %0, t; }" : "=r"(a) : "l"(p));
    return a;
}

__device__ __forceinline__ void ldm_x4(uint32_t* r, uint32_t addr) {
    asm volatile("ldmatrix.sync.aligned.m8n8.x4.shared.b16 {%0,%1,%2,%3}, [%4];"
                 : "=r"(r[0]), "=r"(r[1]), "=r"(r[2]), "=r"(r[3]) : "r"(addr));
}
__device__ __forceinline__ void ldm_x4_t(uint32_t* r, uint32_t addr) {
    asm volatile("ldmatrix.sync.aligned.m8n8.x4.trans.shared.b16 {%0,%1,%2,%3}, [%4];"
                 : "=r"(r[0]), "=r"(r[1]), "=r"(r[2]), "=r"(r[3]) : "r"(addr));
}

__device__ __forceinline__ void mma_bf16(float* c, const uint32_t* a, uint32_t b0, uint32_t b1) {
    asm volatile("mma.sync.aligned.m16n8k16.row.col.f32.bf16.bf16.f32 "
                 "{%0,%1,%2,%3}, {%4,%5,%6,%7}, {%8,%9}, {%0,%1,%2,%3};"
                 : "+f"(c[0]), "+f"(c[1]), "+f"(c[2]), "+f"(c[3])
                 : "r"(a[0]), "r"(a[1]), "r"(a[2]), "r"(a[3]), "r"(b0), "r"(b1));
}

#define CP_ASYNC16(saddr, gptr) \
    asm volatile("cp.async.cg.shared.global [%0], [%1], 16;" :: "r"(saddr), "l"(gptr))
#define CP_COMMIT() asm volatile("cp.async.commit_group;" ::: "memory")
#define CP_WAIT1()  asm volatile("cp.async.wait_group 1;" ::: "memory")
#define CP_WAIT0()  asm volatile("cp.async.wait_group 0;" ::: "memory")

__device__ __forceinline__ uint32_t cvt2bf(float hi, float lo) {
    uint32_t r;
    asm("cvt.rn.bf16x2.f32 %0, %1, %2;" : "=r"(r) : "f"(hi), "f"(lo));
    return r;
}

// MUFU exp2 (runs on MUFU pipe, overlaps tensor/fma)
__device__ __forceinline__ float ex2f(float x) {
    float y;
    asm("ex2.approx.f32 %0, %1;" : "=f"(y) : "f"(x));
    return y;
}

// =====================================================================
// fused fp32 -> bf16 (hi, lo) splits, z-indexed over inputs
// =====================================================================
__device__ __forceinline__ void split_one(const float* __restrict__ x,
                                          __nv_bfloat16* __restrict__ hi,
                                          __nv_bfloat16* __restrict__ lo, int i)
{
    float4 v = reinterpret_cast<const float4*>(x)[i];
    __nv_bfloat16 h0 = __float2bfloat16(v.x);
    __nv_bfloat16 h1 = __float2bfloat16(v.y);
    __nv_bfloat16 h2 = __float2bfloat16(v.z);
    __nv_bfloat16 h3 = __float2bfloat16(v.w);
    __nv_bfloat16 l0 = __float2bfloat16(v.x - __bfloat162float(h0));
    __nv_bfloat16 l1 = __float2bfloat16(v.y - __bfloat162float(h1));
    __nv_bfloat16 l2 = __float2bfloat16(v.z - __bfloat162float(h2));
    __nv_bfloat16 l3 = __float2bfloat16(v.w - __bfloat162float(h3));
    __nv_bfloat162* hp = reinterpret_cast<__nv_bfloat162*>(hi) + i * 2;
    __nv_bfloat162* lp = reinterpret_cast<__nv_bfloat162*>(lo) + i * 2;
    hp[0] = __nv_bfloat162(h0, h1);
    hp[1] = __nv_bfloat162(h2, h3);
    lp[0] = __nv_bfloat162(l0, l1);
    lp[1] = __nv_bfloat162(l2, l3);
}

__global__ __launch_bounds__(256)
void split3_kernel(const float* __restrict__ q, const float* __restrict__ k,
                   const float* __restrict__ v,
                   __nv_bfloat16* __restrict__ hi, __nv_bfloat16* __restrict__ lo)
{
    const int z = blockIdx.z;
    const float* x = (z == 0) ? q : (z == 1) ? k : v;
    int i = blockIdx.x * blockDim.x + threadIdx.x;
    split_one(x, hi + (size_t)z * ASZ, lo + (size_t)z * ASZ, i);
}

__global__ __launch_bounds__(256)
void split4_kernel(const float* __restrict__ w0, const float* __restrict__ w1,
                   const float* __restrict__ w2, const float* __restrict__ w3,
                   __nv_bfloat16* __restrict__ hi, __nv_bfloat16* __restrict__ lo)
{
    const int z = blockIdx.z;
    const float* x = (z == 0) ? w0 : (z == 1) ? w1 : (z == 2) ? w2 : w3;
    int i = blockIdx.x * blockDim.x + threadIdx.x;
    split_one(x, hi + (size_t)z * WSZ, lo + (size_t)z * WSZ, i);
}

// =====================================================================
// mma.sync GEMM core: CTA tile 128x128, BK=32, 8 warps (2m x 4n), warp 64x32
// XOR-swizzled smem (64B rows, no pad), 3-stage cp.async, 1 sync/chunk,
// 2 CTAs/SM.
// =====================================================================
#define TERM_B    8192                 // 128 rows * 64 B
#define OFF_AH    0
#define OFF_AL    TERM_B
#define OFF_BH    (2 * TERM_B)
#define OFF_BL    (3 * TERM_B)
#define STAGE_B   (4 * TERM_B)         // 32768
#define NSTAGE    3
#define GEMM_SMEM (NSTAGE * STAGE_B + 128)   // 98432

// swizzled byte offset of 16B chunk (row, c) within a 128x64B array
__device__ __forceinline__ uint32_t swz(int row, int c) {
    return (uint32_t)(row * 64 + ((c ^ ((row >> 1) & 3)) << 4));
}

__device__ __forceinline__ void gemm_core(const __nv_bfloat16* __restrict__ Ah,
                                          const __nv_bfloat16* __restrict__ Al,
                                          const __nv_bfloat16* __restrict__ Bh,
                                          const __nv_bfloat16* __restrict__ Bl,
                                          const float* __restrict__ bias,
                                          __nv_bfloat16* __restrict__ Chi,
                                          __nv_bfloat16* __restrict__ Clo,
                                          float* __restrict__ Cf,
                                          char* sm, int bm, int bn)
{
    const uint32_t smb = (smem_to_u32(sm) + 127u) & ~127u;
    const int tid  = threadIdx.x;
    const int lane = tid & 31;
    const int wid  = tid >> 5;
    const int warp_m = wid >> 2;   // 0..1
    const int warp_n = wid & 3;    // 0..3

    float acc[4][4][4];
#pragma unroll
    for (int mi = 0; mi < 4; ++mi)
#pragma unroll
        for (int nj = 0; nj < 4; ++nj)
#pragma unroll
            for (int e = 0; e < 4; ++e) acc[mi][nj][e] = 0.f;

    auto issue = [&](int c, int j) {
        const int koff = c * 32;
        const uint32_t sb = smb + (uint32_t)j * STAGE_B;
#pragma unroll
        for (int u = tid; u < 512; u += 256) {
            const int row = u >> 2, cc = u & 3;
            const uint32_t so = swz(row, cc);
            const size_t gA = (size_t)(bm + row) * D_MODEL + koff + cc * 8;
            const size_t gB = (size_t)(bn + row) * D_MODEL + koff + cc * 8;
            CP_ASYNC16(sb + OFF_AH + so, Ah + gA);
            CP_ASYNC16(sb + OFF_AL + so, Al + gA);
            CP_ASYNC16(sb + OFF_BH + so, Bh + gB);
            CP_ASYNC16(sb + OFF_BL + so, Bl + gB);
        }
        CP_COMMIT();
    };

    // lane-static swizzled offsets
    const int rA = lane & 15, cA = lane >> 4;
    const uint32_t aoff = swz(rA, cA);
    const int rB = (lane & 7) | ((lane >> 4) << 3), cB = (lane >> 3) & 1;
    const uint32_t boff = swz(rB, cB);

    const uint32_t aH_base = smb + OFF_AH + (uint32_t)(warp_m * 4096) + aoff;
    const uint32_t aL_base = smb + OFF_AL + (uint32_t)(warp_m * 4096) + aoff;
    const uint32_t bH_base = smb + OFF_BH + (uint32_t)(warp_n * 2048) + boff;
    const uint32_t bL_base = smb + OFF_BL + (uint32_t)(warp_n * 2048) + boff;

    const int NCHUNK = D_MODEL / 32;   // 32
    issue(0, 0);
    issue(1, 1);

    for (int c = 0; c < NCHUNK; ++c) {
        const int j = c % NSTAGE;
        if (c + 1 < NCHUNK) { CP_WAIT1(); } else { CP_WAIT0(); }
        __syncthreads();
        if (c + 2 < NCHUNK) issue(c + 2, (c + 2) % NSTAGE);

        const uint32_t stg = (uint32_t)j * STAGE_B;
#pragma unroll
        for (int ks = 0; ks < 2; ++ks) {
            const uint32_t kx = (uint32_t)(ks << 5);   // XOR chunk-select
            uint32_t ah[4][4], al[4][4], bhv[4][2], blv[4][2];
#pragma unroll
            for (int mi = 0; mi < 4; ++mi) {
                ldm_x4(ah[mi], (aH_base + stg + (uint32_t)(mi * 1024)) ^ kx);
                ldm_x4(al[mi], (aL_base + stg + (uint32_t)(mi * 1024)) ^ kx);
            }
#pragma unroll
            for (int p = 0; p < 2; ++p) {
                uint32_t r[4];
                ldm_x4(r, (bH_base + stg + (uint32_t)(p * 1024)) ^ kx);
                bhv[p * 2 + 0][0] = r[0]; bhv[p * 2 + 0][1] = r[1];
                bhv[p * 2 + 1][0] = r[2]; bhv[p * 2 + 1][1] = r[3];
                ldm_x4(r, (bL_base + stg + (uint32_t)(p * 1024)) ^ kx);
                blv[p * 2 + 0][0] = r[0]; blv[p * 2 + 0][1] = r[1];
                blv[p * 2 + 1][0] = r[2]; blv[p * 2 + 1][1] = r[3];
            }
#pragma unroll
            for (int mi = 0; mi < 4; ++mi)
#pragma unroll
                for (int nj = 0; nj < 4; ++nj)
                    mma_bf16(acc[mi][nj], ah[mi], bhv[nj][0], bhv[nj][1]);
#pragma unroll
            for (int mi = 0; mi < 4; ++mi)
#pragma unroll
                for (int nj = 0; nj < 4; ++nj)
                    mma_bf16(acc[mi][nj], ah[mi], blv[nj][0], blv[nj][1]);
#pragma unroll
            for (int mi = 0; mi < 4; ++mi)
#pragma unroll
                for (int nj = 0; nj < 4; ++nj)
                    mma_bf16(acc[mi][nj], al[mi], bhv[nj][0], bhv[nj][1]);
        }
    }

    const int rbase = bm + warp_m * 64;
    const int cbase = bn + warp_n * 32;
#pragma unroll
    for (int mi = 0; mi < 4; ++mi) {
#pragma unroll
        for (int nj = 0; nj < 4; ++nj) {
            const int r0 = rbase + mi * 16 + (lane >> 2);
            const int cc = cbase + nj * 8 + 2 * (lane & 3);
            const float b0 = bias[cc], b1 = bias[cc + 1];
            const float v0 = acc[mi][nj][0] + b0, v1 = acc[mi][nj][1] + b1;
            const float v2 = acc[mi][nj][2] + b0, v3 = acc[mi][nj][3] + b1;
            if (Cf) {
                float2 w0, w1;
                w0.x = v0; w0.y = v1; w1.x = v2; w1.y = v3;
                *reinterpret_cast<float2*>(Cf + (size_t)r0 * D_MODEL + cc) = w0;
                *reinterpret_cast<float2*>(Cf + (size_t)(r0 + 8) * D_MODEL + cc) = w1;
            } else {
                uint32_t hp0 = cvt2bf(v1, v0);
                uint32_t hp1 = cvt2bf(v3, v2);
                float h0 = __uint_as_float(hp0 << 16), h1 = __uint_as_float(hp0 & 0xFFFF0000u);
                float h2 = __uint_as_float(hp1 << 16), h3 = __uint_as_float(hp1 & 0xFFFF0000u);
                uint32_t lp0 = cvt2bf(v1 - h1, v0 - h0);
                uint32_t lp1 = cvt2bf(v3 - h3, v2 - h2);
                *reinterpret_cast<uint32_t*>(Chi + (size_t)r0 * D_MODEL + cc) = hp0;
                *reinterpret_cast<uint32_t*>(Chi + (size_t)(r0 + 8) * D_MODEL + cc) = hp1;
                *reinterpret_cast<uint32_t*>(Clo + (size_t)r0 * D_MODEL + cc) = lp0;
                *reinterpret_cast<uint32_t*>(Clo + (size_t)(r0 + 8) * D_MODEL + cc) = lp1;
            }
        }
    }
}

__global__ __launch_bounds__(256, 2)
void gemm_qkv_kernel(const __nv_bfloat16* __restrict__ Ah3, const __nv_bfloat16* __restrict__ Al3,
                     const __nv_bfloat16* __restrict__ Wh4, const __nv_bfloat16* __restrict__ Wl4,
                     const float* __restrict__ bq, const float* __restrict__ bk,
                     const float* __restrict__ bv,
                     __nv_bfloat16* __restrict__ Qh, __nv_bfloat16* __restrict__ Ql,
                     __nv_bfloat16* __restrict__ Kh, __nv_bfloat16* __restrict__ Kl,
                     __nv_bfloat16* __restrict__ Vh, __nv_bfloat16* __restrict__ Vl)
{
    extern __shared__ char sm[];
    const int z = blockIdx.z;
    const float* bias = (z == 0) ? bq : (z == 1) ? bk : bv;
    __nv_bfloat16* Chi = (z == 0) ? Qh : (z == 1) ? Kh : Vh;
    __nv_bfloat16* Clo = (z == 0) ? Ql : (z == 1) ? Kl : Vl;
    gemm_core(Ah3 + (size_t)z * ASZ, Al3 + (size_t)z * ASZ,
              Wh4 + (size_t)z * WSZ, Wl4 + (size_t)z * WSZ,
              bias, Chi, Clo, nullptr, sm, blockIdx.y * 128, blockIdx.x * 128);
}

__global__ __launch_bounds__(256, 2)
void gemm_out_kernel(const __nv_bfloat16* __restrict__ Ah, const __nv_bfloat16* __restrict__ Al,
                     const __nv_bfloat16* __restrict__ Bh, const __nv_bfloat16* __restrict__ Bl,
                     const float* __restrict__ bias, float* __restrict__ Cf)
{
    extern __shared__ char sm[];
    gemm_core(Ah, Al, Bh, Bl, bias, nullptr, nullptr, Cf,
              sm, blockIdx.y * 128, blockIdx.x * 128);
}

// =====================================================================
// mma.sync flash attention — 2 CTAs/SM, ex2 softmax, single sync/tile
// =====================================================================
#define QTERM_B  18432               // 128*72*2
#define KVARR_B  9216                // 64*72*2
#define STG_B    (4 * KVARR_B + 256)
#define FL_SMEM  (2 * QTERM_B + 2 * STG_B)   // 111104
#define SCL2E    0.180336879f        // 0.125 * log2(e)

__global__ __launch_bounds__(256, 2)
void flash_tc_kernel(const __nv_bfloat16* __restrict__ Qh_g, const __nv_bfloat16* __restrict__ Ql_g,
                     const __nv_bfloat16* __restrict__ Kh_g, const __nv_bfloat16* __restrict__ Kl_g,
                     const __nv_bfloat16* __restrict__ Vh_g, const __nv_bfloat16* __restrict__ Vl_g,
                     const int* __restrict__ mask, const int* __restrict__ causal_p,
                     __nv_bfloat16* __restrict__ Oh_g, __nv_bfloat16* __restrict__ Ol_g)
{
    extern __shared__ char smc[];
    const uint32_t smb = smem_to_u32(smc);
    const int tid = threadIdx.x, lane = tid & 31, warp = tid >> 5;
    const int qb = (int)(gridDim.x - 1 - blockIdx.x);
    const int bh = blockIdx.y, b = bh >> 4, h = bh & 15;
    const int causal = *causal_p;
    const int kend = causal ? (2 * qb + 1) : (T_ / 64 - 1);
    const int rowg0 = b * T_ + qb * 128;

    auto issue_kv = [&](int kt, int s) {
        const uint32_t sb = smb + 2u * QTERM_B + (uint32_t)s * STG_B;
        const int tk0 = b * T_ + kt * 64;
#pragma unroll
        for (int u = tid; u < 2048; u += 256) {
            const int arr = u >> 9, rem = u & 511;
            const int row = rem >> 3, c = rem & 7;
            const __nv_bfloat16* base = (arr == 0) ? Kh_g : (arr == 1) ? Kl_g
                                       : (arr == 2) ? Vh_g : Vl_g;
            CP_ASYNC16(sb + (uint32_t)(arr * KVARR_B + row * 144 + c * 16),
                       base + ((size_t)(tk0 + row) * D_MODEL + h * 64 + c * 8));
        }
        if (tid < 64) {
            float mv = (mask[tk0 + tid] == 0) ? -1e30f : 0.f;
            reinterpret_cast<float*>(smc + 2 * QTERM_B + s * STG_B + 4 * KVARR_B)[tid] = mv;
        }
    };

    {
#pragma unroll
        for (int u = tid; u < 2048; u += 256) {
            const int term = u >> 10, rem = u & 1023;
            const int row = rem >> 3, c = rem & 7;
            const __nv_bfloat16* src = (term ? Ql_g : Qh_g)
                + ((size_t)(rowg0 + row) * D_MODEL + h * 64 + c * 8);
            CP_ASYNC16(smb + (uint32_t)(term * QTERM_B + row * 144 + c * 16), src);
        }
        issue_kv(0, 0);
        CP_COMMIT();
    }

    const uint32_t a_lane = (uint32_t)((lane & 15) * 144 + (lane >> 4) * 16);
    const uint32_t b_lane = (uint32_t)(((lane & 7) + ((lane >> 4) << 3)) * 144 + ((lane >> 3) & 1) * 16);
    const uint32_t qsH = smb + (uint32_t)(warp * 16 * 144) + a_lane;
    const uint32_t qsL = qsH + QTERM_B;

    uint32_t qhf[4][4];
    float o[8][4];
#pragma unroll
    for (int nd = 0; nd < 8; ++nd)
#pragma unroll
        for (int e = 0; e < 4; ++e) o[nd][e] = 0.f;
    float m0 = -1e30f, m1 = -1e30f, l0 = 0.f, l1 = 0.f;

    const int r_in_warp = lane >> 2;
    const int rg0 = qb * 128 + warp * 16 + r_in_warp;
    const int rg1 = rg0 + 8;
    const int colb = 2 * (lane & 3);

    for (int kt = 0; kt <= kend; ++kt) {
        CP_WAIT0();
        __syncthreads();
        if (kt + 1 <= kend) { issue_kv(kt + 1, (kt + 1) & 1); CP_COMMIT(); }

        if (kt == 0) {
#pragma unroll
            for (int ks = 0; ks < 4; ++ks)
                ldm_x4(qhf[ks], qsH + (uint32_t)(ks * 32));
        }

        const int j = kt & 1;
        const uint32_t sb = smb + 2u * QTERM_B + (uint32_t)j * STG_B;
        const float* madd = reinterpret_cast<const float*>(smc + 2 * QTERM_B + j * STG_B + 4 * KVARR_B);

        // ---- S = Q K^T (3-term) ----
        float c[8][4];
#pragma unroll
        for (int nj = 0; nj < 8; ++nj)
#pragma unroll
            for (int e = 0; e < 4; ++e) c[nj][e] = 0.f;

#pragma unroll
        for (int ks = 0; ks < 4; ++ks) {
            const uint32_t kb = (uint32_t)(ks * 32);
            uint32_t qlf[4];
            ldm_x4(qlf, qsL + kb);
#pragma unroll
            for (int nb = 0; nb < 4; ++nb) {
                uint32_t rh[4], rl[4];
                ldm_x4(rh, sb + 0 * KVARR_B + b_lane + (uint32_t)(nb * 2304) + kb);
                ldm_x4(rl, sb + 1 * KVARR_B + b_lane + (uint32_t)(nb * 2304) + kb);
                mma_bf16(c[2 * nb],     qhf[ks], rh[0], rh[1]);
                mma_bf16(c[2 * nb],     qhf[ks], rl[0], rl[1]);
                mma_bf16(c[2 * nb],     qlf,     rh[0], rh[1]);
                mma_bf16(c[2 * nb + 1], qhf[ks], rh[2], rh[3]);
                mma_bf16(c[2 * nb + 1], qhf[ks], rl[2], rl[3]);
                mma_bf16(c[2 * nb + 1], qlf,     rh[2], rh[3]);
            }
        }

        // ---- scale (log2 domain) + mask + online softmax via ex2 ----
        const bool diag = (causal != 0) && (kt >= 2 * qb);
        float mx0 = -1e30f, mx1 = -1e30f;
#pragma unroll
        for (int nj = 0; nj < 8; ++nj) {
            const int cl = nj * 8 + colb;
            const int cg = kt * 64 + cl;
            const float ma0 = madd[cl], ma1 = madd[cl + 1];
            float s0 = fmaf(c[nj][0], SCL2E, ma0);
            float s1 = fmaf(c[nj][1], SCL2E, ma1);
            float s2 = fmaf(c[nj][2], SCL2E, ma0);
            float s3 = fmaf(c[nj][3], SCL2E, ma1);
            if (diag) {
                if (cg > rg0)     s0 = -1e30f;
                if (cg + 1 > rg0) s1 = -1e30f;
                if (cg > rg1)     s2 = -1e30f;
                if (cg + 1 > rg1) s3 = -1e30f;
            }
            c[nj][0] = s0; c[nj][1] = s1; c[nj][2] = s2; c[nj][3] = s3;
            mx0 = fmaxf(mx0, fmaxf(s0, s1));
            mx1 = fmaxf(mx1, fmaxf(s2, s3));
        }
        mx0 = fmaxf(mx0, __shfl_xor_sync(0xffffffffu, mx0, 1));
        mx0 = fmaxf(mx0, __shfl_xor_sync(0xffffffffu, mx0, 2));
        mx1 = fmaxf(mx1, __shfl_xor_sync(0xffffffffu, mx1, 1));
        mx1 = fmaxf(mx1, __shfl_xor_sync(0xffffffffu, mx1, 2));

        const float mn0 = fmaxf(m0, mx0), mn1 = fmaxf(m1, mx1);
        const float al0 = ex2f(m0 - mn0), al1 = ex2f(m1 - mn1);
        float rs0 = 0.f, rs1 = 0.f;
#pragma unroll
        for (int nj = 0; nj < 8; ++nj) {
            float p0 = ex2f(c[nj][0] - mn0);
            float p1 = ex2f(c[nj][1] - mn0);
            float p2 = ex2f(c[nj][2] - mn1);
            float p3 = ex2f(c[nj][3] - mn1);
            c[nj][0] = p0; c[nj][1] = p1; c[nj][2] = p2; c[nj][3] = p3;
            rs0 += p0 + p1; rs1 += p2 + p3;
        }
        rs0 += __shfl_xor_sync(0xffffffffu, rs0, 1);
        rs0 += __shfl_xor_sync(0xffffffffu, rs0, 2);
        rs1 += __shfl_xor_sync(0xffffffffu, rs1, 1);
        rs1 += __shfl_xor_sync(0xffffffffu, rs1, 2);
        l0 = l0 * al0 + rs0; m0 = mn0;
        l1 = l1 * al1 + rs1; m1 = mn1;
#pragma unroll
        for (int nd = 0; nd < 8; ++nd) {
            o[nd][0] *= al0; o[nd][1] *= al0;
            o[nd][2] *= al1; o[nd][3] *= al1;
        }

        // ---- O += P V (3-term), P split fused per-ks ----
#pragma unroll
        for (int ks = 0; ks < 4; ++ks) {
            uint32_t pfh[4], pfl[4];
#pragma unroll
            for (int half = 0; half < 2; ++half) {
                const int nj = 2 * ks + half;
                uint32_t hpA = cvt2bf(c[nj][1], c[nj][0]);
                uint32_t hpB = cvt2bf(c[nj][3], c[nj][2]);
                float hA0 = __uint_as_float(hpA << 16), hA1 = __uint_as_float(hpA & 0xFFFF0000u);
                float hB0 = __uint_as_float(hpB << 16), hB1 = __uint_as_float(hpB & 0xFFFF0000u);
                pfh[2 * half + 0] = hpA; pfh[2 * half + 1] = hpB;
                pfl[2 * half + 0] = cvt2bf(c[nj][1] - hA1, c[nj][0] - hA0);
                pfl[2 * half + 1] = cvt2bf(c[nj][3] - hB1, c[nj][2] - hB0);
            }
#pragma unroll
            for (int nb = 0; nb < 4; ++nb) {
                uint32_t vh[4], vl[4];
                const uint32_t va = sb + 2u * KVARR_B + a_lane
                                  + (uint32_t)(ks * 16 * 144) + (uint32_t)(nb * 32);
                ldm_x4_t(vh, va);
                ldm_x4_t(vl, va + KVARR_B);
                mma_bf16(o[2 * nb],     pfh, vh[0], vh[1]);
                mma_bf16(o[2 * nb],     pfh, vl[0], vl[1]);
                mma_bf16(o[2 * nb],     pfl, vh[0], vh[1]);
                mma_bf16(o[2 * nb + 1], pfh, vh[2], vh[3]);
                mma_bf16(o[2 * nb + 1], pfh, vl[2], vl[3]);
                mma_bf16(o[2 * nb + 1], pfl, vh[2], vh[3]);
            }
        }
    }

    const float inv0 = __fdividef(1.f, l0);
    const float inv1 = __fdividef(1.f, l1);
    const size_t gr0 = (size_t)(rowg0 + warp * 16 + r_in_warp) * D_MODEL + h * 64;
    const size_t gr1 = gr0 + 8 * D_MODEL;
#pragma unroll
    for (int nd = 0; nd < 8; ++nd) {
        const int cc = nd * 8 + colb;
        float v0 = o[nd][0] * inv0, v1 = o[nd][1] * inv0;
        float v2 = o[nd][2] * inv1, v3 = o[nd][3] * inv1;
        uint32_t hp0 = cvt2bf(v1, v0);
        uint32_t hp1 = cvt2bf(v3, v2);
        float h0 = __uint_as_float(hp0 << 16), h1 = __uint_as_float(hp0 & 0xFFFF0000u);
        float h2 = __uint_as_float(hp1 << 16), h3 = __uint_as_float(hp1 & 0xFFFF0000u);
        uint32_t lp0 = cvt2bf(v1 - h1, v0 - h0);
        uint32_t lp1 = cvt2bf(v3 - h3, v2 - h2);
        *reinterpret_cast<uint32_t*>(Oh_g + gr0 + cc) = hp0;
        *reinterpret_cast<uint32_t*>(Oh_g + gr1 + cc) = hp1;
        *reinterpret_cast<uint32_t*>(Ol_g + gr0 + cc) = lp0;
        *reinterpret_cast<uint32_t*>(Ol_g + gr1 + cc) = lp1;
    }
}

// =====================================================================
// launch
// =====================================================================
extern "C" void kernel_launch(void* const* d_in, const int* in_sizes, int n_in,
                              void* d_out, int out_size)
{
    const float* q    = (const float*)d_in[0];
    const float* k    = (const float*)d_in[1];
    const float* v    = (const float*)d_in[2];
    const float* Wq   = (const float*)d_in[3];
    const float* bq   = (const float*)d_in[4];
    const float* Wk   = (const float*)d_in[5];
    const float* bk   = (const float*)d_in[6];
    const float* Wv   = (const float*)d_in[7];
    const float* bv   = (const float*)d_in[8];
    const float* Wo   = (const float*)d_in[9];
    const float* bo   = (const float*)d_in[10];
    const int*   mask = (const int*)d_in[11];
    const int*   causal = (const int*)d_in[12];
    float* out = (float*)d_out;

    __nv_bfloat16 *Ah, *Al, *Wh, *Wl, *Qh, *Ql, *Kh, *Kl, *Vh, *Vl, *Anh, *Anl;
    cudaGetSymbolAddress((void**)&Ah, g_Ah);
    cudaGetSymbolAddress((void**)&Al, g_Al);
    cudaGetSymbolAddress((void**)&Wh, g_Wh);
    cudaGetSymbolAddress((void**)&Wl, g_Wl);
    cudaGetSymbolAddress((void**)&Qh, g_Qh);
    cudaGetSymbolAddress((void**)&Ql, g_Ql);
    cudaGetSymbolAddress((void**)&Kh, g_Kh);
    cudaGetSymbolAddress((void**)&Kl, g_Kl);
    cudaGetSymbolAddress((void**)&Vh, g_Vh);
    cudaGetSymbolAddress((void**)&Vl, g_Vl);
    cudaGetSymbolAddress((void**)&Anh, g_Anh);
    cudaGetSymbolAddress((void**)&Anl, g_Anl);

    cudaFuncSetAttribute(gemm_qkv_kernel,
                         cudaFuncAttributeMaxDynamicSharedMemorySize, GEMM_SMEM);
    cudaFuncSetAttribute(gemm_out_kernel,
                         cudaFuncAttributeMaxDynamicSharedMemorySize, GEMM_SMEM);
    cudaFuncSetAttribute(flash_tc_kernel,
                         cudaFuncAttributeMaxDynamicSharedMemorySize, FL_SMEM);

    const int nA4 = ASZ / 4;
    const int nW4 = WSZ / 4;

    split3_kernel<<<dim3(nA4 / 256, 1, 3), 256>>>(q, k, v, Ah, Al);
    split4_kernel<<<dim3(nW4 / 256, 1, 4), 256>>>(Wq, Wk, Wv, Wo, Wh, Wl);

    gemm_qkv_kernel<<<dim3(D_MODEL / 128, M_ROWS / 128, 3), 256, GEMM_SMEM>>>(
        Ah, Al, Wh, Wl, bq, bk, bv, Qh, Ql, Kh, Kl, Vh, Vl);

    dim3 fgrid(T_ / 128, B_ * N_HEADS);
    flash_tc_kernel<<<fgrid, 256, FL_SMEM>>>(Qh, Ql, Kh, Kl, Vh, Vl, mask, causal, Anh, Anl);

    gemm_out_kernel<<<dim3(D_MODEL / 128, M_ROWS / 128), 256, GEMM_SMEM>>>(
        Anh, Anl, Wh + (size_t)3 * WSZ, Wl + (size_t)3 * WSZ, bo, out);
}

// round 9
// speedup vs baseline: 3.4920x; 1.1033x over previous
#include <cuda_runtime.h>
#include <cuda_bf16.h>
#include <cstdint>

#define D_MODEL 1024
#define N_HEADS 16
#define D_K     64
#define B_      2
#define T_      2048
#define M_ROWS  (B_ * T_)      // 4096
#define ASZ     (M_ROWS * D_MODEL)
#define WSZ     (D_MODEL * D_MODEL)

// ---------------- scratch (static device globals: allowed) ----------------
__device__ __nv_bfloat16 g_Ah[3 * ASZ];
__device__ __nv_bfloat16 g_Al[3 * ASZ];
__device__ __nv_bfloat16 g_Wh[4 * WSZ];
__device__ __nv_bfloat16 g_Wl[4 * WSZ];
__device__ __nv_bfloat16 g_Qh[ASZ];
__device__ __nv_bfloat16 g_Ql[ASZ];
__device__ __nv_bfloat16 g_Kh[ASZ];
__device__ __nv_bfloat16 g_Kl[ASZ];
__device__ __nv_bfloat16 g_Vh[ASZ];
__device__ __nv_bfloat16 g_Vl[ASZ];
__device__ __nv_bfloat16 g_Anh[ASZ];
__device__ __nv_bfloat16 g_Anl[ASZ];

// =====================================================================
// portable tensor-core helpers (valid on plain sm_103 target)
// =====================================================================
__device__ __forceinline__ uint32_t smem_to_u32(const void* p) {
    uint32_t a;
    asm("{ .reg .u64 t; cvta.to.shared.u64 t, %1; cvt.u32.u64 %0, t; }" : "=r"(a) : "l"(p));
    return a;
}

__device__ __forceinline__ void ldm_x4(uint32_t* r, uint32_t addr) {
    asm volatile("ldmatrix.sync.aligned.m8n8.x4.shared.b16 {%0,%1,%2,%3}, [%4];"
                 : "=r"(r[0]), "=r"(r[1]), "=r"(r[2]), "=r"(r[3]) : "r"(addr));
}
__device__ __forceinline__ void ldm_x4_t(uint32_t* r, uint32_t addr) {
    asm volatile("ldmatrix.sync.aligned.m8n8.x4.trans.shared.b16 {%0,%1,%2,%3}, [%4];"
                 : "=r"(r[0]), "=r"(r[1]), "=r"(r[2]), "=r"(r[3]) : "r"(addr));
}

__device__ __forceinline__ void mma_bf16(float* c, const uint32_t* a, uint32_t b0, uint32_t b1) {
    asm volatile("mma.sync.aligned.m16n8k16.row.col.f32.bf16.bf16.f32 "
                 "{%0,%1,%2,%3}, {%4,%5,%6,%7}, {%8,%9}, {%0,%1,%2,%3};"
                 : "+f"(c[0]), "+f"(c[1]), "+f"(c[2]), "+f"(c[3])
                 : "r"(a[0]), "r"(a[1]), "r"(a[2]), "r"(a[3]), "r"(b0), "r"(b1));
}

#define CP_ASYNC16(saddr, gptr) \
    asm volatile("cp.async.cg.shared.global [%0], [%1], 16;" :: "r"(saddr), "l"(gptr))
#define CP_COMMIT() asm volatile("cp.async.commit_group;" ::: "memory")
#define CP_WAIT1()  asm volatile("cp.async.wait_group 1;" ::: "memory")
#define CP_WAIT0()  asm volatile("cp.async.wait_group 0;" ::: "memory")

__device__ __forceinline__ uint32_t cvt2bf(float hi, float lo) {
    uint32_t r;
    asm("cvt.rn.bf16x2.f32 %0, %1, %2;" : "=r"(r) : "f"(hi), "f"(lo));
    return r;
}

// MUFU exp2 (runs on MUFU pipe, overlaps tensor/fma)
__device__ __forceinline__ float ex2f(float x) {
    float y;
    asm("ex2.approx.f32 %0, %1;" : "=f"(y) : "f"(x));
    return y;
}

// =====================================================================
// fused fp32 -> bf16 (hi, lo) splits, z-indexed over inputs
// =====================================================================
__device__ __forceinline__ void split_one(const float* __restrict__ x,
                                          __nv_bfloat16* __restrict__ hi,
                                          __nv_bfloat16* __restrict__ lo, int i)
{
    float4 v = reinterpret_cast<const float4*>(x)[i];
    __nv_bfloat16 h0 = __float2bfloat16(v.x);
    __nv_bfloat16 h1 = __float2bfloat16(v.y);
    __nv_bfloat16 h2 = __float2bfloat16(v.z);
    __nv_bfloat16 h3 = __float2bfloat16(v.w);
    __nv_bfloat16 l0 = __float2bfloat16(v.x - __bfloat162float(h0));
    __nv_bfloat16 l1 = __float2bfloat16(v.y - __bfloat162float(h1));
    __nv_bfloat16 l2 = __float2bfloat16(v.z - __bfloat162float(h2));
    __nv_bfloat16 l3 = __float2bfloat16(v.w - __bfloat162float(h3));
    __nv_bfloat162* hp = reinterpret_cast<__nv_bfloat162*>(hi) + i * 2;
    __nv_bfloat162* lp = reinterpret_cast<__nv_bfloat162*>(lo) + i * 2;
    hp[0] = __nv_bfloat162(h0, h1);
    hp[1] = __nv_bfloat162(h2, h3);
    lp[0] = __nv_bfloat162(l0, l1);
    lp[1] = __nv_bfloat162(l2, l3);
}

__global__ __launch_bounds__(256)
void split3_kernel(const float* __restrict__ q, const float* __restrict__ k,
                   const float* __restrict__ v,
                   __nv_bfloat16* __restrict__ hi, __nv_bfloat16* __restrict__ lo)
{
    const int z = blockIdx.z;
    const float* x = (z == 0) ? q : (z == 1) ? k : v;
    int i = blockIdx.x * blockDim.x + threadIdx.x;
    split_one(x, hi + (size_t)z * ASZ, lo + (size_t)z * ASZ, i);
}

__global__ __launch_bounds__(256)
void split4_kernel(const float* __restrict__ w0, const float* __restrict__ w1,
                   const float* __restrict__ w2, const float* __restrict__ w3,
                   __nv_bfloat16* __restrict__ hi, __nv_bfloat16* __restrict__ lo)
{
    const int z = blockIdx.z;
    const float* x = (z == 0) ? w0 : (z == 1) ? w1 : (z == 2) ? w2 : w3;
    int i = blockIdx.x * blockDim.x + threadIdx.x;
    split_one(x, hi + (size_t)z * WSZ, lo + (size_t)z * WSZ, i);
}

// =====================================================================
// mma.sync GEMM core: CTA tile 128x128, BK=32, 8 warps (2m x 4n), warp 64x32
// XOR-swizzled smem (64B rows, no pad), 3-stage cp.async, 1 sync/chunk,
// 2 CTAs/SM.  (unchanged from R8)
// =====================================================================
#define TERM_B    8192                 // 128 rows * 64 B
#define OFF_AH    0
#define OFF_AL    TERM_B
#define OFF_BH    (2 * TERM_B)
#define OFF_BL    (3 * TERM_B)
#define STAGE_B   (4 * TERM_B)         // 32768
#define NSTAGE    3
#define GEMM_SMEM (NSTAGE * STAGE_B + 128)   // 98432

__device__ __forceinline__ uint32_t swz(int row, int c) {
    return (uint32_t)(row * 64 + ((c ^ ((row >> 1) & 3)) << 4));
}

__device__ __forceinline__ void gemm_core(const __nv_bfloat16* __restrict__ Ah,
                                          const __nv_bfloat16* __restrict__ Al,
                                          const __nv_bfloat16* __restrict__ Bh,
                                          const __nv_bfloat16* __restrict__ Bl,
                                          const float* __restrict__ bias,
                                          __nv_bfloat16* __restrict__ Chi,
                                          __nv_bfloat16* __restrict__ Clo,
                                          float* __restrict__ Cf,
                                          char* sm, int bm, int bn)
{
    const uint32_t smb = (smem_to_u32(sm) + 127u) & ~127u;
    const int tid  = threadIdx.x;
    const int lane = tid & 31;
    const int wid  = tid >> 5;
    const int warp_m = wid >> 2;   // 0..1
    const int warp_n = wid & 3;    // 0..3

    float acc[4][4][4];
#pragma unroll
    for (int mi = 0; mi < 4; ++mi)
#pragma unroll
        for (int nj = 0; nj < 4; ++nj)
#pragma unroll
            for (int e = 0; e < 4; ++e) acc[mi][nj][e] = 0.f;

    auto issue = [&](int c, int j) {
        const int koff = c * 32;
        const uint32_t sb = smb + (uint32_t)j * STAGE_B;
#pragma unroll
        for (int u = tid; u < 512; u += 256) {
            const int row = u >> 2, cc = u & 3;
            const uint32_t so = swz(row, cc);
            const size_t gA = (size_t)(bm + row) * D_MODEL + koff + cc * 8;
            const size_t gB = (size_t)(bn + row) * D_MODEL + koff + cc * 8;
            CP_ASYNC16(sb + OFF_AH + so, Ah + gA);
            CP_ASYNC16(sb + OFF_AL + so, Al + gA);
            CP_ASYNC16(sb + OFF_BH + so, Bh + gB);
            CP_ASYNC16(sb + OFF_BL + so, Bl + gB);
        }
        CP_COMMIT();
    };

    const int rA = lane & 15, cA = lane >> 4;
    const uint32_t aoff = swz(rA, cA);
    const int rB = (lane & 7) | ((lane >> 4) << 3), cB = (lane >> 3) & 1;
    const uint32_t boff = swz(rB, cB);

    const uint32_t aH_base = smb + OFF_AH + (uint32_t)(warp_m * 4096) + aoff;
    const uint32_t aL_base = smb + OFF_AL + (uint32_t)(warp_m * 4096) + aoff;
    const uint32_t bH_base = smb + OFF_BH + (uint32_t)(warp_n * 2048) + boff;
    const uint32_t bL_base = smb + OFF_BL + (uint32_t)(warp_n * 2048) + boff;

    const int NCHUNK = D_MODEL / 32;   // 32
    issue(0, 0);
    issue(1, 1);

    for (int c = 0; c < NCHUNK; ++c) {
        const int j = c % NSTAGE;
        if (c + 1 < NCHUNK) { CP_WAIT1(); } else { CP_WAIT0(); }
        __syncthreads();
        if (c + 2 < NCHUNK) issue(c + 2, (c + 2) % NSTAGE);

        const uint32_t stg = (uint32_t)j * STAGE_B;
#pragma unroll
        for (int ks = 0; ks < 2; ++ks) {
            const uint32_t kx = (uint32_t)(ks << 5);
            uint32_t ah[4][4], al[4][4], bhv[4][2], blv[4][2];
#pragma unroll
            for (int mi = 0; mi < 4; ++mi) {
                ldm_x4(ah[mi], (aH_base + stg + (uint32_t)(mi * 1024)) ^ kx);
                ldm_x4(al[mi], (aL_base + stg + (uint32_t)(mi * 1024)) ^ kx);
            }
#pragma unroll
            for (int p = 0; p < 2; ++p) {
                uint32_t r[4];
                ldm_x4(r, (bH_base + stg + (uint32_t)(p * 1024)) ^ kx);
                bhv[p * 2 + 0][0] = r[0]; bhv[p * 2 + 0][1] = r[1];
                bhv[p * 2 + 1][0] = r[2]; bhv[p * 2 + 1][1] = r[3];
                ldm_x4(r, (bL_base + stg + (uint32_t)(p * 1024)) ^ kx);
                blv[p * 2 + 0][0] = r[0]; blv[p * 2 + 0][1] = r[1];
                blv[p * 2 + 1][0] = r[2]; blv[p * 2 + 1][1] = r[3];
            }
#pragma unroll
            for (int mi = 0; mi < 4; ++mi)
#pragma unroll
                for (int nj = 0; nj < 4; ++nj)
                    mma_bf16(acc[mi][nj], ah[mi], bhv[nj][0], bhv[nj][1]);
#pragma unroll
            for (int mi = 0; mi < 4; ++mi)
#pragma unroll
                for (int nj = 0; nj < 4; ++nj)
                    mma_bf16(acc[mi][nj], ah[mi], blv[nj][0], blv[nj][1]);
#pragma unroll
            for (int mi = 0; mi < 4; ++mi)
#pragma unroll
                for (int nj = 0; nj < 4; ++nj)
                    mma_bf16(acc[mi][nj], al[mi], bhv[nj][0], bhv[nj][1]);
        }
    }

    const int rbase = bm + warp_m * 64;
    const int cbase = bn + warp_n * 32;
#pragma unroll
    for (int mi = 0; mi < 4; ++mi) {
#pragma unroll
        for (int nj = 0; nj < 4; ++nj) {
            const int r0 = rbase + mi * 16 + (lane >> 2);
            const int cc = cbase + nj * 8 + 2 * (lane & 3);
            const float b0 = bias[cc], b1 = bias[cc + 1];
            const float v0 = acc[mi][nj][0] + b0, v1 = acc[mi][nj][1] + b1;
            const float v2 = acc[mi][nj][2] + b0, v3 = acc[mi][nj][3] + b1;
            if (Cf) {
                float2 w0, w1;
                w0.x = v0; w0.y = v1; w1.x = v2; w1.y = v3;
                *reinterpret_cast<float2*>(Cf + (size_t)r0 * D_MODEL + cc) = w0;
                *reinterpret_cast<float2*>(Cf + (size_t)(r0 + 8) * D_MODEL + cc) = w1;
            } else {
                uint32_t hp0 = cvt2bf(v1, v0);
                uint32_t hp1 = cvt2bf(v3, v2);
                float h0 = __uint_as_float(hp0 << 16), h1 = __uint_as_float(hp0 & 0xFFFF0000u);
                float h2 = __uint_as_float(hp1 << 16), h3 = __uint_as_float(hp1 & 0xFFFF0000u);
                uint32_t lp0 = cvt2bf(v1 - h1, v0 - h0);
                uint32_t lp1 = cvt2bf(v3 - h3, v2 - h2);
                *reinterpret_cast<uint32_t*>(Chi + (size_t)r0 * D_MODEL + cc) = hp0;
                *reinterpret_cast<uint32_t*>(Chi + (size_t)(r0 + 8) * D_MODEL + cc) = hp1;
                *reinterpret_cast<uint32_t*>(Clo + (size_t)r0 * D_MODEL + cc) = lp0;
                *reinterpret_cast<uint32_t*>(Clo + (size_t)(r0 + 8) * D_MODEL + cc) = lp1;
            }
        }
    }
}

__global__ __launch_bounds__(256, 2)
void gemm_qkv_kernel(const __nv_bfloat16* __restrict__ Ah3, const __nv_bfloat16* __restrict__ Al3,
                     const __nv_bfloat16* __restrict__ Wh4, const __nv_bfloat16* __restrict__ Wl4,
                     const float* __restrict__ bq, const float* __restrict__ bk,
                     const float* __restrict__ bv,
                     __nv_bfloat16* __restrict__ Qh, __nv_bfloat16* __restrict__ Ql,
                     __nv_bfloat16* __restrict__ Kh, __nv_bfloat16* __restrict__ Kl,
                     __nv_bfloat16* __restrict__ Vh, __nv_bfloat16* __restrict__ Vl)
{
    extern __shared__ char sm[];
    const int z = blockIdx.z;
    const float* bias = (z == 0) ? bq : (z == 1) ? bk : bv;
    __nv_bfloat16* Chi = (z == 0) ? Qh : (z == 1) ? Kh : Vh;
    __nv_bfloat16* Clo = (z == 0) ? Ql : (z == 1) ? Kl : Vl;
    gemm_core(Ah3 + (size_t)z * ASZ, Al3 + (size_t)z * ASZ,
              Wh4 + (size_t)z * WSZ, Wl4 + (size_t)z * WSZ,
              bias, Chi, Clo, nullptr, sm, blockIdx.y * 128, blockIdx.x * 128);
}

__global__ __launch_bounds__(256, 2)
void gemm_out_kernel(const __nv_bfloat16* __restrict__ Ah, const __nv_bfloat16* __restrict__ Al,
                     const __nv_bfloat16* __restrict__ Bh, const __nv_bfloat16* __restrict__ Bl,
                     const float* __restrict__ bias, float* __restrict__ Cf)
{
    extern __shared__ char sm[];
    gemm_core(Ah, Al, Bh, Bl, bias, nullptr, nullptr, Cf,
              sm, blockIdx.y * 128, blockIdx.x * 128);
}

// =====================================================================
// mma.sync flash attention — paired q-blocks (i, 15-i) per CTA for perfect
// load balance (single wave of 256 CTAs @ 2/SM). ex2 softmax, 1 sync/tile.
// =====================================================================
#define QTERM_B  18432               // 128*72*2
#define KVARR_B  9216                // 64*72*2
#define STG_B    (4 * KVARR_B + 256)
#define FL_SMEM  (2 * QTERM_B + 2 * STG_B)   // 111104
#define SCL2E    0.180336879f        // 0.125 * log2(e)
#define NQB      (T_ / 128)          // 16

__global__ __launch_bounds__(256, 2)
void flash_tc_kernel(const __nv_bfloat16* __restrict__ Qh_g, const __nv_bfloat16* __restrict__ Ql_g,
                     const __nv_bfloat16* __restrict__ Kh_g, const __nv_bfloat16* __restrict__ Kl_g,
                     const __nv_bfloat16* __restrict__ Vh_g, const __nv_bfloat16* __restrict__ Vl_g,
                     const int* __restrict__ mask, const int* __restrict__ causal_p,
                     __nv_bfloat16* __restrict__ Oh_g, __nv_bfloat16* __restrict__ Ol_g)
{
    extern __shared__ char smc[];
    const uint32_t smb = smem_to_u32(smc);
    const int tid = threadIdx.x, lane = tid & 31, warp = tid >> 5;
    const int pair = blockIdx.x;                 // 0..7
    const int bh = blockIdx.y, b = bh >> 4, h = bh & 15;
    const int causal = *causal_p;

    auto issue_kv = [&](int kt, int s) {
        const uint32_t sb = smb + 2u * QTERM_B + (uint32_t)s * STG_B;
        const int tk0 = b * T_ + kt * 64;
#pragma unroll
        for (int u = tid; u < 2048; u += 256) {
            const int arr = u >> 9, rem = u & 511;
            const int row = rem >> 3, c = rem & 7;
            const __nv_bfloat16* base = (arr == 0) ? Kh_g : (arr == 1) ? Kl_g
                                       : (arr == 2) ? Vh_g : Vl_g;
            CP_ASYNC16(sb + (uint32_t)(arr * KVARR_B + row * 144 + c * 16),
                       base + ((size_t)(tk0 + row) * D_MODEL + h * 64 + c * 8));
        }
        if (tid < 64) {
            float mv = (mask[tk0 + tid] == 0) ? -1e30f : 0.f;
            reinterpret_cast<float*>(smc + 2 * QTERM_B + s * STG_B + 4 * KVARR_B)[tid] = mv;
        }
    };

    const uint32_t a_lane = (uint32_t)((lane & 15) * 144 + (lane >> 4) * 16);
    const uint32_t b_lane = (uint32_t)(((lane & 7) + ((lane >> 4) << 3)) * 144 + ((lane >> 3) & 1) * 16);
    const uint32_t qsH = smb + (uint32_t)(warp * 16 * 144) + a_lane;
    const uint32_t qsL = qsH + QTERM_B;
    const int r_in_warp = lane >> 2;
    const int colb = 2 * (lane & 3);

    for (int blk = 0; blk < 2; ++blk) {
        const int qb = (blk == 0) ? (NQB - 1 - pair) : pair;   // big block first
        const int kend = causal ? (2 * qb + 1) : (T_ / 64 - 1);
        const int rowg0 = b * T_ + qb * 128;

        __syncthreads();   // all reads of previous block's Q smem are done

        // prologue: Q (both terms) + kv tile0, one commit group
        {
#pragma unroll
            for (int u = tid; u < 2048; u += 256) {
                const int term = u >> 10, rem = u & 1023;
                const int row = rem >> 3, c = rem & 7;
                const __nv_bfloat16* src = (term ? Ql_g : Qh_g)
                    + ((size_t)(rowg0 + row) * D_MODEL + h * 64 + c * 8);
                CP_ASYNC16(smb + (uint32_t)(term * QTERM_B + row * 144 + c * 16), src);
            }
            issue_kv(0, 0);
            CP_COMMIT();
        }

        uint32_t qhf[4][4];
        float o[8][4];
#pragma unroll
        for (int nd = 0; nd < 8; ++nd)
#pragma unroll
            for (int e = 0; e < 4; ++e) o[nd][e] = 0.f;
        float m0 = -1e30f, m1 = -1e30f, l0 = 0.f, l1 = 0.f;

        const int rg0 = qb * 128 + warp * 16 + r_in_warp;
        const int rg1 = rg0 + 8;

        for (int kt = 0; kt <= kend; ++kt) {
            CP_WAIT0();
            __syncthreads();
            if (kt + 1 <= kend) { issue_kv(kt + 1, (kt + 1) & 1); CP_COMMIT(); }

            if (kt == 0) {
#pragma unroll
                for (int ks = 0; ks < 4; ++ks)
                    ldm_x4(qhf[ks], qsH + (uint32_t)(ks * 32));
            }

            const int j = kt & 1;
            const uint32_t sb = smb + 2u * QTERM_B + (uint32_t)j * STG_B;
            const float* madd = reinterpret_cast<const float*>(smc + 2 * QTERM_B + j * STG_B + 4 * KVARR_B);

            // ---- S = Q K^T (3-term) ----
            float c[8][4];
#pragma unroll
            for (int nj = 0; nj < 8; ++nj)
#pragma unroll
                for (int e = 0; e < 4; ++e) c[nj][e] = 0.f;

#pragma unroll
            for (int ks = 0; ks < 4; ++ks) {
                const uint32_t kb = (uint32_t)(ks * 32);
                uint32_t qlf[4];
                ldm_x4(qlf, qsL + kb);
#pragma unroll
                for (int nb = 0; nb < 4; ++nb) {
                    uint32_t rh[4], rl[4];
                    ldm_x4(rh, sb + 0 * KVARR_B + b_lane + (uint32_t)(nb * 2304) + kb);
                    ldm_x4(rl, sb + 1 * KVARR_B + b_lane + (uint32_t)(nb * 2304) + kb);
                    mma_bf16(c[2 * nb],     qhf[ks], rh[0], rh[1]);
                    mma_bf16(c[2 * nb],     qhf[ks], rl[0], rl[1]);
                    mma_bf16(c[2 * nb],     qlf,     rh[0], rh[1]);
                    mma_bf16(c[2 * nb + 1], qhf[ks], rh[2], rh[3]);
                    mma_bf16(c[2 * nb + 1], qhf[ks], rl[2], rl[3]);
                    mma_bf16(c[2 * nb + 1], qlf,     rh[2], rh[3]);
                }
            }

            // ---- scale (log2 domain) + mask + online softmax via ex2 ----
            const bool diag = (causal != 0) && (kt >= 2 * qb);
            float mx0 = -1e30f, mx1 = -1e30f;
#pragma unroll
            for (int nj = 0; nj < 8; ++nj) {
                const int cl = nj * 8 + colb;
                const int cg = kt * 64 + cl;
                const float ma0 = madd[cl], ma1 = madd[cl + 1];
                float s0 = fmaf(c[nj][0], SCL2E, ma0);
                float s1 = fmaf(c[nj][1], SCL2E, ma1);
                float s2 = fmaf(c[nj][2], SCL2E, ma0);
                float s3 = fmaf(c[nj][3], SCL2E, ma1);
                if (diag) {
                    if (cg > rg0)     s0 = -1e30f;
                    if (cg + 1 > rg0) s1 = -1e30f;
                    if (cg > rg1)     s2 = -1e30f;
                    if (cg + 1 > rg1) s3 = -1e30f;
                }
                c[nj][0] = s0; c[nj][1] = s1; c[nj][2] = s2; c[nj][3] = s3;
                mx0 = fmaxf(mx0, fmaxf(s0, s1));
                mx1 = fmaxf(mx1, fmaxf(s2, s3));
            }
            mx0 = fmaxf(mx0, __shfl_xor_sync(0xffffffffu, mx0, 1));
            mx0 = fmaxf(mx0, __shfl_xor_sync(0xffffffffu, mx0, 2));
            mx1 = fmaxf(mx1, __shfl_xor_sync(0xffffffffu, mx1, 1));
            mx1 = fmaxf(mx1, __shfl_xor_sync(0xffffffffu, mx1, 2));

            const float mn0 = fmaxf(m0, mx0), mn1 = fmaxf(m1, mx1);
            const float al0 = ex2f(m0 - mn0), al1 = ex2f(m1 - mn1);
            float rs0 = 0.f, rs1 = 0.f;
#pragma unroll
            for (int nj = 0; nj < 8; ++nj) {
                float p0 = ex2f(c[nj][0] - mn0);
                float p1 = ex2f(c[nj][1] - mn0);
                float p2 = ex2f(c[nj][2] - mn1);
                float p3 = ex2f(c[nj][3] - mn1);
                c[nj][0] = p0; c[nj][1] = p1; c[nj][2] = p2; c[nj][3] = p3;
                rs0 += p0 + p1; rs1 += p2 + p3;
            }
            rs0 += __shfl_xor_sync(0xffffffffu, rs0, 1);
            rs0 += __shfl_xor_sync(0xffffffffu, rs0, 2);
            rs1 += __shfl_xor_sync(0xffffffffu, rs1, 1);
            rs1 += __shfl_xor_sync(0xffffffffu, rs1, 2);
            l0 = l0 * al0 + rs0; m0 = mn0;
            l1 = l1 * al1 + rs1; m1 = mn1;
#pragma unroll
            for (int nd = 0; nd < 8; ++nd) {
                o[nd][0] *= al0; o[nd][1] *= al0;
                o[nd][2] *= al1; o[nd][3] *= al1;
            }

            // ---- O += P V (3-term), P split fused per-ks ----
#pragma unroll
            for (int ks = 0; ks < 4; ++ks) {
                uint32_t pfh[4], pfl[4];
#pragma unroll
                for (int half = 0; half < 2; ++half) {
                    const int nj = 2 * ks + half;
                    uint32_t hpA = cvt2bf(c[nj][1], c[nj][0]);
                    uint32_t hpB = cvt2bf(c[nj][3], c[nj][2]);
                    float hA0 = __uint_as_float(hpA << 16), hA1 = __uint_as_float(hpA & 0xFFFF0000u);
                    float hB0 = __uint_as_float(hpB << 16), hB1 = __uint_as_float(hpB & 0xFFFF0000u);
                    pfh[2 * half + 0] = hpA; pfh[2 * half + 1] = hpB;
                    pfl[2 * half + 0] = cvt2bf(c[nj][1] - hA1, c[nj][0] - hA0);
                    pfl[2 * half + 1] = cvt2bf(c[nj][3] - hB1, c[nj][2] - hB0);
                }
#pragma unroll
                for (int nb = 0; nb < 4; ++nb) {
                    uint32_t vh[4], vl[4];
                    const uint32_t va = sb + 2u * KVARR_B + a_lane
                                      + (uint32_t)(ks * 16 * 144) + (uint32_t)(nb * 32);
                    ldm_x4_t(vh, va);
                    ldm_x4_t(vl, va + KVARR_B);
                    mma_bf16(o[2 * nb],     pfh, vh[0], vh[1]);
                    mma_bf16(o[2 * nb],     pfh, vl[0], vl[1]);
                    mma_bf16(o[2 * nb],     pfl, vh[0], vh[1]);
                    mma_bf16(o[2 * nb + 1], pfh, vh[2], vh[3]);
                    mma_bf16(o[2 * nb + 1], pfh, vl[2], vl[3]);
                    mma_bf16(o[2 * nb + 1], pfl, vh[2], vh[3]);
                }
            }
        }

        // ---- epilogue: normalize, write bf16 hi/lo ----
        const float inv0 = __fdividef(1.f, l0);
        const float inv1 = __fdividef(1.f, l1);
        const size_t gr0 = (size_t)(rowg0 + warp * 16 + r_in_warp) * D_MODEL + h * 64;
        const size_t gr1 = gr0 + 8 * D_MODEL;
#pragma unroll
        for (int nd = 0; nd < 8; ++nd) {
            const int cc = nd * 8 + colb;
            float v0 = o[nd][0] * inv0, v1 = o[nd][1] * inv0;
            float v2 = o[nd][2] * inv1, v3 = o[nd][3] * inv1;
            uint32_t hp0 = cvt2bf(v1, v0);
            uint32_t hp1 = cvt2bf(v3, v2);
            float h0 = __uint_as_float(hp0 << 16), h1 = __uint_as_float(hp0 & 0xFFFF0000u);
            float h2 = __uint_as_float(hp1 << 16), h3 = __uint_as_float(hp1 & 0xFFFF0000u);
            uint32_t lp0 = cvt2bf(v1 - h1, v0 - h0);
            uint32_t lp1 = cvt2bf(v3 - h3, v2 - h2);
            *reinterpret_cast<uint32_t*>(Oh_g + gr0 + cc) = hp0;
            *reinterpret_cast<uint32_t*>(Oh_g + gr1 + cc) = hp1;
            *reinterpret_cast<uint32_t*>(Ol_g + gr0 + cc) = lp0;
            *reinterpret_cast<uint32_t*>(Ol_g + gr1 + cc) = lp1;
        }
    }
}

// =====================================================================
// launch
// =====================================================================
extern "C" void kernel_launch(void* const* d_in, const int* in_sizes, int n_in,
                              void* d_out, int out_size)
{
    const float* q    = (const float*)d_in[0];
    const float* k    = (const float*)d_in[1];
    const float* v    = (const float*)d_in[2];
    const float* Wq   = (const float*)d_in[3];
    const float* bq   = (const float*)d_in[4];
    const float* Wk   = (const float*)d_in[5];
    const float* bk   = (const float*)d_in[6];
    const float* Wv   = (const float*)d_in[7];
    const float* bv   = (const float*)d_in[8];
    const float* Wo   = (const float*)d_in[9];
    const float* bo   = (const float*)d_in[10];
    const int*   mask = (const int*)d_in[11];
    const int*   causal = (const int*)d_in[12];
    float* out = (float*)d_out;

    __nv_bfloat16 *Ah, *Al, *Wh, *Wl, *Qh, *Ql, *Kh, *Kl, *Vh, *Vl, *Anh, *Anl;
    cudaGetSymbolAddress((void**)&Ah, g_Ah);
    cudaGetSymbolAddress((void**)&Al, g_Al);
    cudaGetSymbolAddress((void**)&Wh, g_Wh);
    cudaGetSymbolAddress((void**)&Wl, g_Wl);
    cudaGetSymbolAddress((void**)&Qh, g_Qh);
    cudaGetSymbolAddress((void**)&Ql, g_Ql);
    cudaGetSymbolAddress((void**)&Kh, g_Kh);
    cudaGetSymbolAddress((void**)&Kl, g_Kl);
    cudaGetSymbolAddress((void**)&Vh, g_Vh);
    cudaGetSymbolAddress((void**)&Vl, g_Vl);
    cudaGetSymbolAddress((void**)&Anh, g_Anh);
    cudaGetSymbolAddress((void**)&Anl, g_Anl);

    cudaFuncSetAttribute(gemm_qkv_kernel,
                         cudaFuncAttributeMaxDynamicSharedMemorySize, GEMM_SMEM);
    cudaFuncSetAttribute(gemm_out_kernel,
                         cudaFuncAttributeMaxDynamicSharedMemorySize, GEMM_SMEM);
    cudaFuncSetAttribute(flash_tc_kernel,
                         cudaFuncAttributeMaxDynamicSharedMemorySize, FL_SMEM);

    const int nA4 = ASZ / 4;
    const int nW4 = WSZ / 4;

    split3_kernel<<<dim3(nA4 / 256, 1, 3), 256>>>(q, k, v, Ah, Al);
    split4_kernel<<<dim3(nW4 / 256, 1, 4), 256>>>(Wq, Wk, Wv, Wo, Wh, Wl);

    gemm_qkv_kernel<<<dim3(D_MODEL / 128, M_ROWS / 128, 3), 256, GEMM_SMEM>>>(
        Ah, Al, Wh, Wl, bq, bk, bv, Qh, Ql, Kh, Kl, Vh, Vl);

    dim3 fgrid(NQB / 2, B_ * N_HEADS);   // (8, 32) = 256 CTAs, one balanced wave
    flash_tc_kernel<<<fgrid, 256, FL_SMEM>>>(Qh, Ql, Kh, Kl, Vh, Vl, mask, causal, Anh, Anl);

    gemm_out_kernel<<<dim3(D_MODEL / 128, M_ROWS / 128), 256, GEMM_SMEM>>>(
        Anh, Anl, Wh + (size_t)3 * WSZ, Wl + (size_t)3 * WSZ, bo, out);
}